// round 5
// baseline (speedup 1.0000x reference)
#include <cuda_runtime.h>
#include <cuda_fp16.h>
#include <math.h>
#include <stdint.h>

// ---- problem constants ----
#define BB 8
#define NTOK 1024
#define TT 1026            // N + cls + dict
#define DD 256
#define HH 8
#define LL 6
#define HD3 6144           // H*D*3
#define OD 2048            // H*D
#define ED 1024            // EXP*D
#define MM (BB*TT)         // 8208 rows
#define BHn (BB*HH)        // 64
#define TS2 1056           // padded fp32 score row stride (= padded attention K)
#define KATT 1056          // padded key count for WV GEMM

typedef __half hf;

// ---- scratch (device globals; no allocs allowed) ----
__device__ __align__(16) float g_h [(size_t)MM*DD];
__device__ __align__(16) float g_s [(size_t)BHn*TT*TS2];
__device__ __align__(16) float g_rmax[(size_t)BHn*TT];
__device__ __align__(16) float g_rinv[(size_t)BHn*TT];
__device__ __align__(16) float g_qkvb[(size_t)LL*HD3];
__device__ __align__(16) hf g_lnh[(size_t)MM*DD];
__device__ __align__(16) hf g_lnl[(size_t)MM*DD];
__device__ __align__(16) hf g_qh[(size_t)BHn*TT*DD];
__device__ __align__(16) hf g_ql[(size_t)BHn*TT*DD];
__device__ __align__(16) hf g_kh[(size_t)BHn*TT*DD];
__device__ __align__(16) hf g_kl[(size_t)BHn*TT*DD];
__device__ __align__(16) hf g_vh[(size_t)BHn*TT*DD];
__device__ __align__(16) hf g_vl[(size_t)BHn*TT*DD];
__device__ __align__(16) hf g_vTh[(size_t)BHn*DD*KATT];
__device__ __align__(16) hf g_vTl[(size_t)BHn*DD*KATT];
__device__ __align__(16) hf g_oh[(size_t)MM*OD];
__device__ __align__(16) hf g_ol[(size_t)MM*OD];
__device__ __align__(16) hf g_mh[(size_t)MM*ED];
__device__ __align__(16) hf g_ml[(size_t)MM*ED];
// transposed + split weights [N,K] per layer
__device__ __align__(16) hf g_qkvTh[(size_t)LL*HD3*DD];
__device__ __align__(16) hf g_qkvTl[(size_t)LL*HD3*DD];
__device__ __align__(16) hf g_projTh[(size_t)LL*DD*OD];
__device__ __align__(16) hf g_projTl[(size_t)LL*DD*OD];
__device__ __align__(16) hf g_w1Th[(size_t)LL*ED*DD];
__device__ __align__(16) hf g_w1Tl[(size_t)LL*ED*DD];
__device__ __align__(16) hf g_w2Th[(size_t)LL*DD*ED];
__device__ __align__(16) hf g_w2Tl[(size_t)LL*DD*ED];

__device__ __forceinline__ float gelu_exact(float x) {
    return 0.5f * x * (1.0f + erff(x * 0.70710678118654752440f));
}

__device__ __forceinline__ uint32_t smem_u32(const void* p) {
    uint32_t a;
    asm("{ .reg .u64 t; cvta.to.shared.u64 t, %1; cvt.u32.u64 %0, t; }" : "=r"(a) : "l"(p));
    return a;
}

__device__ __forceinline__ void ldsm4(uint32_t* r, uint32_t addr) {
    asm volatile("ldmatrix.sync.aligned.m8n8.x4.shared.b16 {%0,%1,%2,%3}, [%4];"
                 : "=r"(r[0]), "=r"(r[1]), "=r"(r[2]), "=r"(r[3]) : "r"(addr));
}

__device__ __forceinline__ void mma16816(float* d, const uint32_t* a, const uint32_t* b) {
    asm volatile(
        "mma.sync.aligned.m16n8k16.row.col.f32.f16.f16.f32 "
        "{%0,%1,%2,%3}, {%4,%5,%6,%7}, {%8,%9}, {%0,%1,%2,%3};"
        : "+f"(d[0]), "+f"(d[1]), "+f"(d[2]), "+f"(d[3])
        : "r"(a[0]), "r"(a[1]), "r"(a[2]), "r"(a[3]), "r"(b[0]), "r"(b[1]));
}

__device__ __forceinline__ void cpa16(uint32_t dst, const void* src, bool v) {
    int sz = v ? 16 : 0;
    asm volatile("cp.async.cg.shared.global [%0], [%1], 16, %2;"
                 :: "r"(dst), "l"(src), "r"(sz) : "memory");
}
__device__ __forceinline__ void cpa_commit() {
    asm volatile("cp.async.commit_group;" ::: "memory");
}

__device__ __forceinline__ void split_store(hf* dh, hf* dl, size_t off, float v) {
    hf h = __float2half_rn(v);
    dh[off] = h;
    dl[off] = __float2half_rn(v - __half2float(h));
}

// pack 8 fp32 into hi/lo half uint4s
__device__ __forceinline__ void pack8(const float* p, uint4& h, uint4& l) {
    __half2 hh[4], ll[4];
    #pragma unroll
    for (int i = 0; i < 4; i++) {
        __half a = __float2half_rn(p[2*i]);
        __half b = __float2half_rn(p[2*i+1]);
        hh[i] = __halves2half2(a, b);
        ll[i] = __halves2half2(__float2half_rn(p[2*i]   - __half2float(a)),
                               __float2half_rn(p[2*i+1] - __half2float(b)));
    }
    h = *(uint4*)hh;
    l = *(uint4*)ll;
}

// per-element epilogue
template<int EPI>
__device__ __forceinline__ void epi_store(int gm, int gn, float v, int M, int N,
                                          const float* __restrict__ bias,
                                          float* __restrict__ C, int ldc, long sC, int z) {
    if (gm >= M || gn >= N) return;
    if constexpr (EPI == 0) {                 // scores -> fp32 (ldc=TS2)
        C[(size_t)z * sC + (size_t)gm * ldc + gn] = v;
    } else if constexpr (EPI == 1) {          // qkv scatter (permuted cols: c*2048+h*256+f)
        v += bias[gn];
        int c = gn >> 11;
        int rem = gn & 2047;
        int h = rem >> 8, f = rem & 255;
        int b = gm / TT, t = gm - b * TT;
        int bh = b * HH + h;
        size_t o = ((size_t)bh * TT + t) * DD + f;
        if (c == 2) {
            split_store(g_vh, g_vl, o, v);
        } else {
            v *= 0.0625f;                     // 1/sqrt(256)
            if (c == 0) split_store(g_qh, g_ql, o, v);
            else        split_store(g_kh, g_kl, o, v);
        }
    } else if constexpr (EPI == 2) {          // WV -> normalize by 1/rowsum, split to o
        v *= g_rinv[(size_t)z * TT + gm];
        int b = z >> 3, head = z & 7;
        split_store(g_oh, g_ol, ((size_t)b * TT + gm) * OD + (size_t)head * DD + gn, v);
    } else if constexpr (EPI == 3) {          // proj -> fp32 + bias
        C[(size_t)gm * ldc + gn] = v + bias[gn];
    } else if constexpr (EPI == 4) {          // mlp1: bias+gelu -> m split
        split_store(g_mh, g_ml, (size_t)gm * ED + gn, gelu_exact(v + bias[gn]));
    } else {                                  // mlp2: bias+gelu -> fp32
        C[(size_t)gm * ldc + gn] = gelu_exact(v + bias[gn]);
    }
}

// ============ HMMA fp16x3 GEMM: 128x128 block, BK=32, cp.async 2-stage ============
// A: [M,K] K-major (hi/lo). B: [N,K] K-major (hi/lo). D = A @ B^T.
// LEXP=1: A is fp32 scores (g_s, stride TS2, batch z); load applies exp(x - rowmax)
//         and splits hi/lo on the fly. Epilogue (EPI=2) multiplies by 1/rowsum.
#define SLD 40            // padded smem row stride in halves (80 bytes)
#define STG_BYTES 40960
#define AH_OFF 0
#define AL_OFF 10240
#define BH_OFF 20480
#define BL_OFF 30720
#define SMEM_DYN (2*STG_BYTES)

template<int EPI, int LEXP>
__global__ void __launch_bounds__(256, 2) mma_gemm(
    const hf* __restrict__ Ah, const hf* __restrict__ Al, int lda, long sA,
    const hf* __restrict__ Bh, const hf* __restrict__ Bl, int ldb, long sB,
    const float* __restrict__ bias,
    float* __restrict__ C, int ldc, long sC,
    int M, int N, int K)
{
    extern __shared__ char smdyn[];
    uint32_t sb = smem_u32(smdyn);

    int tid = threadIdx.x, lane = tid & 31, wid = tid >> 5;
    int wm = wid >> 1, wn = wid & 1;
    int z = blockIdx.z;
    Bh += (size_t)z * sB;  Bl += (size_t)z * sB;
    int bm = blockIdx.y * 128, bn = blockIdx.x * 128;

    int row0 = tid >> 2, row1 = row0 + 64;
    int cvb = (tid & 3) * 16;                 // byte offset within 64B half-row
    bool aval0 = (bm + row0) < M, aval1 = (bm + row1) < M;
    bool bval0 = (bn + row0) < N, bval1 = (bn + row1) < N;
    const char* pBh0 = (const char*)(Bh + (size_t)(bval0 ? bn + row0 : 0) * ldb) + cvb;
    const char* pBh1 = (const char*)(Bh + (size_t)(bval1 ? bn + row1 : 0) * ldb) + cvb;
    const char* pBl0 = (const char*)(Bl + (size_t)(bval0 ? bn + row0 : 0) * ldb) + cvb;
    const char* pBl1 = (const char*)(Bl + (size_t)(bval1 ? bn + row1 : 0) * ldb) + cvb;
    uint32_t st0 = (uint32_t)(row0 * SLD * 2) + (uint32_t)cvb;
    uint32_t st1 = (uint32_t)(row1 * SLD * 2) + (uint32_t)cvb;

    // A source (cp.async path)
    const char *pAh0 = nullptr, *pAh1 = nullptr, *pAl0 = nullptr, *pAl1 = nullptr;
    // A source (LEXP path)
    const float *pS0 = nullptr, *pS1 = nullptr;
    float rm0 = 0.f, rm1 = 0.f;
    if constexpr (LEXP) {
        const float* Sz = g_s + (size_t)z * TT * TS2;
        pS0 = Sz + (size_t)(aval0 ? bm + row0 : 0) * TS2 + (tid & 3) * 8;
        pS1 = Sz + (size_t)(aval1 ? bm + row1 : 0) * TS2 + (tid & 3) * 8;
        if (aval0) rm0 = g_rmax[(size_t)z * TT + bm + row0];
        if (aval1) rm1 = g_rmax[(size_t)z * TT + bm + row1];
    } else {
        Ah += (size_t)z * sA;  Al += (size_t)z * sA;
        pAh0 = (const char*)(Ah + (size_t)(aval0 ? bm + row0 : 0) * lda) + cvb;
        pAh1 = (const char*)(Ah + (size_t)(aval1 ? bm + row1 : 0) * lda) + cvb;
        pAl0 = (const char*)(Al + (size_t)(aval0 ? bm + row0 : 0) * lda) + cvb;
        pAl1 = (const char*)(Al + (size_t)(aval1 ? bm + row1 : 0) * lda) + cvb;
    }

    float d[2][8][4];
    #pragma unroll
    for (int i = 0; i < 2; i++)
        #pragma unroll
        for (int j = 0; j < 8; j++)
            #pragma unroll
            for (int q = 0; q < 4; q++) d[i][j][q] = 0.f;

    // ldmatrix lane addressing
    int group = lane >> 3, lrow = lane & 7;
    int a_row = wm * 32 + (group & 1) * 8 + lrow;
    int a_ko  = (group >> 1) * 8;
    int b_row = wn * 64 + (group >> 1) * 8 + lrow;
    int b_ko  = (group & 1) * 8;
    uint32_t aoff = (uint32_t)(a_row * SLD + a_ko) * 2;
    uint32_t boff = (uint32_t)(b_row * SLD + b_ko) * 2;

    auto issue = [&](int c, int stg) {
        uint32_t s0 = sb + (uint32_t)stg * STG_BYTES;
        size_t adv = (size_t)c * 64;          // 32 halves = 64 bytes
        if constexpr (!LEXP) {
            cpa16(s0 + AH_OFF + st0, pAh0 + adv, aval0);
            cpa16(s0 + AH_OFF + st1, pAh1 + adv, aval1);
            cpa16(s0 + AL_OFF + st0, pAl0 + adv, aval0);
            cpa16(s0 + AL_OFF + st1, pAl1 + adv, aval1);
        }
        cpa16(s0 + BH_OFF + st0, pBh0 + adv, bval0);
        cpa16(s0 + BH_OFF + st1, pBh1 + adv, bval1);
        cpa16(s0 + BL_OFF + st0, pBl0 + adv, bval0);
        cpa16(s0 + BL_OFF + st1, pBl1 + adv, bval1);
        cpa_commit();
    };

    uint4 ah0, al0, ah1, al1, nh0, nl0, nh1, nl1;
    auto loadexpA = [&](int c, uint4& h0, uint4& l0, uint4& h1, uint4& l1) {
        int kc = c * 32;
        float4 x0 = *(const float4*)(pS0 + kc);
        float4 x1 = *(const float4*)(pS0 + kc + 4);
        float4 y0 = *(const float4*)(pS1 + kc);
        float4 y1 = *(const float4*)(pS1 + kc + 4);
        float p[8];
        p[0] = aval0 ? __expf(x0.x - rm0) : 0.f;
        p[1] = aval0 ? __expf(x0.y - rm0) : 0.f;
        p[2] = aval0 ? __expf(x0.z - rm0) : 0.f;
        p[3] = aval0 ? __expf(x0.w - rm0) : 0.f;
        p[4] = aval0 ? __expf(x1.x - rm0) : 0.f;
        p[5] = aval0 ? __expf(x1.y - rm0) : 0.f;
        p[6] = aval0 ? __expf(x1.z - rm0) : 0.f;
        p[7] = aval0 ? __expf(x1.w - rm0) : 0.f;
        pack8(p, h0, l0);
        p[0] = aval1 ? __expf(y0.x - rm1) : 0.f;
        p[1] = aval1 ? __expf(y0.y - rm1) : 0.f;
        p[2] = aval1 ? __expf(y0.z - rm1) : 0.f;
        p[3] = aval1 ? __expf(y0.w - rm1) : 0.f;
        p[4] = aval1 ? __expf(y1.x - rm1) : 0.f;
        p[5] = aval1 ? __expf(y1.y - rm1) : 0.f;
        p[6] = aval1 ? __expf(y1.z - rm1) : 0.f;
        p[7] = aval1 ? __expf(y1.w - rm1) : 0.f;
        pack8(p, h1, l1);
    };

    int nit = K >> 5;
    if constexpr (LEXP) loadexpA(0, ah0, al0, ah1, al1);
    issue(0, 0);

    for (int c = 0; c < nit; c++) {
        uint32_t cb = sb + (uint32_t)(c & 1) * STG_BYTES;
        if constexpr (LEXP) {
            char* as = smdyn + (size_t)(c & 1) * STG_BYTES;
            *(uint4*)(as + AH_OFF + st0) = ah0;
            *(uint4*)(as + AL_OFF + st0) = al0;
            *(uint4*)(as + AH_OFF + st1) = ah1;
            *(uint4*)(as + AL_OFF + st1) = al1;
        }
        if (c + 1 < nit) {
            issue(c + 1, (c + 1) & 1);
            asm volatile("cp.async.wait_group 1;" ::: "memory");
            if constexpr (LEXP) loadexpA(c + 1, nh0, nl0, nh1, nl1);
        } else {
            asm volatile("cp.async.wait_group 0;" ::: "memory");
        }
        __syncthreads();

        #pragma unroll
        for (int ks = 0; ks < 32; ks += 16) {
            uint32_t a_hf[2][4], a_lf[2][4];
            #pragma unroll
            for (int mt = 0; mt < 2; mt++) {
                uint32_t o = cb + aoff + (uint32_t)((mt * 16 * SLD + ks) * 2);
                ldsm4(a_hf[mt], o + AH_OFF);
                ldsm4(a_lf[mt], o + AL_OFF);
            }
            #pragma unroll
            for (int np = 0; np < 4; np++) {
                uint32_t b_hf[4], b_lf[4];
                uint32_t o = cb + boff + (uint32_t)((np * 16 * SLD + ks) * 2);
                ldsm4(b_hf, o + BH_OFF);
                ldsm4(b_lf, o + BL_OFF);
                #pragma unroll
                for (int mt = 0; mt < 2; mt++)
                    #pragma unroll
                    for (int hq = 0; hq < 2; hq++) {
                        float* acc = d[mt][np * 2 + hq];
                        mma16816(acc, a_hf[mt], &b_hf[hq * 2]);
                        mma16816(acc, a_lf[mt], &b_hf[hq * 2]);
                        mma16816(acc, a_hf[mt], &b_lf[hq * 2]);
                    }
            }
        }
        __syncthreads();
        if constexpr (LEXP) { ah0 = nh0; al0 = nl0; ah1 = nh1; al1 = nl1; }
    }

    // epilogue
    #pragma unroll
    for (int mt = 0; mt < 2; mt++)
        #pragma unroll
        for (int nt = 0; nt < 8; nt++) {
            int r0 = bm + wm * 32 + mt * 16 + (lane >> 2);
            int c0 = bn + wn * 64 + nt * 8 + (lane & 3) * 2;
            float* dd = d[mt][nt];
            epi_store<EPI>(r0,     c0,     dd[0], M, N, bias, C, ldc, sC, z);
            epi_store<EPI>(r0,     c0 + 1, dd[1], M, N, bias, C, ldc, sC, z);
            epi_store<EPI>(r0 + 8, c0,     dd[2], M, N, bias, C, ldc, sC, z);
            epi_store<EPI>(r0 + 8, c0 + 1, dd[3], M, N, bias, C, ldc, sC, z);
        }
}

// ---- shared transpose+split body: src [K,N] fp32 -> dh/dl [N,K] half ----
template<int PERM>
__device__ __forceinline__ void tsplit_body(const float* __restrict__ src,
                                            hf* __restrict__ dh, hf* __restrict__ dl,
                                            int K, int N) {
    __shared__ float t[32][33];
    int n0 = blockIdx.x * 32, k0 = blockIdx.y * 32;
    int tx = threadIdx.x, ty = threadIdx.y;  // 32 x 8
    #pragma unroll
    for (int i = 0; i < 4; i++) {
        int k = k0 + ty + i * 8, n = n0 + tx;
        if (k < K && n < N) t[ty + i * 8][tx] = src[(size_t)k * N + n];
    }
    __syncthreads();
    #pragma unroll
    for (int i = 0; i < 4; i++) {
        int n = n0 + ty + i * 8, k = k0 + tx;
        if (n < N && k < K) {
            float v = t[tx][ty + i * 8];
            int nd = n;
            if (PERM) {
                int h = n / 768, r = n - h * 768;
                int f = r / 3, c = r - f * 3;
                nd = c * 2048 + h * 256 + f;
            }
            split_store(dh, dl, (size_t)nd * K + k, v);
        }
    }
}

// batched over layers; z == LL slice permutes qkv bias
__global__ void tsplit_qkv(const float* __restrict__ src, const float* __restrict__ qb) {
    int zl = blockIdx.z;
    if (zl == LL) {
        int bid = blockIdx.y * gridDim.x + blockIdx.x;
        int idx = bid * 256 + threadIdx.y * 32 + threadIdx.x;
        if (idx < LL * HD3) {
            int l = idx / HD3, j = idx - l * HD3;
            int h = j / 768, r = j - h * 768;
            int f = r / 3, c = r - f * 3;
            g_qkvb[(size_t)l * HD3 + c * 2048 + h * 256 + f] = qb[idx];
        }
        return;
    }
    tsplit_body<1>(src + (size_t)zl * DD * HD3,
                   g_qkvTh + (size_t)zl * HD3 * DD, g_qkvTl + (size_t)zl * HD3 * DD,
                   DD, HD3);
}

// batched over layers; z == LL slice fills g_s pad columns with -1e30
__global__ void tsplit_proj(const float* __restrict__ src) {
    int zl = blockIdx.z;
    if (zl == LL) {
        long bid = blockIdx.y * gridDim.x + blockIdx.x;        // < 512
        long i0 = bid * 256 + threadIdx.y * 32 + threadIdx.x;
        const long PER = TS2 - TT;                              // 30
        const long TOT = (long)BHn * TT * PER;
        for (long i = i0; i < TOT; i += 512L * 256L) {
            long row = i / PER, j = i - row * PER;
            g_s[(size_t)row * TS2 + TT + j] = -1e30f;
        }
        return;
    }
    tsplit_body<0>(src + (size_t)zl * OD * DD,
                   g_projTh + (size_t)zl * DD * OD, g_projTl + (size_t)zl * DD * OD,
                   OD, DD);
}

__global__ void tsplit_w1(const float* __restrict__ src) {
    int zl = blockIdx.z;
    tsplit_body<0>(src + (size_t)zl * DD * ED,
                   g_w1Th + (size_t)zl * ED * DD, g_w1Tl + (size_t)zl * ED * DD,
                   DD, ED);
}

__global__ void tsplit_w2(const float* __restrict__ src) {
    int zl = blockIdx.z;
    tsplit_body<0>(src + (size_t)zl * ED * DD,
                   g_w2Th + (size_t)zl * DD * ED, g_w2Tl + (size_t)zl * DD * ED,
                   ED, DD);
}

// ---- transpose V: [bh][t][f] -> vT [bh][f][t(pad KATT)] (hi+lo) ----
__global__ void transpose_v() {
    __shared__ hf th[32][33], tl[32][33];
    int bh = blockIdx.z;
    int f0 = blockIdx.x * 32, t0 = blockIdx.y * 32;
    int tx = threadIdx.x, ty = threadIdx.y;   // 32 x 8
    const hf* vh = g_vh + (size_t)bh * TT * DD;
    const hf* vl = g_vl + (size_t)bh * TT * DD;
    #pragma unroll
    for (int i = 0; i < 4; i++) {
        int t = t0 + ty + i * 8;
        hf a = __float2half(0.f), b = a;
        if (t < TT) {
            a = vh[(size_t)t * DD + f0 + tx];
            b = vl[(size_t)t * DD + f0 + tx];
        }
        th[ty + i * 8][tx] = a;
        tl[ty + i * 8][tx] = b;
    }
    __syncthreads();
    hf* dH = g_vTh + (size_t)bh * DD * KATT;
    hf* dL = g_vTl + (size_t)bh * DD * KATT;
    #pragma unroll
    for (int i = 0; i < 4; i++) {
        int f = f0 + ty + i * 8, t = t0 + tx;
        dH[(size_t)f * KATT + t] = th[tx][ty + i * 8];
        dL[(size_t)f * KATT + t] = tl[tx][ty + i * 8];
    }
}

// ---- layernorm: fp32 (or concat inputs for layer 0) -> half hi/lo out ----
__global__ void ln_kernel(const float* __restrict__ in,
                          const float* __restrict__ x, const float* __restrict__ cls,
                          const float* __restrict__ dict, int first,
                          hf* __restrict__ outh, hf* __restrict__ outl,
                          const float* __restrict__ gamma, const float* __restrict__ beta) {
    int row = blockIdx.x;
    int tid = threadIdx.x;
    float v;
    if (first) {
        int b = row / TT, t = row - b * TT;
        if (t < NTOK)        v = x[((size_t)b * NTOK + t) * DD + tid];
        else if (t == NTOK)  v = cls[tid];
        else                 v = dict[tid];
    } else {
        v = in[(size_t)row * DD + tid];
    }
    float s = v, s2 = v * v;
    #pragma unroll
    for (int o = 16; o > 0; o >>= 1) {
        s  += __shfl_xor_sync(0xFFFFFFFFu, s,  o);
        s2 += __shfl_xor_sync(0xFFFFFFFFu, s2, o);
    }
    __shared__ float sh[8], sh2[8];
    int w = tid >> 5;
    if ((tid & 31) == 0) { sh[w] = s; sh2[w] = s2; }
    __syncthreads();
    if (tid < 32) {
        float a  = (tid < 8) ? sh[tid]  : 0.f;
        float a2 = (tid < 8) ? sh2[tid] : 0.f;
        #pragma unroll
        for (int o = 4; o > 0; o >>= 1) {
            a  += __shfl_xor_sync(0xFFFFFFFFu, a,  o);
            a2 += __shfl_xor_sync(0xFFFFFFFFu, a2, o);
        }
        if (tid == 0) { sh[0] = a; sh2[0] = a2; }
    }
    __syncthreads();
    float mean = sh[0] * (1.0f / DD);
    float var  = sh2[0] * (1.0f / DD) - mean * mean;
    float rr = rsqrtf(var + 1e-5f);
    float y = (v - mean) * rr * gamma[tid] + beta[tid];
    split_store(outh, outl, (size_t)row * DD + tid, y);
}

// ---- attention row reduce: max + 1/sum(exp) over each score row ----
__global__ void attn_reduce() {
    int row = blockIdx.x;                       // bh*TT + t
    const float* p = g_s + (size_t)row * TS2;
    int tid = threadIdx.x;
    float v[5];
    float mx = -1e30f;
    #pragma unroll
    for (int it = 0; it < 5; it++) {
        int j = tid + it * 256;
        if (j < TT) { v[it] = p[j]; mx = fmaxf(mx, v[it]); }
    }
    __shared__ float red_m[8], red_s[8];
    #pragma unroll
    for (int o = 16; o > 0; o >>= 1) mx = fmaxf(mx, __shfl_xor_sync(0xFFFFFFFFu, mx, o));
    if ((tid & 31) == 0) red_m[tid >> 5] = mx;
    __syncthreads();
    if (tid < 32) {
        float a = (tid < 8) ? red_m[tid] : -1e30f;
        #pragma unroll
        for (int o = 4; o > 0; o >>= 1) a = fmaxf(a, __shfl_xor_sync(0xFFFFFFFFu, a, o));
        if (tid == 0) red_m[0] = a;
    }
    __syncthreads();
    mx = red_m[0];
    float sum = 0.f;
    #pragma unroll
    for (int it = 0; it < 5; it++) {
        int j = tid + it * 256;
        if (j < TT) sum += __expf(v[it] - mx);
    }
    #pragma unroll
    for (int o = 16; o > 0; o >>= 1) sum += __shfl_xor_sync(0xFFFFFFFFu, sum, o);
    if ((tid & 31) == 0) red_s[tid >> 5] = sum;
    __syncthreads();
    if (tid < 32) {
        float a = (tid < 8) ? red_s[tid] : 0.f;
        #pragma unroll
        for (int o = 4; o > 0; o >>= 1) a += __shfl_xor_sync(0xFFFFFFFFu, a, o);
        if (tid == 0) { g_rmax[row] = mx; g_rinv[row] = 1.0f / a; }
    }
}

// ---- final output split ----
__global__ void out_kernel(float* __restrict__ out) {
    long i = (long)blockIdx.x * blockDim.x + threadIdx.x;
    if (i >= (long)MM * DD) return;
    int d = (int)(i % DD);
    long r = i / DD;
    int t = (int)(r % TT);
    int b = (int)(r / TT);
    float v = g_h[i];
    if (t < NTOK)        out[((long)b * NTOK + t) * DD + d] = v;
    else if (t == NTOK)  out[(long)BB * NTOK * DD + (long)b * DD + d] = v;
    else                 out[(long)BB * NTOK * DD + (long)BB * DD + (long)b * DD + d] = v;
}

extern "C" void kernel_launch(void* const* d_in, const int* in_sizes, int n_in,
                              void* d_out, int out_size) {
    const float* x      = (const float*)d_in[0];
    const float* cls    = (const float*)d_in[1];
    const float* dict   = (const float*)d_in[2];
    const float* ln1_g  = (const float*)d_in[3];
    const float* ln1_b  = (const float*)d_in[4];
    const float* qkv_w  = (const float*)d_in[5];
    const float* qkv_b  = (const float*)d_in[6];
    const float* proj_w = (const float*)d_in[7];
    const float* proj_b = (const float*)d_in[8];
    const float* ln2_g  = (const float*)d_in[9];
    const float* ln2_b  = (const float*)d_in[10];
    const float* mlp_w1 = (const float*)d_in[11];
    const float* mlp_b1 = (const float*)d_in[12];
    const float* mlp_w2 = (const float*)d_in[13];
    const float* mlp_b2 = (const float*)d_in[14];

    cudaFuncSetAttribute(mma_gemm<0,0>, cudaFuncAttributeMaxDynamicSharedMemorySize, SMEM_DYN);
    cudaFuncSetAttribute(mma_gemm<1,0>, cudaFuncAttributeMaxDynamicSharedMemorySize, SMEM_DYN);
    cudaFuncSetAttribute(mma_gemm<2,1>, cudaFuncAttributeMaxDynamicSharedMemorySize, SMEM_DYN);
    cudaFuncSetAttribute(mma_gemm<3,0>, cudaFuncAttributeMaxDynamicSharedMemorySize, SMEM_DYN);
    cudaFuncSetAttribute(mma_gemm<4,0>, cudaFuncAttributeMaxDynamicSharedMemorySize, SMEM_DYN);
    cudaFuncSetAttribute(mma_gemm<5,0>, cudaFuncAttributeMaxDynamicSharedMemorySize, SMEM_DYN);

    float *gh, *gs, *qkvb;
    hf *lnh, *lnl, *qh, *ql, *kh, *kl, *vTh, *vTl, *oh, *ol, *mh, *ml;
    hf *qkvTh, *qkvTl, *projTh, *projTl, *w1Th, *w1Tl, *w2Th, *w2Tl;
    cudaGetSymbolAddress((void**)&gh,  g_h);
    cudaGetSymbolAddress((void**)&gs,  g_s);
    cudaGetSymbolAddress((void**)&qkvb, g_qkvb);
    cudaGetSymbolAddress((void**)&lnh, g_lnh);
    cudaGetSymbolAddress((void**)&lnl, g_lnl);
    cudaGetSymbolAddress((void**)&qh,  g_qh);
    cudaGetSymbolAddress((void**)&ql,  g_ql);
    cudaGetSymbolAddress((void**)&kh,  g_kh);
    cudaGetSymbolAddress((void**)&kl,  g_kl);
    cudaGetSymbolAddress((void**)&vTh, g_vTh);
    cudaGetSymbolAddress((void**)&vTl, g_vTl);
    cudaGetSymbolAddress((void**)&oh,  g_oh);
    cudaGetSymbolAddress((void**)&ol,  g_ol);
    cudaGetSymbolAddress((void**)&mh,  g_mh);
    cudaGetSymbolAddress((void**)&ml,  g_ml);
    cudaGetSymbolAddress((void**)&qkvTh, g_qkvTh);
    cudaGetSymbolAddress((void**)&qkvTl, g_qkvTl);
    cudaGetSymbolAddress((void**)&projTh, g_projTh);
    cudaGetSymbolAddress((void**)&projTl, g_projTl);
    cudaGetSymbolAddress((void**)&w1Th, g_w1Th);
    cudaGetSymbolAddress((void**)&w1Tl, g_w1Tl);
    cudaGetSymbolAddress((void**)&w2Th, g_w2Th);
    cudaGetSymbolAddress((void**)&w2Tl, g_w2Tl);

    dim3 tb(32, 8);
    // launches 0-3: batched weight prep (bias permute + score-pad fill folded in)
    tsplit_qkv <<<dim3(HD3/32, DD/32, LL+1), tb>>>(qkv_w, qkv_b);
    tsplit_proj<<<dim3(DD/32,  OD/32, LL+1), tb>>>(proj_w);
    tsplit_w1  <<<dim3(ED/32,  DD/32, LL),   tb>>>(mlp_w1);
    tsplit_w2  <<<dim3(DD/32,  ED/32, LL),   tb>>>(mlp_w2);

    for (int l = 0; l < LL; l++) {
        // launch 4 (l=0): LN1 — layer 0 reads concat inputs directly
        ln_kernel<<<MM, 256>>>(gh, x, cls, dict, l == 0 ? 1 : 0,
                               lnh, lnl, ln1_g + (size_t)l*DD, ln1_b + (size_t)l*DD);

        // launch 5 (l=0): QKV GEMM  [8208,256] x [6144,256]^T  <- ncu target
        mma_gemm<1,0><<<dim3(HD3/128, (MM+127)/128, 1), 256, SMEM_DYN>>>(
            lnh, lnl, DD, 0,
            qkvTh + (size_t)l*HD3*DD, qkvTl + (size_t)l*HD3*DD, DD, 0,
            qkvb + (size_t)l*HD3, nullptr, 0, 0, MM, HD3, DD);

        transpose_v<<<dim3(DD/32, KATT/32, BHn), tb>>>();

        // scores = Q K^T (fp32, stride TS2), batched over 64 heads
        mma_gemm<0,0><<<dim3((TT+127)/128, (TT+127)/128, BHn), 256, SMEM_DYN>>>(
            qh, ql, DD, (long)TT*DD,
            kh, kl, DD, (long)TT*DD,
            nullptr, gs, TS2, (long)TT*TS2, TT, TT, DD);

        attn_reduce<<<BHn*TT, 256>>>();

        // O = exp(S-max) V * (1/sum): A loaded+exp'd on the fly from g_s
        mma_gemm<2,1><<<dim3(DD/128, (TT+127)/128, BHn), 256, SMEM_DYN>>>(
            nullptr, nullptr, 0, 0,
            vTh, vTl, KATT, (long)DD*KATT,
            nullptr, nullptr, 0, 0, TT, DD, KATT);

        // proj: [8208,2048] x [256,2048]^T -> fp32 h
        mma_gemm<3,0><<<dim3(DD/128, (MM+127)/128, 1), 256, SMEM_DYN>>>(
            oh, ol, OD, 0,
            projTh + (size_t)l*DD*OD, projTl + (size_t)l*DD*OD, OD, 0,
            proj_b + (size_t)l*DD, gh, DD, 0, MM, DD, OD);

        ln_kernel<<<MM, 256>>>(gh, x, cls, dict, 0,
                               lnh, lnl, ln2_g + (size_t)l*DD, ln2_b + (size_t)l*DD);

        // mlp1 + gelu -> m split
        mma_gemm<4,0><<<dim3(ED/128, (MM+127)/128, 1), 256, SMEM_DYN>>>(
            lnh, lnl, DD, 0,
            w1Th + (size_t)l*ED*DD, w1Tl + (size_t)l*ED*DD, DD, 0,
            mlp_b1 + (size_t)l*ED, nullptr, 0, 0, MM, ED, DD);

        // mlp2 + gelu -> fp32 h
        mma_gemm<5,0><<<dim3(DD/128, (MM+127)/128, 1), 256, SMEM_DYN>>>(
            mh, ml, ED, 0,
            w2Th + (size_t)l*DD*ED, w2Tl + (size_t)l*DD*ED, ED, 0,
            mlp_b2 + (size_t)l*DD, gh, DD, 0, MM, DD, ED);
    }

    long total = (long)MM * DD;
    out_kernel<<<(unsigned)((total + 255) / 256), 256>>>((float*)d_out);
}

// round 6
// speedup vs baseline: 1.1775x; 1.1775x over previous
#include <cuda_runtime.h>
#include <cuda_fp16.h>
#include <math.h>
#include <stdint.h>

// ---- problem constants ----
#define BB 8
#define NTOK 1024
#define TT 1026            // N + cls + dict
#define DD 256
#define HH 8
#define LL 6
#define HD3 6144           // H*D*3
#define OD 2048            // H*D
#define ED 1024            // EXP*D
#define MM (BB*TT)         // 8208 rows
#define BHn (BB*HH)        // 64
#define TS2 1056           // padded fp32 score row stride (= padded attention K)
#define KATT 1056          // padded key count for WV GEMM

typedef __half hf;

// ---- scratch (device globals; no allocs allowed) ----
__device__ __align__(16) float g_h [(size_t)MM*DD];
__device__ __align__(16) float g_s [(size_t)BHn*TT*TS2];
__device__ __align__(16) float g_rmax[(size_t)BHn*TT];
__device__ __align__(16) float g_rinv[(size_t)BHn*TT];
__device__ __align__(16) float g_lnm[(size_t)MM];
__device__ __align__(16) float g_lnr[(size_t)MM];
__device__ __align__(16) float g_qkvb[(size_t)LL*HD3];
__device__ __align__(16) hf g_qh[(size_t)BHn*TT*DD];
__device__ __align__(16) hf g_ql[(size_t)BHn*TT*DD];
__device__ __align__(16) hf g_kh[(size_t)BHn*TT*DD];
__device__ __align__(16) hf g_vh[(size_t)BHn*TT*DD];
__device__ __align__(16) hf g_vTh[(size_t)BHn*DD*KATT];
__device__ __align__(16) hf g_oh[(size_t)MM*OD];
__device__ __align__(16) hf g_ol[(size_t)MM*OD];
__device__ __align__(16) hf g_mh[(size_t)MM*ED];
__device__ __align__(16) hf g_ml[(size_t)MM*ED];
// transposed + split weights [N,K] per layer
__device__ __align__(16) hf g_qkvTh[(size_t)LL*HD3*DD];
__device__ __align__(16) hf g_qkvTl[(size_t)LL*HD3*DD];
__device__ __align__(16) hf g_projTh[(size_t)LL*DD*OD];
__device__ __align__(16) hf g_projTl[(size_t)LL*DD*OD];
__device__ __align__(16) hf g_w1Th[(size_t)LL*ED*DD];
__device__ __align__(16) hf g_w1Tl[(size_t)LL*ED*DD];
__device__ __align__(16) hf g_w2Th[(size_t)LL*DD*ED];
__device__ __align__(16) hf g_w2Tl[(size_t)LL*DD*ED];

__device__ __forceinline__ float gelu_exact(float x) {
    return 0.5f * x * (1.0f + erff(x * 0.70710678118654752440f));
}

__device__ __forceinline__ uint32_t smem_u32(const void* p) {
    uint32_t a;
    asm("{ .reg .u64 t; cvta.to.shared.u64 t, %1; cvt.u32.u64 %0, t; }" : "=r"(a) : "l"(p));
    return a;
}

__device__ __forceinline__ void ldsm4(uint32_t* r, uint32_t addr) {
    asm volatile("ldmatrix.sync.aligned.m8n8.x4.shared.b16 {%0,%1,%2,%3}, [%4];"
                 : "=r"(r[0]), "=r"(r[1]), "=r"(r[2]), "=r"(r[3]) : "r"(addr));
}

__device__ __forceinline__ void mma16816(float* d, const uint32_t* a, const uint32_t* b) {
    asm volatile(
        "mma.sync.aligned.m16n8k16.row.col.f32.f16.f16.f32 "
        "{%0,%1,%2,%3}, {%4,%5,%6,%7}, {%8,%9}, {%0,%1,%2,%3};"
        : "+f"(d[0]), "+f"(d[1]), "+f"(d[2]), "+f"(d[3])
        : "r"(a[0]), "r"(a[1]), "r"(a[2]), "r"(a[3]), "r"(b[0]), "r"(b[1]));
}

__device__ __forceinline__ void cpa16(uint32_t dst, const void* src, bool v) {
    int sz = v ? 16 : 0;
    asm volatile("cp.async.cg.shared.global [%0], [%1], 16, %2;"
                 :: "r"(dst), "l"(src), "r"(sz) : "memory");
}
__device__ __forceinline__ void cpa_commit() {
    asm volatile("cp.async.commit_group;" ::: "memory");
}

__device__ __forceinline__ void split_store(hf* dh, hf* dl, size_t off, float v) {
    hf h = __float2half_rn(v);
    dh[off] = h;
    dl[off] = __float2half_rn(v - __half2float(h));
}

// pack 8 fp32 into hi/lo half uint4s
__device__ __forceinline__ void pack8(const float* p, uint4& h, uint4& l) {
    __half2 hh[4], ll[4];
    #pragma unroll
    for (int i = 0; i < 4; i++) {
        __half a = __float2half_rn(p[2*i]);
        __half b = __float2half_rn(p[2*i+1]);
        hh[i] = __halves2half2(a, b);
        ll[i] = __halves2half2(__float2half_rn(p[2*i]   - __half2float(a)),
                               __float2half_rn(p[2*i+1] - __half2float(b)));
    }
    h = *(uint4*)hh;
    l = *(uint4*)ll;
}

// per-element epilogue
template<int EPI>
__device__ __forceinline__ void epi_store(int gm, int gn, float v, int M, int N,
                                          const float* __restrict__ bias,
                                          float* __restrict__ C, int ldc, long sC, int z) {
    if (gm >= M || gn >= N) return;
    if constexpr (EPI == 0) {                 // scores -> fp32 (ldc=TS2)
        C[(size_t)z * sC + (size_t)gm * ldc + gn] = v;
    } else if constexpr (EPI == 1) {          // qkv scatter (permuted cols: c*2048+h*256+f)
        v += bias[gn];
        int c = gn >> 11;
        int rem = gn & 2047;
        int h = rem >> 8, f = rem & 255;
        int b = gm / TT, t = gm - b * TT;
        int bh = b * HH + h;
        size_t o = ((size_t)bh * TT + t) * DD + f;
        if (c == 2) {
            g_vh[o] = __float2half_rn(v);     // hi only (2-pass WV)
        } else {
            v *= 0.0625f;                     // 1/sqrt(256)
            if (c == 0) split_store(g_qh, g_ql, o, v);
            else        g_kh[o] = __float2half_rn(v);  // hi only (2-pass scores)
        }
    } else if constexpr (EPI == 2) {          // WV -> normalize by 1/rowsum, split to o
        v *= g_rinv[(size_t)z * TT + gm];
        int b = z >> 3, head = z & 7;
        split_store(g_oh, g_ol, ((size_t)b * TT + gm) * OD + (size_t)head * DD + gn, v);
    } else if constexpr (EPI == 3) {          // proj -> fp32 + bias
        C[(size_t)gm * ldc + gn] = v + bias[gn];
    } else if constexpr (EPI == 4) {          // mlp1: bias+gelu -> m split
        split_store(g_mh, g_ml, (size_t)gm * ED + gn, gelu_exact(v + bias[gn]));
    } else {                                  // mlp2: bias+gelu -> fp32
        C[(size_t)gm * ldc + gn] = gelu_exact(v + bias[gn]);
    }
}

// ============ HMMA fp16 split GEMM: 128x128 block, BK=32, cp.async 2-stage ============
// A: [M,K] K-major (hi/lo). B: [N,K] K-major (hi[/lo]). D = A @ B^T.
// MODE 0: A hi/lo via cp.async.
// MODE 1: A = exp(score - rowmax) computed from g_s on the fly (stride TS2, batch z).
// MODE 2: A = LayerNorm(g_h row) via g_lnm/g_lnr stats + lng/lnb, split on the fly.
// NPASS 3: Ah*Bh + Al*Bh + Ah*Bl.  NPASS 2: Ah*Bh + Al*Bh (B-lo dropped).
#define SLD 40            // padded smem row stride in halves (80 bytes)
#define STG_BYTES 40960
#define AH_OFF 0
#define AL_OFF 10240
#define BH_OFF 20480
#define BL_OFF 30720
#define SMEM_DYN (2*STG_BYTES)

template<int EPI, int MODE, int NPASS>
__global__ void __launch_bounds__(256, 2) mma_gemm(
    const hf* __restrict__ Ah, const hf* __restrict__ Al, int lda, long sA,
    const hf* __restrict__ Bh, const hf* __restrict__ Bl, int ldb, long sB,
    const float* __restrict__ bias,
    const float* __restrict__ lng, const float* __restrict__ lnb,
    float* __restrict__ C, int ldc, long sC,
    int M, int N, int K)
{
    extern __shared__ char smdyn[];
    uint32_t sb = smem_u32(smdyn);

    int tid = threadIdx.x, lane = tid & 31, wid = tid >> 5;
    int wm = wid >> 1, wn = wid & 1;
    int z = blockIdx.z;
    Bh += (size_t)z * sB;
    if constexpr (NPASS == 3) Bl += (size_t)z * sB;
    int bm = blockIdx.y * 128, bn = blockIdx.x * 128;

    int row0 = tid >> 2, row1 = row0 + 64;
    int cvb = (tid & 3) * 16;                 // byte offset within 64B half-row
    int cofs = (tid & 3) * 8;                 // element offset (8 elems per thread)
    bool aval0 = (bm + row0) < M, aval1 = (bm + row1) < M;
    bool bval0 = (bn + row0) < N, bval1 = (bn + row1) < N;
    const char* pBh0 = (const char*)(Bh + (size_t)(bval0 ? bn + row0 : 0) * ldb) + cvb;
    const char* pBh1 = (const char*)(Bh + (size_t)(bval1 ? bn + row1 : 0) * ldb) + cvb;
    const char* pBl0 = nullptr; const char* pBl1 = nullptr;
    if constexpr (NPASS == 3) {
        pBl0 = (const char*)(Bl + (size_t)(bval0 ? bn + row0 : 0) * ldb) + cvb;
        pBl1 = (const char*)(Bl + (size_t)(bval1 ? bn + row1 : 0) * ldb) + cvb;
    }
    uint32_t st0 = (uint32_t)(row0 * SLD * 2) + (uint32_t)cvb;
    uint32_t st1 = (uint32_t)(row1 * SLD * 2) + (uint32_t)cvb;

    // A sources
    const char *pAh0 = nullptr, *pAh1 = nullptr, *pAl0 = nullptr, *pAl1 = nullptr;
    const float *pS0 = nullptr, *pS1 = nullptr;
    float rm0 = 0.f, rm1 = 0.f, rr0 = 0.f, rr1 = 0.f;
    if constexpr (MODE == 1) {
        const float* Sz = g_s + (size_t)z * TT * TS2;
        pS0 = Sz + (size_t)(aval0 ? bm + row0 : 0) * TS2 + cofs;
        pS1 = Sz + (size_t)(aval1 ? bm + row1 : 0) * TS2 + cofs;
        if (aval0) rm0 = g_rmax[(size_t)z * TT + bm + row0];
        if (aval1) rm1 = g_rmax[(size_t)z * TT + bm + row1];
    } else if constexpr (MODE == 2) {
        pS0 = g_h + (size_t)(aval0 ? bm + row0 : 0) * DD + cofs;
        pS1 = g_h + (size_t)(aval1 ? bm + row1 : 0) * DD + cofs;
        if (aval0) { rm0 = g_lnm[bm + row0]; rr0 = g_lnr[bm + row0]; }
        if (aval1) { rm1 = g_lnm[bm + row1]; rr1 = g_lnr[bm + row1]; }
    } else {
        Ah += (size_t)z * sA;  Al += (size_t)z * sA;
        pAh0 = (const char*)(Ah + (size_t)(aval0 ? bm + row0 : 0) * lda) + cvb;
        pAh1 = (const char*)(Ah + (size_t)(aval1 ? bm + row1 : 0) * lda) + cvb;
        pAl0 = (const char*)(Al + (size_t)(aval0 ? bm + row0 : 0) * lda) + cvb;
        pAl1 = (const char*)(Al + (size_t)(aval1 ? bm + row1 : 0) * lda) + cvb;
    }

    float d[2][8][4];
    #pragma unroll
    for (int i = 0; i < 2; i++)
        #pragma unroll
        for (int j = 0; j < 8; j++)
            #pragma unroll
            for (int q = 0; q < 4; q++) d[i][j][q] = 0.f;

    // ldmatrix lane addressing
    int group = lane >> 3, lrow = lane & 7;
    int a_row = wm * 32 + (group & 1) * 8 + lrow;
    int a_ko  = (group >> 1) * 8;
    int b_row = wn * 64 + (group >> 1) * 8 + lrow;
    int b_ko  = (group & 1) * 8;
    uint32_t aoff = (uint32_t)(a_row * SLD + a_ko) * 2;
    uint32_t boff = (uint32_t)(b_row * SLD + b_ko) * 2;

    auto issue = [&](int c, int stg) {
        uint32_t s0 = sb + (uint32_t)stg * STG_BYTES;
        size_t adv = (size_t)c * 64;          // 32 halves = 64 bytes
        if constexpr (MODE == 0) {
            cpa16(s0 + AH_OFF + st0, pAh0 + adv, aval0);
            cpa16(s0 + AH_OFF + st1, pAh1 + adv, aval1);
            cpa16(s0 + AL_OFF + st0, pAl0 + adv, aval0);
            cpa16(s0 + AL_OFF + st1, pAl1 + adv, aval1);
        }
        cpa16(s0 + BH_OFF + st0, pBh0 + adv, bval0);
        cpa16(s0 + BH_OFF + st1, pBh1 + adv, bval1);
        if constexpr (NPASS == 3) {
            cpa16(s0 + BL_OFF + st0, pBl0 + adv, bval0);
            cpa16(s0 + BL_OFF + st1, pBl1 + adv, bval1);
        }
        cpa_commit();
    };

    uint4 ah0, al0, ah1, al1, nh0, nl0, nh1, nl1;
    auto loadA = [&](int c, uint4& h0, uint4& l0, uint4& h1, uint4& l1) {
        int kc = c * 32;
        float4 x0 = *(const float4*)(pS0 + kc);
        float4 x1 = *(const float4*)(pS0 + kc + 4);
        float4 y0 = *(const float4*)(pS1 + kc);
        float4 y1 = *(const float4*)(pS1 + kc + 4);
        float p[8];
        if constexpr (MODE == 1) {
            p[0] = aval0 ? __expf(x0.x - rm0) : 0.f;
            p[1] = aval0 ? __expf(x0.y - rm0) : 0.f;
            p[2] = aval0 ? __expf(x0.z - rm0) : 0.f;
            p[3] = aval0 ? __expf(x0.w - rm0) : 0.f;
            p[4] = aval0 ? __expf(x1.x - rm0) : 0.f;
            p[5] = aval0 ? __expf(x1.y - rm0) : 0.f;
            p[6] = aval0 ? __expf(x1.z - rm0) : 0.f;
            p[7] = aval0 ? __expf(x1.w - rm0) : 0.f;
            pack8(p, h0, l0);
            p[0] = aval1 ? __expf(y0.x - rm1) : 0.f;
            p[1] = aval1 ? __expf(y0.y - rm1) : 0.f;
            p[2] = aval1 ? __expf(y0.z - rm1) : 0.f;
            p[3] = aval1 ? __expf(y0.w - rm1) : 0.f;
            p[4] = aval1 ? __expf(y1.x - rm1) : 0.f;
            p[5] = aval1 ? __expf(y1.y - rm1) : 0.f;
            p[6] = aval1 ? __expf(y1.z - rm1) : 0.f;
            p[7] = aval1 ? __expf(y1.w - rm1) : 0.f;
            pack8(p, h1, l1);
        } else {  // MODE == 2: LayerNorm transform
            const float* gk = lng + kc + cofs;
            const float* bk = lnb + kc + cofs;
            float4 g0 = *(const float4*)gk, g1 = *(const float4*)(gk + 4);
            float4 b0 = *(const float4*)bk, b1 = *(const float4*)(bk + 4);
            p[0] = aval0 ? (x0.x - rm0) * rr0 * g0.x + b0.x : 0.f;
            p[1] = aval0 ? (x0.y - rm0) * rr0 * g0.y + b0.y : 0.f;
            p[2] = aval0 ? (x0.z - rm0) * rr0 * g0.z + b0.z : 0.f;
            p[3] = aval0 ? (x0.w - rm0) * rr0 * g0.w + b0.w : 0.f;
            p[4] = aval0 ? (x1.x - rm0) * rr0 * g1.x + b1.x : 0.f;
            p[5] = aval0 ? (x1.y - rm0) * rr0 * g1.y + b1.y : 0.f;
            p[6] = aval0 ? (x1.z - rm0) * rr0 * g1.z + b1.z : 0.f;
            p[7] = aval0 ? (x1.w - rm0) * rr0 * g1.w + b1.w : 0.f;
            pack8(p, h0, l0);
            p[0] = aval1 ? (y0.x - rm1) * rr1 * g0.x + b0.x : 0.f;
            p[1] = aval1 ? (y0.y - rm1) * rr1 * g0.y + b0.y : 0.f;
            p[2] = aval1 ? (y0.z - rm1) * rr1 * g0.z + b0.z : 0.f;
            p[3] = aval1 ? (y0.w - rm1) * rr1 * g0.w + b0.w : 0.f;
            p[4] = aval1 ? (y1.x - rm1) * rr1 * g1.x + b1.x : 0.f;
            p[5] = aval1 ? (y1.y - rm1) * rr1 * g1.y + b1.y : 0.f;
            p[6] = aval1 ? (y1.z - rm1) * rr1 * g1.z + b1.z : 0.f;
            p[7] = aval1 ? (y1.w - rm1) * rr1 * g1.w + b1.w : 0.f;
            pack8(p, h1, l1);
        }
    };

    int nit = K >> 5;
    if constexpr (MODE != 0) loadA(0, ah0, al0, ah1, al1);
    issue(0, 0);

    for (int c = 0; c < nit; c++) {
        uint32_t cb = sb + (uint32_t)(c & 1) * STG_BYTES;
        if constexpr (MODE != 0) {
            char* as = smdyn + (size_t)(c & 1) * STG_BYTES;
            *(uint4*)(as + AH_OFF + st0) = ah0;
            *(uint4*)(as + AL_OFF + st0) = al0;
            *(uint4*)(as + AH_OFF + st1) = ah1;
            *(uint4*)(as + AL_OFF + st1) = al1;
        }
        if (c + 1 < nit) {
            issue(c + 1, (c + 1) & 1);
            asm volatile("cp.async.wait_group 1;" ::: "memory");
            if constexpr (MODE != 0) loadA(c + 1, nh0, nl0, nh1, nl1);
        } else {
            asm volatile("cp.async.wait_group 0;" ::: "memory");
        }
        __syncthreads();

        #pragma unroll
        for (int ks = 0; ks < 32; ks += 16) {
            uint32_t a_hf[2][4], a_lf[2][4];
            #pragma unroll
            for (int mt = 0; mt < 2; mt++) {
                uint32_t o = cb + aoff + (uint32_t)((mt * 16 * SLD + ks) * 2);
                ldsm4(a_hf[mt], o + AH_OFF);
                ldsm4(a_lf[mt], o + AL_OFF);
            }
            #pragma unroll
            for (int np = 0; np < 4; np++) {
                uint32_t b_hf[4], b_lf[4];
                uint32_t o = cb + boff + (uint32_t)((np * 16 * SLD + ks) * 2);
                ldsm4(b_hf, o + BH_OFF);
                if constexpr (NPASS == 3) ldsm4(b_lf, o + BL_OFF);
                #pragma unroll
                for (int mt = 0; mt < 2; mt++)
                    #pragma unroll
                    for (int hq = 0; hq < 2; hq++) {
                        float* acc = d[mt][np * 2 + hq];
                        mma16816(acc, a_hf[mt], &b_hf[hq * 2]);
                        mma16816(acc, a_lf[mt], &b_hf[hq * 2]);
                        if constexpr (NPASS == 3)
                            mma16816(acc, a_hf[mt], &b_lf[hq * 2]);
                    }
            }
        }
        __syncthreads();
        if constexpr (MODE != 0) { ah0 = nh0; al0 = nl0; ah1 = nh1; al1 = nl1; }
    }

    // epilogue
    #pragma unroll
    for (int mt = 0; mt < 2; mt++)
        #pragma unroll
        for (int nt = 0; nt < 8; nt++) {
            int r0 = bm + wm * 32 + mt * 16 + (lane >> 2);
            int c0 = bn + wn * 64 + nt * 8 + (lane & 3) * 2;
            float* dd = d[mt][nt];
            epi_store<EPI>(r0,     c0,     dd[0], M, N, bias, C, ldc, sC, z);
            epi_store<EPI>(r0,     c0 + 1, dd[1], M, N, bias, C, ldc, sC, z);
            epi_store<EPI>(r0 + 8, c0,     dd[2], M, N, bias, C, ldc, sC, z);
            epi_store<EPI>(r0 + 8, c0 + 1, dd[3], M, N, bias, C, ldc, sC, z);
        }
}

// ---- shared transpose+split body: src [K,N] fp32 -> dh/dl [N,K] half ----
template<int PERM>
__device__ __forceinline__ void tsplit_body(const float* __restrict__ src,
                                            hf* __restrict__ dh, hf* __restrict__ dl,
                                            int K, int N) {
    __shared__ float t[32][33];
    int n0 = blockIdx.x * 32, k0 = blockIdx.y * 32;
    int tx = threadIdx.x, ty = threadIdx.y;  // 32 x 8
    #pragma unroll
    for (int i = 0; i < 4; i++) {
        int k = k0 + ty + i * 8, n = n0 + tx;
        if (k < K && n < N) t[ty + i * 8][tx] = src[(size_t)k * N + n];
    }
    __syncthreads();
    #pragma unroll
    for (int i = 0; i < 4; i++) {
        int n = n0 + ty + i * 8, k = k0 + tx;
        if (n < N && k < K) {
            float v = t[tx][ty + i * 8];
            int nd = n;
            if (PERM) {
                int h = n / 768, r = n - h * 768;
                int f = r / 3, c = r - f * 3;
                nd = c * 2048 + h * 256 + f;
            }
            split_store(dh, dl, (size_t)nd * K + k, v);
        }
    }
}

// launch 0: qkv weights (z<LL) + bias permute (z==LL)
__global__ void tsplit_qkv(const float* __restrict__ src, const float* __restrict__ qb) {
    int zl = blockIdx.z;
    if (zl == LL) {
        int bid = blockIdx.y * gridDim.x + blockIdx.x;
        int idx = bid * 256 + threadIdx.y * 32 + threadIdx.x;
        if (idx < LL * HD3) {
            int l = idx / HD3, j = idx - l * HD3;
            int h = j / 768, r = j - h * 768;
            int f = r / 3, c = r - f * 3;
            g_qkvb[(size_t)l * HD3 + c * 2048 + h * 256 + f] = qb[idx];
        }
        return;
    }
    tsplit_body<1>(src + (size_t)zl * DD * HD3,
                   g_qkvTh + (size_t)zl * HD3 * DD, g_qkvTl + (size_t)zl * HD3 * DD,
                   DD, HD3);
}

// launch 1: proj (z<LL), w1 (z<2LL), w2 (z<3LL), score-pad fill (z==3LL)
__global__ void tsplit_rest(const float* __restrict__ pw,
                            const float* __restrict__ w1,
                            const float* __restrict__ w2) {
    int zl = blockIdx.z;
    if (zl < LL) {
        tsplit_body<0>(pw + (size_t)zl * OD * DD,
                       g_projTh + (size_t)zl * DD * OD, g_projTl + (size_t)zl * DD * OD,
                       OD, DD);
    } else if (zl < 2 * LL) {
        int l = zl - LL;
        tsplit_body<0>(w1 + (size_t)l * DD * ED,
                       g_w1Th + (size_t)l * ED * DD, g_w1Tl + (size_t)l * ED * DD,
                       DD, ED);
    } else if (zl < 3 * LL) {
        int l = zl - 2 * LL;
        tsplit_body<0>(w2 + (size_t)l * ED * DD,
                       g_w2Th + (size_t)l * DD * ED, g_w2Tl + (size_t)l * DD * ED,
                       ED, DD);
    } else {
        long nb = (long)gridDim.x * gridDim.y;
        long bid = (long)blockIdx.y * gridDim.x + blockIdx.x;
        long i0 = bid * 256 + threadIdx.y * 32 + threadIdx.x;
        const long PER = TS2 - TT;                              // 30
        const long TOT = (long)BHn * TT * PER;
        for (long i = i0; i < TOT; i += nb * 256) {
            long row = i / PER, j = i - row * PER;
            g_s[(size_t)row * TS2 + TT + j] = -1e30f;
        }
    }
}

// ---- LN row stats (+ optional embed materialization into g_h for layer 0) ----
__global__ void ln_stats(const float* __restrict__ x, const float* __restrict__ cls,
                         const float* __restrict__ dict, int first) {
    int row = blockIdx.x * 8 + (threadIdx.x >> 5);   // 8 warps, one row each
    int lane = threadIdx.x & 31;
    float v[8];
    if (first) {
        int b = row / TT, t = row - b * TT;
        const float* src;
        if (t < NTOK)        src = x + ((size_t)b * NTOK + t) * DD;
        else if (t == NTOK)  src = cls;
        else                 src = dict;
        float4 a0 = *(const float4*)(src + lane * 8);
        float4 a1 = *(const float4*)(src + lane * 8 + 4);
        v[0]=a0.x; v[1]=a0.y; v[2]=a0.z; v[3]=a0.w;
        v[4]=a1.x; v[5]=a1.y; v[6]=a1.z; v[7]=a1.w;
        float4* dst = (float4*)(g_h + (size_t)row * DD + lane * 8);
        dst[0] = a0; dst[1] = a1;
    } else {
        float4 a0 = *(const float4*)(g_h + (size_t)row * DD + lane * 8);
        float4 a1 = *(const float4*)(g_h + (size_t)row * DD + lane * 8 + 4);
        v[0]=a0.x; v[1]=a0.y; v[2]=a0.z; v[3]=a0.w;
        v[4]=a1.x; v[5]=a1.y; v[6]=a1.z; v[7]=a1.w;
    }
    float s = 0.f, s2 = 0.f;
    #pragma unroll
    for (int i = 0; i < 8; i++) { s += v[i]; s2 += v[i] * v[i]; }
    #pragma unroll
    for (int o = 16; o > 0; o >>= 1) {
        s  += __shfl_xor_sync(0xFFFFFFFFu, s,  o);
        s2 += __shfl_xor_sync(0xFFFFFFFFu, s2, o);
    }
    if (lane == 0) {
        float mean = s * (1.0f / DD);
        float var  = s2 * (1.0f / DD) - mean * mean;
        g_lnm[row] = mean;
        g_lnr[row] = rsqrtf(var + 1e-5f);
    }
}

// ---- transpose V: [bh][t][f] -> vT [bh][f][t(pad KATT)] (hi only) ----
__global__ void transpose_v() {
    __shared__ hf th[32][33];
    int bh = blockIdx.z;
    int f0 = blockIdx.x * 32, t0 = blockIdx.y * 32;
    int tx = threadIdx.x, ty = threadIdx.y;   // 32 x 8
    const hf* vh = g_vh + (size_t)bh * TT * DD;
    #pragma unroll
    for (int i = 0; i < 4; i++) {
        int t = t0 + ty + i * 8;
        hf a = __float2half(0.f);
        if (t < TT) a = vh[(size_t)t * DD + f0 + tx];
        th[ty + i * 8][tx] = a;
    }
    __syncthreads();
    hf* dH = g_vTh + (size_t)bh * DD * KATT;
    #pragma unroll
    for (int i = 0; i < 4; i++) {
        int f = f0 + ty + i * 8, t = t0 + tx;
        dH[(size_t)f * KATT + t] = th[tx][ty + i * 8];
    }
}

// ---- attention row reduce: max + 1/sum(exp) over each score row ----
__global__ void attn_reduce() {
    int row = blockIdx.x;                       // bh*TT + t
    const float* p = g_s + (size_t)row * TS2;
    int tid = threadIdx.x;
    float v[5];
    float mx = -1e30f;
    #pragma unroll
    for (int it = 0; it < 5; it++) {
        int j = tid + it * 256;
        if (j < TT) { v[it] = p[j]; mx = fmaxf(mx, v[it]); }
    }
    __shared__ float red_m[8], red_s[8];
    #pragma unroll
    for (int o = 16; o > 0; o >>= 1) mx = fmaxf(mx, __shfl_xor_sync(0xFFFFFFFFu, mx, o));
    if ((tid & 31) == 0) red_m[tid >> 5] = mx;
    __syncthreads();
    if (tid < 32) {
        float a = (tid < 8) ? red_m[tid] : -1e30f;
        #pragma unroll
        for (int o = 4; o > 0; o >>= 1) a = fmaxf(a, __shfl_xor_sync(0xFFFFFFFFu, a, o));
        if (tid == 0) red_m[0] = a;
    }
    __syncthreads();
    mx = red_m[0];
    float sum = 0.f;
    #pragma unroll
    for (int it = 0; it < 5; it++) {
        int j = tid + it * 256;
        if (j < TT) sum += __expf(v[it] - mx);
    }
    #pragma unroll
    for (int o = 16; o > 0; o >>= 1) sum += __shfl_xor_sync(0xFFFFFFFFu, sum, o);
    if ((tid & 31) == 0) red_s[tid >> 5] = sum;
    __syncthreads();
    if (tid < 32) {
        float a = (tid < 8) ? red_s[tid] : 0.f;
        #pragma unroll
        for (int o = 4; o > 0; o >>= 1) a += __shfl_xor_sync(0xFFFFFFFFu, a, o);
        if (tid == 0) { g_rmax[row] = mx; g_rinv[row] = 1.0f / a; }
    }
}

// ---- final output split ----
__global__ void out_kernel(float* __restrict__ out) {
    long i = (long)blockIdx.x * blockDim.x + threadIdx.x;
    if (i >= (long)MM * DD) return;
    int d = (int)(i % DD);
    long r = i / DD;
    int t = (int)(r % TT);
    int b = (int)(r / TT);
    float v = g_h[i];
    if (t < NTOK)        out[((long)b * NTOK + t) * DD + d] = v;
    else if (t == NTOK)  out[(long)BB * NTOK * DD + (long)b * DD + d] = v;
    else                 out[(long)BB * NTOK * DD + (long)BB * DD + (long)b * DD + d] = v;
}

extern "C" void kernel_launch(void* const* d_in, const int* in_sizes, int n_in,
                              void* d_out, int out_size) {
    const float* x      = (const float*)d_in[0];
    const float* cls    = (const float*)d_in[1];
    const float* dict   = (const float*)d_in[2];
    const float* ln1_g  = (const float*)d_in[3];
    const float* ln1_b  = (const float*)d_in[4];
    const float* qkv_w  = (const float*)d_in[5];
    const float* qkv_b  = (const float*)d_in[6];
    const float* proj_w = (const float*)d_in[7];
    const float* proj_b = (const float*)d_in[8];
    const float* ln2_g  = (const float*)d_in[9];
    const float* ln2_b  = (const float*)d_in[10];
    const float* mlp_w1 = (const float*)d_in[11];
    const float* mlp_b1 = (const float*)d_in[12];
    const float* mlp_w2 = (const float*)d_in[13];
    const float* mlp_b2 = (const float*)d_in[14];

    cudaFuncSetAttribute(mma_gemm<0,0,2>, cudaFuncAttributeMaxDynamicSharedMemorySize, SMEM_DYN);
    cudaFuncSetAttribute(mma_gemm<1,2,3>, cudaFuncAttributeMaxDynamicSharedMemorySize, SMEM_DYN);
    cudaFuncSetAttribute(mma_gemm<2,1,2>, cudaFuncAttributeMaxDynamicSharedMemorySize, SMEM_DYN);
    cudaFuncSetAttribute(mma_gemm<3,0,3>, cudaFuncAttributeMaxDynamicSharedMemorySize, SMEM_DYN);
    cudaFuncSetAttribute(mma_gemm<4,2,3>, cudaFuncAttributeMaxDynamicSharedMemorySize, SMEM_DYN);
    cudaFuncSetAttribute(mma_gemm<5,0,3>, cudaFuncAttributeMaxDynamicSharedMemorySize, SMEM_DYN);

    float *gh, *gs, *qkvb;
    hf *qh, *ql, *kh, *vTh, *oh, *ol, *mh, *ml;
    hf *qkvTh, *qkvTl, *projTh, *projTl, *w1Th, *w1Tl, *w2Th, *w2Tl;
    cudaGetSymbolAddress((void**)&gh,  g_h);
    cudaGetSymbolAddress((void**)&gs,  g_s);
    cudaGetSymbolAddress((void**)&qkvb, g_qkvb);
    cudaGetSymbolAddress((void**)&qh,  g_qh);
    cudaGetSymbolAddress((void**)&ql,  g_ql);
    cudaGetSymbolAddress((void**)&kh,  g_kh);
    cudaGetSymbolAddress((void**)&vTh, g_vTh);
    cudaGetSymbolAddress((void**)&oh,  g_oh);
    cudaGetSymbolAddress((void**)&ol,  g_ol);
    cudaGetSymbolAddress((void**)&mh,  g_mh);
    cudaGetSymbolAddress((void**)&ml,  g_ml);
    cudaGetSymbolAddress((void**)&qkvTh, g_qkvTh);
    cudaGetSymbolAddress((void**)&qkvTl, g_qkvTl);
    cudaGetSymbolAddress((void**)&projTh, g_projTh);
    cudaGetSymbolAddress((void**)&projTl, g_projTl);
    cudaGetSymbolAddress((void**)&w1Th, g_w1Th);
    cudaGetSymbolAddress((void**)&w1Tl, g_w1Tl);
    cudaGetSymbolAddress((void**)&w2Th, g_w2Th);
    cudaGetSymbolAddress((void**)&w2Tl, g_w2Tl);

    dim3 tb(32, 8);
    // launch 0, 1: weight prep
    tsplit_qkv <<<dim3(HD3/32, DD/32, LL+1), tb>>>(qkv_w, qkv_b);
    tsplit_rest<<<dim3(32, 64, 3*LL+1), tb>>>(proj_w, mlp_w1, mlp_w2);

    for (int l = 0; l < LL; l++) {
        // launch 2 (l=0): LN1 stats (+ embed for layer 0)
        ln_stats<<<MM/8, 256>>>(x, cls, dict, l == 0 ? 1 : 0);

        // launch 3 (l=0): QKV GEMM with fused LN A-load  <- ncu capture target
        mma_gemm<1,2,3><<<dim3(HD3/128, (MM+127)/128, 1), 256, SMEM_DYN>>>(
            nullptr, nullptr, 0, 0,
            qkvTh + (size_t)l*HD3*DD, qkvTl + (size_t)l*HD3*DD, DD, 0,
            qkvb + (size_t)l*HD3, ln1_g + (size_t)l*DD, ln1_b + (size_t)l*DD,
            nullptr, 0, 0, MM, HD3, DD);

        transpose_v<<<dim3(DD/32, KATT/32, BHn), tb>>>();

        // scores = Q K^T (2-pass: K hi only), batched over 64 heads
        mma_gemm<0,0,2><<<dim3((TT+127)/128, (TT+127)/128, BHn), 256, SMEM_DYN>>>(
            qh, ql, DD, (long)TT*DD,
            kh, nullptr, DD, (long)TT*DD,
            nullptr, nullptr, nullptr, gs, TS2, (long)TT*TS2, TT, TT, DD);

        attn_reduce<<<BHn*TT, 256>>>();

        // O = exp(S-max) V * (1/sum): fused exp A-load, V hi only (2-pass)
        mma_gemm<2,1,2><<<dim3(DD/128, (TT+127)/128, BHn), 256, SMEM_DYN>>>(
            nullptr, nullptr, 0, 0,
            vTh, nullptr, KATT, (long)DD*KATT,
            nullptr, nullptr, nullptr, nullptr, 0, 0, TT, DD, KATT);

        // proj: [8208,2048] x [256,2048]^T -> fp32 h
        mma_gemm<3,0,3><<<dim3(DD/128, (MM+127)/128, 1), 256, SMEM_DYN>>>(
            oh, ol, OD, 0,
            projTh + (size_t)l*DD*OD, projTl + (size_t)l*DD*OD, OD, 0,
            proj_b + (size_t)l*DD, nullptr, nullptr, gh, DD, 0, MM, DD, OD);

        // LN2 stats
        ln_stats<<<MM/8, 256>>>(x, cls, dict, 0);

        // mlp1 with fused LN A-load, + gelu -> m split
        mma_gemm<4,2,3><<<dim3(ED/128, (MM+127)/128, 1), 256, SMEM_DYN>>>(
            nullptr, nullptr, 0, 0,
            w1Th + (size_t)l*ED*DD, w1Tl + (size_t)l*ED*DD, DD, 0,
            mlp_b1 + (size_t)l*ED, ln2_g + (size_t)l*DD, ln2_b + (size_t)l*DD,
            nullptr, 0, 0, MM, ED, DD);

        // mlp2 + gelu -> fp32 h
        mma_gemm<5,0,3><<<dim3(DD/128, (MM+127)/128, 1), 256, SMEM_DYN>>>(
            mh, ml, ED, 0,
            w2Th + (size_t)l*DD*ED, w2Tl + (size_t)l*DD*ED, ED, 0,
            mlp_b2 + (size_t)l*DD, nullptr, nullptr, gh, DD, 0, MM, DD, ED);
    }

    long total = (long)MM * DD;
    out_kernel<<<(unsigned)((total + 255) / 256), 256>>>((float*)d_out);
}

// round 7
// speedup vs baseline: 1.1842x; 1.0057x over previous
#include <cuda_runtime.h>
#include <cuda_fp16.h>
#include <math.h>
#include <stdint.h>

// ---- problem constants ----
#define BB 8
#define NTOK 1024
#define TT 1026            // N + cls + dict
#define DD 256
#define HH 8
#define LL 6
#define HD3 6144           // H*D*3
#define OD 2048            // H*D
#define ED 1024            // EXP*D
#define MM (BB*TT)         // 8208 rows
#define BHn (BB*HH)        // 64
#define TS2 1056           // padded fp32 score row stride (= padded attention K)
#define KATT 1056          // padded key count for WV GEMM

typedef __half hf;

// ---- scratch (device globals; no allocs allowed) ----
__device__ __align__(16) float g_h [(size_t)MM*DD];
__device__ __align__(16) float g_s [(size_t)BHn*TT*TS2];
__device__ __align__(16) float g_rmax[(size_t)BHn*TT];
__device__ __align__(16) float g_rinv[(size_t)BHn*TT];
__device__ __align__(16) float g_lnm[(size_t)MM];
__device__ __align__(16) float g_lnr[(size_t)MM];
__device__ __align__(16) float g_qkvb[(size_t)LL*HD3];
__device__ __align__(16) hf g_qh[(size_t)BHn*TT*DD];
__device__ __align__(16) hf g_ql[(size_t)BHn*TT*DD];
__device__ __align__(16) hf g_kh[(size_t)BHn*TT*DD];
__device__ __align__(16) hf g_vh[(size_t)BHn*TT*DD];
__device__ __align__(16) hf g_vTh[(size_t)BHn*DD*KATT];
__device__ __align__(16) hf g_oh[(size_t)MM*OD];
__device__ __align__(16) hf g_ol[(size_t)MM*OD];
__device__ __align__(16) hf g_mh[(size_t)MM*ED];
__device__ __align__(16) hf g_ml[(size_t)MM*ED];
// transposed + split weights [N,K] per layer
__device__ __align__(16) hf g_qkvTh[(size_t)LL*HD3*DD];
__device__ __align__(16) hf g_qkvTl[(size_t)LL*HD3*DD];
__device__ __align__(16) hf g_projTh[(size_t)LL*DD*OD];
__device__ __align__(16) hf g_projTl[(size_t)LL*DD*OD];
__device__ __align__(16) hf g_w1Th[(size_t)LL*ED*DD];
__device__ __align__(16) hf g_w1Tl[(size_t)LL*ED*DD];
__device__ __align__(16) hf g_w2Th[(size_t)LL*DD*ED];
__device__ __align__(16) hf g_w2Tl[(size_t)LL*DD*ED];

__device__ __forceinline__ float gelu_exact(float x) {
    return 0.5f * x * (1.0f + erff(x * 0.70710678118654752440f));
}

__device__ __forceinline__ uint32_t smem_u32(const void* p) {
    uint32_t a;
    asm("{ .reg .u64 t; cvta.to.shared.u64 t, %1; cvt.u32.u64 %0, t; }" : "=r"(a) : "l"(p));
    return a;
}

__device__ __forceinline__ void ldsm4(uint32_t* r, uint32_t addr) {
    asm volatile("ldmatrix.sync.aligned.m8n8.x4.shared.b16 {%0,%1,%2,%3}, [%4];"
                 : "=r"(r[0]), "=r"(r[1]), "=r"(r[2]), "=r"(r[3]) : "r"(addr));
}

__device__ __forceinline__ void mma16816(float* d, const uint32_t* a, const uint32_t* b) {
    asm volatile(
        "mma.sync.aligned.m16n8k16.row.col.f32.f16.f16.f32 "
        "{%0,%1,%2,%3}, {%4,%5,%6,%7}, {%8,%9}, {%0,%1,%2,%3};"
        : "+f"(d[0]), "+f"(d[1]), "+f"(d[2]), "+f"(d[3])
        : "r"(a[0]), "r"(a[1]), "r"(a[2]), "r"(a[3]), "r"(b[0]), "r"(b[1]));
}

__device__ __forceinline__ void cpa16(uint32_t dst, const void* src, bool v) {
    int sz = v ? 16 : 0;
    asm volatile("cp.async.cg.shared.global [%0], [%1], 16, %2;"
                 :: "r"(dst), "l"(src), "r"(sz) : "memory");
}
__device__ __forceinline__ void cpa_commit() {
    asm volatile("cp.async.commit_group;" ::: "memory");
}

__device__ __forceinline__ void split_store(hf* dh, hf* dl, size_t off, float v) {
    hf h = __float2half_rn(v);
    dh[off] = h;
    dl[off] = __float2half_rn(v - __half2float(h));
}

// pack 8 fp32 into hi/lo half uint4s
__device__ __forceinline__ void pack8(const float* p, uint4& h, uint4& l) {
    __half2 hh[4], ll[4];
    #pragma unroll
    for (int i = 0; i < 4; i++) {
        __half a = __float2half_rn(p[2*i]);
        __half b = __float2half_rn(p[2*i+1]);
        hh[i] = __halves2half2(a, b);
        ll[i] = __halves2half2(__float2half_rn(p[2*i]   - __half2float(a)),
                               __float2half_rn(p[2*i+1] - __half2float(b)));
    }
    h = *(uint4*)hh;
    l = *(uint4*)ll;
}

// per-element epilogue
template<int EPI>
__device__ __forceinline__ void epi_store(int gm, int gn, float v, int M, int N,
                                          const float* __restrict__ bias,
                                          float* __restrict__ C, int ldc, long sC, int z) {
    if (gm >= M || gn >= N) return;
    if constexpr (EPI == 0) {                 // scores -> fp32 (ldc=TS2)
        C[(size_t)z * sC + (size_t)gm * ldc + gn] = v;
    } else if constexpr (EPI == 1) {          // qkv scatter (permuted cols: c*2048+h*256+f)
        v += bias[gn];
        int c = gn >> 11;
        int rem = gn & 2047;
        int h = rem >> 8, f = rem & 255;
        int b = gm / TT, t = gm - b * TT;
        int bh = b * HH + h;
        size_t o = ((size_t)bh * TT + t) * DD + f;
        if (c == 2) {
            g_vh[o] = __float2half_rn(v);     // hi only (2-pass WV)
        } else {
            v *= 0.0625f;                     // 1/sqrt(256)
            if (c == 0) split_store(g_qh, g_ql, o, v);
            else        g_kh[o] = __float2half_rn(v);  // hi only (2-pass scores)
        }
    } else if constexpr (EPI == 2) {          // WV -> normalize by 1/rowsum, split to o
        v *= g_rinv[(size_t)z * TT + gm];
        int b = z >> 3, head = z & 7;
        split_store(g_oh, g_ol, ((size_t)b * TT + gm) * OD + (size_t)head * DD + gn, v);
    } else if constexpr (EPI == 3) {          // proj -> fp32 + bias
        C[(size_t)gm * ldc + gn] = v + bias[gn];
    } else if constexpr (EPI == 4) {          // mlp1: bias+gelu -> m split
        split_store(g_mh, g_ml, (size_t)gm * ED + gn, gelu_exact(v + bias[gn]));
    } else {                                  // mlp2: bias+gelu -> fp32
        C[(size_t)gm * ldc + gn] = gelu_exact(v + bias[gn]);
    }
}

// ============ HMMA fp16 split GEMM: 128x128 block, BK=32, cp.async 2-stage ============
// A: [M,K] K-major (hi/lo). B: [N,K] K-major (hi[/lo]). D = A @ B^T.
// MODE 0: A hi/lo via cp.async.
// MODE 1: A = exp(score - rowmax) computed from g_s on the fly (stride TS2, batch z).
// MODE 2: A = LayerNorm(g_h row) via g_lnm/g_lnr stats + lng/lnb, split on the fly.
// NPASS 3: Ah*Bh + Al*Bh + Ah*Bl.  NPASS 2: Ah*Bh + Al*Bh (B-lo dropped).
// MMA order is pass-major within each np block: dependent MMAs on the same
// accumulator are 4 independent MMAs apart (RAW latency hiding).
#define SLD 40            // padded smem row stride in halves (80 bytes)
#define STG_BYTES 40960
#define AH_OFF 0
#define AL_OFF 10240
#define BH_OFF 20480
#define BL_OFF 30720
#define SMEM_DYN (2*STG_BYTES)

template<int EPI, int MODE, int NPASS>
__global__ void __launch_bounds__(256, 2) mma_gemm(
    const hf* __restrict__ Ah, const hf* __restrict__ Al, int lda, long sA,
    const hf* __restrict__ Bh, const hf* __restrict__ Bl, int ldb, long sB,
    const float* __restrict__ bias,
    const float* __restrict__ lng, const float* __restrict__ lnb,
    float* __restrict__ C, int ldc, long sC,
    int M, int N, int K)
{
    extern __shared__ char smdyn[];
    uint32_t sb = smem_u32(smdyn);

    int tid = threadIdx.x, lane = tid & 31, wid = tid >> 5;
    int wm = wid >> 1, wn = wid & 1;
    int z = blockIdx.z;
    Bh += (size_t)z * sB;
    if constexpr (NPASS == 3) Bl += (size_t)z * sB;
    int bm = blockIdx.y * 128, bn = blockIdx.x * 128;

    int row0 = tid >> 2, row1 = row0 + 64;
    int cvb = (tid & 3) * 16;                 // byte offset within 64B half-row
    int cofs = (tid & 3) * 8;                 // element offset (8 elems per thread)
    bool aval0 = (bm + row0) < M, aval1 = (bm + row1) < M;
    bool bval0 = (bn + row0) < N, bval1 = (bn + row1) < N;
    const char* pBh0 = (const char*)(Bh + (size_t)(bval0 ? bn + row0 : 0) * ldb) + cvb;
    const char* pBh1 = (const char*)(Bh + (size_t)(bval1 ? bn + row1 : 0) * ldb) + cvb;
    const char* pBl0 = nullptr; const char* pBl1 = nullptr;
    if constexpr (NPASS == 3) {
        pBl0 = (const char*)(Bl + (size_t)(bval0 ? bn + row0 : 0) * ldb) + cvb;
        pBl1 = (const char*)(Bl + (size_t)(bval1 ? bn + row1 : 0) * ldb) + cvb;
    }
    uint32_t st0 = (uint32_t)(row0 * SLD * 2) + (uint32_t)cvb;
    uint32_t st1 = (uint32_t)(row1 * SLD * 2) + (uint32_t)cvb;

    // A sources
    const char *pAh0 = nullptr, *pAh1 = nullptr, *pAl0 = nullptr, *pAl1 = nullptr;
    const float *pS0 = nullptr, *pS1 = nullptr;
    float rm0 = 0.f, rm1 = 0.f, rr0 = 0.f, rr1 = 0.f;
    if constexpr (MODE == 1) {
        const float* Sz = g_s + (size_t)z * TT * TS2;
        pS0 = Sz + (size_t)(aval0 ? bm + row0 : 0) * TS2 + cofs;
        pS1 = Sz + (size_t)(aval1 ? bm + row1 : 0) * TS2 + cofs;
        if (aval0) rm0 = g_rmax[(size_t)z * TT + bm + row0];
        if (aval1) rm1 = g_rmax[(size_t)z * TT + bm + row1];
    } else if constexpr (MODE == 2) {
        pS0 = g_h + (size_t)(aval0 ? bm + row0 : 0) * DD + cofs;
        pS1 = g_h + (size_t)(aval1 ? bm + row1 : 0) * DD + cofs;
        if (aval0) { rm0 = g_lnm[bm + row0]; rr0 = g_lnr[bm + row0]; }
        if (aval1) { rm1 = g_lnm[bm + row1]; rr1 = g_lnr[bm + row1]; }
    } else {
        Ah += (size_t)z * sA;  Al += (size_t)z * sA;
        pAh0 = (const char*)(Ah + (size_t)(aval0 ? bm + row0 : 0) * lda) + cvb;
        pAh1 = (const char*)(Ah + (size_t)(aval1 ? bm + row1 : 0) * lda) + cvb;
        pAl0 = (const char*)(Al + (size_t)(aval0 ? bm + row0 : 0) * lda) + cvb;
        pAl1 = (const char*)(Al + (size_t)(aval1 ? bm + row1 : 0) * lda) + cvb;
    }

    float d[2][8][4];
    #pragma unroll
    for (int i = 0; i < 2; i++)
        #pragma unroll
        for (int j = 0; j < 8; j++)
            #pragma unroll
            for (int q = 0; q < 4; q++) d[i][j][q] = 0.f;

    // ldmatrix lane addressing
    int group = lane >> 3, lrow = lane & 7;
    int a_row = wm * 32 + (group & 1) * 8 + lrow;
    int a_ko  = (group >> 1) * 8;
    int b_row = wn * 64 + (group >> 1) * 8 + lrow;
    int b_ko  = (group & 1) * 8;
    uint32_t aoff = (uint32_t)(a_row * SLD + a_ko) * 2;
    uint32_t boff = (uint32_t)(b_row * SLD + b_ko) * 2;

    auto issue = [&](int c, int stg) {
        uint32_t s0 = sb + (uint32_t)stg * STG_BYTES;
        size_t adv = (size_t)c * 64;          // 32 halves = 64 bytes
        if constexpr (MODE == 0) {
            cpa16(s0 + AH_OFF + st0, pAh0 + adv, aval0);
            cpa16(s0 + AH_OFF + st1, pAh1 + adv, aval1);
            cpa16(s0 + AL_OFF + st0, pAl0 + adv, aval0);
            cpa16(s0 + AL_OFF + st1, pAl1 + adv, aval1);
        }
        cpa16(s0 + BH_OFF + st0, pBh0 + adv, bval0);
        cpa16(s0 + BH_OFF + st1, pBh1 + adv, bval1);
        if constexpr (NPASS == 3) {
            cpa16(s0 + BL_OFF + st0, pBl0 + adv, bval0);
            cpa16(s0 + BL_OFF + st1, pBl1 + adv, bval1);
        }
        cpa_commit();
    };

    uint4 ah0, al0, ah1, al1, nh0, nl0, nh1, nl1;
    auto loadA = [&](int c, uint4& h0, uint4& l0, uint4& h1, uint4& l1) {
        int kc = c * 32;
        float4 x0 = *(const float4*)(pS0 + kc);
        float4 x1 = *(const float4*)(pS0 + kc + 4);
        float4 y0 = *(const float4*)(pS1 + kc);
        float4 y1 = *(const float4*)(pS1 + kc + 4);
        float p[8];
        if constexpr (MODE == 1) {
            p[0] = aval0 ? __expf(x0.x - rm0) : 0.f;
            p[1] = aval0 ? __expf(x0.y - rm0) : 0.f;
            p[2] = aval0 ? __expf(x0.z - rm0) : 0.f;
            p[3] = aval0 ? __expf(x0.w - rm0) : 0.f;
            p[4] = aval0 ? __expf(x1.x - rm0) : 0.f;
            p[5] = aval0 ? __expf(x1.y - rm0) : 0.f;
            p[6] = aval0 ? __expf(x1.z - rm0) : 0.f;
            p[7] = aval0 ? __expf(x1.w - rm0) : 0.f;
            pack8(p, h0, l0);
            p[0] = aval1 ? __expf(y0.x - rm1) : 0.f;
            p[1] = aval1 ? __expf(y0.y - rm1) : 0.f;
            p[2] = aval1 ? __expf(y0.z - rm1) : 0.f;
            p[3] = aval1 ? __expf(y0.w - rm1) : 0.f;
            p[4] = aval1 ? __expf(y1.x - rm1) : 0.f;
            p[5] = aval1 ? __expf(y1.y - rm1) : 0.f;
            p[6] = aval1 ? __expf(y1.z - rm1) : 0.f;
            p[7] = aval1 ? __expf(y1.w - rm1) : 0.f;
            pack8(p, h1, l1);
        } else {  // MODE == 2: LayerNorm transform
            const float* gk = lng + kc + cofs;
            const float* bk = lnb + kc + cofs;
            float4 g0 = *(const float4*)gk, g1 = *(const float4*)(gk + 4);
            float4 b0 = *(const float4*)bk, b1 = *(const float4*)(bk + 4);
            p[0] = aval0 ? (x0.x - rm0) * rr0 * g0.x + b0.x : 0.f;
            p[1] = aval0 ? (x0.y - rm0) * rr0 * g0.y + b0.y : 0.f;
            p[2] = aval0 ? (x0.z - rm0) * rr0 * g0.z + b0.z : 0.f;
            p[3] = aval0 ? (x0.w - rm0) * rr0 * g0.w + b0.w : 0.f;
            p[4] = aval0 ? (x1.x - rm0) * rr0 * g1.x + b1.x : 0.f;
            p[5] = aval0 ? (x1.y - rm0) * rr0 * g1.y + b1.y : 0.f;
            p[6] = aval0 ? (x1.z - rm0) * rr0 * g1.z + b1.z : 0.f;
            p[7] = aval0 ? (x1.w - rm0) * rr0 * g1.w + b1.w : 0.f;
            pack8(p, h0, l0);
            p[0] = aval1 ? (y0.x - rm1) * rr1 * g0.x + b0.x : 0.f;
            p[1] = aval1 ? (y0.y - rm1) * rr1 * g0.y + b0.y : 0.f;
            p[2] = aval1 ? (y0.z - rm1) * rr1 * g0.z + b0.z : 0.f;
            p[3] = aval1 ? (y0.w - rm1) * rr1 * g0.w + b0.w : 0.f;
            p[4] = aval1 ? (y1.x - rm1) * rr1 * g1.x + b1.x : 0.f;
            p[5] = aval1 ? (y1.y - rm1) * rr1 * g1.y + b1.y : 0.f;
            p[6] = aval1 ? (y1.z - rm1) * rr1 * g1.z + b1.z : 0.f;
            p[7] = aval1 ? (y1.w - rm1) * rr1 * g1.w + b1.w : 0.f;
            pack8(p, h1, l1);
        }
    };

    int nit = K >> 5;
    if constexpr (MODE != 0) loadA(0, ah0, al0, ah1, al1);
    issue(0, 0);

    for (int c = 0; c < nit; c++) {
        uint32_t cb = sb + (uint32_t)(c & 1) * STG_BYTES;
        if constexpr (MODE != 0) {
            char* as = smdyn + (size_t)(c & 1) * STG_BYTES;
            *(uint4*)(as + AH_OFF + st0) = ah0;
            *(uint4*)(as + AL_OFF + st0) = al0;
            *(uint4*)(as + AH_OFF + st1) = ah1;
            *(uint4*)(as + AL_OFF + st1) = al1;
        }
        if (c + 1 < nit) {
            issue(c + 1, (c + 1) & 1);
            asm volatile("cp.async.wait_group 1;" ::: "memory");
            if constexpr (MODE != 0) loadA(c + 1, nh0, nl0, nh1, nl1);
        } else {
            asm volatile("cp.async.wait_group 0;" ::: "memory");
        }
        __syncthreads();

        #pragma unroll
        for (int ks = 0; ks < 32; ks += 16) {
            uint32_t a_hf[2][4], a_lf[2][4];
            #pragma unroll
            for (int mt = 0; mt < 2; mt++) {
                uint32_t o = cb + aoff + (uint32_t)((mt * 16 * SLD + ks) * 2);
                ldsm4(a_hf[mt], o + AH_OFF);
                ldsm4(a_lf[mt], o + AL_OFF);
            }
            #pragma unroll
            for (int np = 0; np < 4; np++) {
                uint32_t b_hf[4], b_lf[4];
                uint32_t o = cb + boff + (uint32_t)((np * 16 * SLD + ks) * 2);
                ldsm4(b_hf, o + BH_OFF);
                if constexpr (NPASS == 3) ldsm4(b_lf, o + BL_OFF);
                // pass-major: dependent MMAs on one accumulator are 4 apart
                #pragma unroll
                for (int mt = 0; mt < 2; mt++)
                    #pragma unroll
                    for (int hq = 0; hq < 2; hq++)
                        mma16816(d[mt][np * 2 + hq], a_hf[mt], &b_hf[hq * 2]);
                #pragma unroll
                for (int mt = 0; mt < 2; mt++)
                    #pragma unroll
                    for (int hq = 0; hq < 2; hq++)
                        mma16816(d[mt][np * 2 + hq], a_lf[mt], &b_hf[hq * 2]);
                if constexpr (NPASS == 3) {
                    #pragma unroll
                    for (int mt = 0; mt < 2; mt++)
                        #pragma unroll
                        for (int hq = 0; hq < 2; hq++)
                            mma16816(d[mt][np * 2 + hq], a_hf[mt], &b_lf[hq * 2]);
                }
            }
        }
        __syncthreads();
        if constexpr (MODE != 0) { ah0 = nh0; al0 = nl0; ah1 = nh1; al1 = nl1; }
    }

    // epilogue
    #pragma unroll
    for (int mt = 0; mt < 2; mt++)
        #pragma unroll
        for (int nt = 0; nt < 8; nt++) {
            int r0 = bm + wm * 32 + mt * 16 + (lane >> 2);
            int c0 = bn + wn * 64 + nt * 8 + (lane & 3) * 2;
            float* dd = d[mt][nt];
            epi_store<EPI>(r0,     c0,     dd[0], M, N, bias, C, ldc, sC, z);
            epi_store<EPI>(r0,     c0 + 1, dd[1], M, N, bias, C, ldc, sC, z);
            epi_store<EPI>(r0 + 8, c0,     dd[2], M, N, bias, C, ldc, sC, z);
            epi_store<EPI>(r0 + 8, c0 + 1, dd[3], M, N, bias, C, ldc, sC, z);
        }
}

// ---- shared transpose+split body: src [K,N] fp32 -> dh/dl [N,K] half ----
template<int PERM>
__device__ __forceinline__ void tsplit_body(const float* __restrict__ src,
                                            hf* __restrict__ dh, hf* __restrict__ dl,
                                            int K, int N) {
    __shared__ float t[32][33];
    int n0 = blockIdx.x * 32, k0 = blockIdx.y * 32;
    int tx = threadIdx.x, ty = threadIdx.y;  // 32 x 8
    #pragma unroll
    for (int i = 0; i < 4; i++) {
        int k = k0 + ty + i * 8, n = n0 + tx;
        if (k < K && n < N) t[ty + i * 8][tx] = src[(size_t)k * N + n];
    }
    __syncthreads();
    #pragma unroll
    for (int i = 0; i < 4; i++) {
        int n = n0 + ty + i * 8, k = k0 + tx;
        if (n < N && k < K) {
            float v = t[tx][ty + i * 8];
            int nd = n;
            if (PERM) {
                int h = n / 768, r = n - h * 768;
                int f = r / 3, c = r - f * 3;
                nd = c * 2048 + h * 256 + f;
            }
            split_store(dh, dl, (size_t)nd * K + k, v);
        }
    }
}

// launch 0: qkv weights (z<LL) + bias permute (z==LL)
__global__ void tsplit_qkv(const float* __restrict__ src, const float* __restrict__ qb) {
    int zl = blockIdx.z;
    if (zl == LL) {
        int bid = blockIdx.y * gridDim.x + blockIdx.x;
        int idx = bid * 256 + threadIdx.y * 32 + threadIdx.x;
        if (idx < LL * HD3) {
            int l = idx / HD3, j = idx - l * HD3;
            int h = j / 768, r = j - h * 768;
            int f = r / 3, c = r - f * 3;
            g_qkvb[(size_t)l * HD3 + c * 2048 + h * 256 + f] = qb[idx];
        }
        return;
    }
    tsplit_body<1>(src + (size_t)zl * DD * HD3,
                   g_qkvTh + (size_t)zl * HD3 * DD, g_qkvTl + (size_t)zl * HD3 * DD,
                   DD, HD3);
}

// launch 1: proj (z<LL), w1 (z<2LL), w2 (z<3LL), score-pad fill (z==3LL)
__global__ void tsplit_rest(const float* __restrict__ pw,
                            const float* __restrict__ w1,
                            const float* __restrict__ w2) {
    int zl = blockIdx.z;
    if (zl < LL) {
        tsplit_body<0>(pw + (size_t)zl * OD * DD,
                       g_projTh + (size_t)zl * DD * OD, g_projTl + (size_t)zl * DD * OD,
                       OD, DD);
    } else if (zl < 2 * LL) {
        int l = zl - LL;
        tsplit_body<0>(w1 + (size_t)l * DD * ED,
                       g_w1Th + (size_t)l * ED * DD, g_w1Tl + (size_t)l * ED * DD,
                       DD, ED);
    } else if (zl < 3 * LL) {
        int l = zl - 2 * LL;
        tsplit_body<0>(w2 + (size_t)l * ED * DD,
                       g_w2Th + (size_t)l * DD * ED, g_w2Tl + (size_t)l * DD * ED,
                       ED, DD);
    } else {
        long nb = (long)gridDim.x * gridDim.y;
        long bid = (long)blockIdx.y * gridDim.x + blockIdx.x;
        long i0 = bid * 256 + threadIdx.y * 32 + threadIdx.x;
        const long PER = TS2 - TT;                              // 30
        const long TOT = (long)BHn * TT * PER;
        for (long i = i0; i < TOT; i += nb * 256) {
            long row = i / PER, j = i - row * PER;
            g_s[(size_t)row * TS2 + TT + j] = -1e30f;
        }
    }
}

// ---- LN row stats (+ optional embed materialization into g_h for layer 0) ----
__global__ void ln_stats(const float* __restrict__ x, const float* __restrict__ cls,
                         const float* __restrict__ dict, int first) {
    int row = blockIdx.x * 8 + (threadIdx.x >> 5);   // 8 warps, one row each
    int lane = threadIdx.x & 31;
    float v[8];
    if (first) {
        int b = row / TT, t = row - b * TT;
        const float* src;
        if (t < NTOK)        src = x + ((size_t)b * NTOK + t) * DD;
        else if (t == NTOK)  src = cls;
        else                 src = dict;
        float4 a0 = *(const float4*)(src + lane * 8);
        float4 a1 = *(const float4*)(src + lane * 8 + 4);
        v[0]=a0.x; v[1]=a0.y; v[2]=a0.z; v[3]=a0.w;
        v[4]=a1.x; v[5]=a1.y; v[6]=a1.z; v[7]=a1.w;
        float4* dst = (float4*)(g_h + (size_t)row * DD + lane * 8);
        dst[0] = a0; dst[1] = a1;
    } else {
        float4 a0 = *(const float4*)(g_h + (size_t)row * DD + lane * 8);
        float4 a1 = *(const float4*)(g_h + (size_t)row * DD + lane * 8 + 4);
        v[0]=a0.x; v[1]=a0.y; v[2]=a0.z; v[3]=a0.w;
        v[4]=a1.x; v[5]=a1.y; v[6]=a1.z; v[7]=a1.w;
    }
    float s = 0.f, s2 = 0.f;
    #pragma unroll
    for (int i = 0; i < 8; i++) { s += v[i]; s2 += v[i] * v[i]; }
    #pragma unroll
    for (int o = 16; o > 0; o >>= 1) {
        s  += __shfl_xor_sync(0xFFFFFFFFu, s,  o);
        s2 += __shfl_xor_sync(0xFFFFFFFFu, s2, o);
    }
    if (lane == 0) {
        float mean = s * (1.0f / DD);
        float var  = s2 * (1.0f / DD) - mean * mean;
        g_lnm[row] = mean;
        g_lnr[row] = rsqrtf(var + 1e-5f);
    }
}

// ---- transpose V: [bh][t][f] -> vT [bh][f][t(pad KATT)] (hi only) ----
__global__ void transpose_v() {
    __shared__ hf th[32][33];
    int bh = blockIdx.z;
    int f0 = blockIdx.x * 32, t0 = blockIdx.y * 32;
    int tx = threadIdx.x, ty = threadIdx.y;   // 32 x 8
    const hf* vh = g_vh + (size_t)bh * TT * DD;
    #pragma unroll
    for (int i = 0; i < 4; i++) {
        int t = t0 + ty + i * 8;
        hf a = __float2half(0.f);
        if (t < TT) a = vh[(size_t)t * DD + f0 + tx];
        th[ty + i * 8][tx] = a;
    }
    __syncthreads();
    hf* dH = g_vTh + (size_t)bh * DD * KATT;
    #pragma unroll
    for (int i = 0; i < 4; i++) {
        int f = f0 + ty + i * 8, t = t0 + tx;
        dH[(size_t)f * KATT + t] = th[tx][ty + i * 8];
    }
}

// ---- attention row reduce: max + 1/sum(exp) over each score row ----
__global__ void attn_reduce() {
    int row = blockIdx.x;                       // bh*TT + t
    const float* p = g_s + (size_t)row * TS2;
    int tid = threadIdx.x;
    float v[5];
    float mx = -1e30f;
    #pragma unroll
    for (int it = 0; it < 5; it++) {
        int j = tid + it * 256;
        if (j < TT) { v[it] = p[j]; mx = fmaxf(mx, v[it]); }
    }
    __shared__ float red_m[8], red_s[8];
    #pragma unroll
    for (int o = 16; o > 0; o >>= 1) mx = fmaxf(mx, __shfl_xor_sync(0xFFFFFFFFu, mx, o));
    if ((tid & 31) == 0) red_m[tid >> 5] = mx;
    __syncthreads();
    if (tid < 32) {
        float a = (tid < 8) ? red_m[tid] : -1e30f;
        #pragma unroll
        for (int o = 4; o > 0; o >>= 1) a = fmaxf(a, __shfl_xor_sync(0xFFFFFFFFu, a, o));
        if (tid == 0) red_m[0] = a;
    }
    __syncthreads();
    mx = red_m[0];
    float sum = 0.f;
    #pragma unroll
    for (int it = 0; it < 5; it++) {
        int j = tid + it * 256;
        if (j < TT) sum += __expf(v[it] - mx);
    }
    #pragma unroll
    for (int o = 16; o > 0; o >>= 1) sum += __shfl_xor_sync(0xFFFFFFFFu, sum, o);
    if ((tid & 31) == 0) red_s[tid >> 5] = sum;
    __syncthreads();
    if (tid < 32) {
        float a = (tid < 8) ? red_s[tid] : 0.f;
        #pragma unroll
        for (int o = 4; o > 0; o >>= 1) a += __shfl_xor_sync(0xFFFFFFFFu, a, o);
        if (tid == 0) { g_rmax[row] = mx; g_rinv[row] = 1.0f / a; }
    }
}

// ---- final output split ----
__global__ void out_kernel(float* __restrict__ out) {
    long i = (long)blockIdx.x * blockDim.x + threadIdx.x;
    if (i >= (long)MM * DD) return;
    int d = (int)(i % DD);
    long r = i / DD;
    int t = (int)(r % TT);
    int b = (int)(r / TT);
    float v = g_h[i];
    if (t < NTOK)        out[((long)b * NTOK + t) * DD + d] = v;
    else if (t == NTOK)  out[(long)BB * NTOK * DD + (long)b * DD + d] = v;
    else                 out[(long)BB * NTOK * DD + (long)BB * DD + (long)b * DD + d] = v;
}

extern "C" void kernel_launch(void* const* d_in, const int* in_sizes, int n_in,
                              void* d_out, int out_size) {
    const float* x      = (const float*)d_in[0];
    const float* cls    = (const float*)d_in[1];
    const float* dict   = (const float*)d_in[2];
    const float* ln1_g  = (const float*)d_in[3];
    const float* ln1_b  = (const float*)d_in[4];
    const float* qkv_w  = (const float*)d_in[5];
    const float* qkv_b  = (const float*)d_in[6];
    const float* proj_w = (const float*)d_in[7];
    const float* proj_b = (const float*)d_in[8];
    const float* ln2_g  = (const float*)d_in[9];
    const float* ln2_b  = (const float*)d_in[10];
    const float* mlp_w1 = (const float*)d_in[11];
    const float* mlp_b1 = (const float*)d_in[12];
    const float* mlp_w2 = (const float*)d_in[13];
    const float* mlp_b2 = (const float*)d_in[14];

    cudaFuncSetAttribute(mma_gemm<0,0,2>, cudaFuncAttributeMaxDynamicSharedMemorySize, SMEM_DYN);
    cudaFuncSetAttribute(mma_gemm<1,2,3>, cudaFuncAttributeMaxDynamicSharedMemorySize, SMEM_DYN);
    cudaFuncSetAttribute(mma_gemm<2,1,2>, cudaFuncAttributeMaxDynamicSharedMemorySize, SMEM_DYN);
    cudaFuncSetAttribute(mma_gemm<3,0,3>, cudaFuncAttributeMaxDynamicSharedMemorySize, SMEM_DYN);
    cudaFuncSetAttribute(mma_gemm<4,2,3>, cudaFuncAttributeMaxDynamicSharedMemorySize, SMEM_DYN);
    cudaFuncSetAttribute(mma_gemm<5,0,3>, cudaFuncAttributeMaxDynamicSharedMemorySize, SMEM_DYN);

    float *gh, *gs, *qkvb;
    hf *qh, *ql, *kh, *vTh, *oh, *ol, *mh, *ml;
    hf *qkvTh, *qkvTl, *projTh, *projTl, *w1Th, *w1Tl, *w2Th, *w2Tl;
    cudaGetSymbolAddress((void**)&gh,  g_h);
    cudaGetSymbolAddress((void**)&gs,  g_s);
    cudaGetSymbolAddress((void**)&qkvb, g_qkvb);
    cudaGetSymbolAddress((void**)&qh,  g_qh);
    cudaGetSymbolAddress((void**)&ql,  g_ql);
    cudaGetSymbolAddress((void**)&kh,  g_kh);
    cudaGetSymbolAddress((void**)&vTh, g_vTh);
    cudaGetSymbolAddress((void**)&oh,  g_oh);
    cudaGetSymbolAddress((void**)&ol,  g_ol);
    cudaGetSymbolAddress((void**)&mh,  g_mh);
    cudaGetSymbolAddress((void**)&ml,  g_ml);
    cudaGetSymbolAddress((void**)&qkvTh, g_qkvTh);
    cudaGetSymbolAddress((void**)&qkvTl, g_qkvTl);
    cudaGetSymbolAddress((void**)&projTh, g_projTh);
    cudaGetSymbolAddress((void**)&projTl, g_projTl);
    cudaGetSymbolAddress((void**)&w1Th, g_w1Th);
    cudaGetSymbolAddress((void**)&w1Tl, g_w1Tl);
    cudaGetSymbolAddress((void**)&w2Th, g_w2Th);
    cudaGetSymbolAddress((void**)&w2Tl, g_w2Tl);

    dim3 tb(32, 8);
    // launch 0, 1: weight prep
    tsplit_qkv <<<dim3(HD3/32, DD/32, LL+1), tb>>>(qkv_w, qkv_b);
    tsplit_rest<<<dim3(32, 64, 3*LL+1), tb>>>(proj_w, mlp_w1, mlp_w2);

    for (int l = 0; l < LL; l++) {
        // launch 2 (l=0): LN1 stats (+ embed for layer 0)
        ln_stats<<<MM/8, 256>>>(x, cls, dict, l == 0 ? 1 : 0);

        // launch 3 (l=0): QKV GEMM with fused LN A-load  <- ncu capture target
        mma_gemm<1,2,3><<<dim3(HD3/128, (MM+127)/128, 1), 256, SMEM_DYN>>>(
            nullptr, nullptr, 0, 0,
            qkvTh + (size_t)l*HD3*DD, qkvTl + (size_t)l*HD3*DD, DD, 0,
            qkvb + (size_t)l*HD3, ln1_g + (size_t)l*DD, ln1_b + (size_t)l*DD,
            nullptr, 0, 0, MM, HD3, DD);

        transpose_v<<<dim3(DD/32, KATT/32, BHn), tb>>>();

        // scores = Q K^T (2-pass: K hi only), batched over 64 heads
        mma_gemm<0,0,2><<<dim3((TT+127)/128, (TT+127)/128, BHn), 256, SMEM_DYN>>>(
            qh, ql, DD, (long)TT*DD,
            kh, nullptr, DD, (long)TT*DD,
            nullptr, nullptr, nullptr, gs, TS2, (long)TT*TS2, TT, TT, DD);

        attn_reduce<<<BHn*TT, 256>>>();

        // O = exp(S-max) V * (1/sum): fused exp A-load, V hi only (2-pass)
        mma_gemm<2,1,2><<<dim3(DD/128, (TT+127)/128, BHn), 256, SMEM_DYN>>>(
            nullptr, nullptr, 0, 0,
            vTh, nullptr, KATT, (long)DD*KATT,
            nullptr, nullptr, nullptr, nullptr, 0, 0, TT, DD, KATT);

        // proj: [8208,2048] x [256,2048]^T -> fp32 h
        mma_gemm<3,0,3><<<dim3(DD/128, (MM+127)/128, 1), 256, SMEM_DYN>>>(
            oh, ol, OD, 0,
            projTh + (size_t)l*DD*OD, projTl + (size_t)l*DD*OD, OD, 0,
            proj_b + (size_t)l*DD, nullptr, nullptr, gh, DD, 0, MM, DD, OD);

        // LN2 stats
        ln_stats<<<MM/8, 256>>>(x, cls, dict, 0);

        // mlp1 with fused LN A-load, + gelu -> m split
        mma_gemm<4,2,3><<<dim3(ED/128, (MM+127)/128, 1), 256, SMEM_DYN>>>(
            nullptr, nullptr, 0, 0,
            w1Th + (size_t)l*ED*DD, w1Tl + (size_t)l*ED*DD, DD, 0,
            mlp_b1 + (size_t)l*ED, ln2_g + (size_t)l*DD, ln2_b + (size_t)l*DD,
            nullptr, 0, 0, MM, ED, DD);

        // mlp2 + gelu -> fp32 h
        mma_gemm<5,0,3><<<dim3(DD/128, (MM+127)/128, 1), 256, SMEM_DYN>>>(
            mh, ml, ED, 0,
            w2Th + (size_t)l*DD*ED, w2Tl + (size_t)l*DD*ED, ED, 0,
            mlp_b2 + (size_t)l*DD, nullptr, nullptr, gh, DD, 0, MM, DD, ED);
    }

    long total = (long)MM * DD;
    out_kernel<<<(unsigned)((total + 255) / 256), 256>>>((float*)d_out);
}

// round 9
// speedup vs baseline: 1.2750x; 1.0766x over previous
#include <cuda_runtime.h>
#include <cuda_fp16.h>
#include <math.h>
#include <stdint.h>

// ---- problem constants ----
#define BB 8
#define NTOK 1024
#define TT 1026            // N + cls + dict
#define DD 256
#define HH 8
#define LL 6
#define HD3 6144           // H*D*3
#define OD 2048            // H*D
#define ED 1024            // EXP*D
#define MM (BB*TT)         // 8208 rows
#define BHn (BB*HH)        // 64
#define TS2 1056           // padded fp32 score row stride (= padded attention K)
#define KATT 1056          // padded key count for WV GEMM

typedef __half hf;

// ---- scratch (device globals; no allocs allowed) ----
__device__ __align__(16) float g_h [(size_t)MM*DD];
__device__ __align__(16) float g_s [(size_t)BHn*TT*TS2];
__device__ __align__(16) float g_rmax[(size_t)BHn*TT];
__device__ __align__(16) float g_rinv[(size_t)BHn*TT];
__device__ __align__(16) float g_lnm[(size_t)MM];
__device__ __align__(16) float g_lnr[(size_t)MM];
__device__ __align__(16) float g_qkvb[(size_t)LL*HD3];
__device__ __align__(16) hf g_qh[(size_t)BHn*TT*DD];
__device__ __align__(16) hf g_ql[(size_t)BHn*TT*DD];
__device__ __align__(16) hf g_kh[(size_t)BHn*TT*DD];
__device__ __align__(16) hf g_vh[(size_t)BHn*TT*DD];
__device__ __align__(16) hf g_vTh[(size_t)BHn*DD*KATT];
__device__ __align__(16) hf g_oh[(size_t)MM*OD];
__device__ __align__(16) hf g_ol[(size_t)MM*OD];
__device__ __align__(16) hf g_mh[(size_t)MM*ED];
__device__ __align__(16) hf g_ml[(size_t)MM*ED];
// transposed + split weights [N,K] per layer
__device__ __align__(16) hf g_qkvTh[(size_t)LL*HD3*DD];
__device__ __align__(16) hf g_qkvTl[(size_t)LL*HD3*DD];
__device__ __align__(16) hf g_projTh[(size_t)LL*DD*OD];
__device__ __align__(16) hf g_projTl[(size_t)LL*DD*OD];
__device__ __align__(16) hf g_w1Th[(size_t)LL*ED*DD];
__device__ __align__(16) hf g_w1Tl[(size_t)LL*ED*DD];
__device__ __align__(16) hf g_w2Th[(size_t)LL*DD*ED];
__device__ __align__(16) hf g_w2Tl[(size_t)LL*DD*ED];

__device__ __forceinline__ float gelu_exact(float x) {
    return 0.5f * x * (1.0f + erff(x * 0.70710678118654752440f));
}

__device__ __forceinline__ uint32_t smem_u32(const void* p) {
    uint32_t a;
    asm("{ .reg .u64 t; cvta.to.shared.u64 t, %1; cvt.u32.u64 %0, t; }" : "=r"(a) : "l"(p));
    return a;
}

__device__ __forceinline__ void ldsm4(uint32_t* r, uint32_t addr) {
    asm volatile("ldmatrix.sync.aligned.m8n8.x4.shared.b16 {%0,%1,%2,%3}, [%4];"
                 : "=r"(r[0]), "=r"(r[1]), "=r"(r[2]), "=r"(r[3]) : "r"(addr));
}

__device__ __forceinline__ void mma16816(float* d, const uint32_t* a, const uint32_t* b) {
    asm volatile(
        "mma.sync.aligned.m16n8k16.row.col.f32.f16.f16.f32 "
        "{%0,%1,%2,%3}, {%4,%5,%6,%7}, {%8,%9}, {%0,%1,%2,%3};"
        : "+f"(d[0]), "+f"(d[1]), "+f"(d[2]), "+f"(d[3])
        : "r"(a[0]), "r"(a[1]), "r"(a[2]), "r"(a[3]), "r"(b[0]), "r"(b[1]));
}

__device__ __forceinline__ void cpa16(uint32_t dst, const void* src, bool v) {
    int sz = v ? 16 : 0;
    asm volatile("cp.async.cg.shared.global [%0], [%1], 16, %2;"
                 :: "r"(dst), "l"(src), "r"(sz) : "memory");
}
__device__ __forceinline__ void cpa_commit() {
    asm volatile("cp.async.commit_group;" ::: "memory");
}

__device__ __forceinline__ void split_store(hf* dh, hf* dl, size_t off, float v) {
    hf h = __float2half_rn(v);
    dh[off] = h;
    dl[off] = __float2half_rn(v - __half2float(h));
}

// pack 8 fp32 into hi/lo half uint4s
__device__ __forceinline__ void pack8(const float* p, uint4& h, uint4& l) {
    __half2 hh[4], ll[4];
    #pragma unroll
    for (int i = 0; i < 4; i++) {
        __half a = __float2half_rn(p[2*i]);
        __half b = __float2half_rn(p[2*i+1]);
        hh[i] = __halves2half2(a, b);
        ll[i] = __halves2half2(__float2half_rn(p[2*i]   - __half2float(a)),
                               __float2half_rn(p[2*i+1] - __half2float(b)));
    }
    h = *(uint4*)hh;
    l = *(uint4*)ll;
}

// per-element epilogue
template<int EPI>
__device__ __forceinline__ void epi_store(int gm, int gn, float v, int M, int N,
                                          const float* __restrict__ bias,
                                          float* __restrict__ C, int ldc, long sC, int z) {
    if (gm >= M || gn >= N) return;
    if constexpr (EPI == 0) {                 // scores -> fp32 (ldc=TS2)
        C[(size_t)z * sC + (size_t)gm * ldc + gn] = v;
    } else if constexpr (EPI == 1) {          // qkv scatter (permuted cols: c*2048+h*256+f)
        v += bias[gn];
        int c = gn >> 11;
        int rem = gn & 2047;
        int h = rem >> 8, f = rem & 255;
        int b = gm / TT, t = gm - b * TT;
        int bh = b * HH + h;
        size_t o = ((size_t)bh * TT + t) * DD + f;
        if (c == 2) {
            g_vh[o] = __float2half_rn(v);     // hi only (2-pass WV)
        } else {
            v *= 0.0625f;                     // 1/sqrt(256)
            if (c == 0) split_store(g_qh, g_ql, o, v);
            else        g_kh[o] = __float2half_rn(v);  // hi only (2-pass scores)
        }
    } else if constexpr (EPI == 2) {          // WV -> normalize by 1/rowsum, split to o
        v *= g_rinv[(size_t)z * TT + gm];
        int b = z >> 3, head = z & 7;
        split_store(g_oh, g_ol, ((size_t)b * TT + gm) * OD + (size_t)head * DD + gn, v);
    } else if constexpr (EPI == 3) {          // proj -> fp32 + bias
        C[(size_t)gm * ldc + gn] = v + bias[gn];
    } else if constexpr (EPI == 4) {          // mlp1: bias+gelu -> m split
        split_store(g_mh, g_ml, (size_t)gm * ED + gn, gelu_exact(v + bias[gn]));
    } else {                                  // mlp2: bias+gelu -> fp32
        C[(size_t)gm * ldc + gn] = gelu_exact(v + bias[gn]);
    }
}

// ============ HMMA fp16 split GEMM: 128x128 block, BK=32, cp.async 3-stage ============
// Tile layout: 64B rows (32 halves), 16B-chunk XOR swizzle:
//   chunk c of row r lives at r*64 + ((c ^ ((r>>1)&3)) * 16)
// -> 16B-aligned cp.async AND conflict-free ldmatrix, no padding.
// MODE 0: A hi/lo via cp.async.
// MODE 1: A = exp(score - rowmax) from g_s on the fly (stride TS2, batch z).
// MODE 2: A = LayerNorm(g_h row) via g_lnm/g_lnr + lng/lnb, split on the fly.
// NPASS 3: Ah*Bh + Al*Bh + Ah*Bl.  NPASS 2: Ah*Bh + Al*Bh.
// 3-stage pipeline, ONE __syncthreads per iter; MODE!=0 raw A loads for c+2
// issue before the MMA block, pack+store after it (latency hidden by MMAs).
#define AH_OFF 0
#define AL_OFF 8192
#define BH_OFF 16384
#define BL_OFF 24576
#define STG_BYTES 32768
#define SMEM_DYN (3*STG_BYTES)

template<int EPI, int MODE, int NPASS>
__global__ void __launch_bounds__(256, 2) mma_gemm(
    const hf* __restrict__ Ah, const hf* __restrict__ Al, int lda, long sA,
    const hf* __restrict__ Bh, const hf* __restrict__ Bl, int ldb, long sB,
    const float* __restrict__ bias,
    const float* __restrict__ lng, const float* __restrict__ lnb,
    float* __restrict__ C, int ldc, long sC,
    int M, int N, int K)
{
    extern __shared__ char smdyn[];
    uint32_t sb = smem_u32(smdyn);

    int tid = threadIdx.x, lane = tid & 31, wid = tid >> 5;
    int wm = wid >> 1, wn = wid & 1;
    int z = blockIdx.z;
    Bh += (size_t)z * sB;
    if constexpr (NPASS == 3) Bl += (size_t)z * sB;
    int bm = blockIdx.y * 128, bn = blockIdx.x * 128;

    int row0 = tid >> 2, row1 = row0 + 64;
    int cv  = tid & 3;                        // 16B chunk index
    int cvb = cv * 16;                        // byte offset in source row
    int cofs = cv * 8;                        // element offset (8 elems)
    bool aval0 = (bm + row0) < M, aval1 = (bm + row1) < M;
    bool bval0 = (bn + row0) < N, bval1 = (bn + row1) < N;
    const char* pBh0 = (const char*)(Bh + (size_t)(bval0 ? bn + row0 : 0) * ldb) + cvb;
    const char* pBh1 = (const char*)(Bh + (size_t)(bval1 ? bn + row1 : 0) * ldb) + cvb;
    const char* pBl0 = nullptr; const char* pBl1 = nullptr;
    if constexpr (NPASS == 3) {
        pBl0 = (const char*)(Bl + (size_t)(bval0 ? bn + row0 : 0) * ldb) + cvb;
        pBl1 = (const char*)(Bl + (size_t)(bval1 ? bn + row1 : 0) * ldb) + cvb;
    }
    // swizzled smem offsets for the two rows this thread fills
    uint32_t st0 = (uint32_t)(row0 * 64 + ((cv ^ ((row0 >> 1) & 3)) * 16));
    uint32_t st1 = (uint32_t)(row1 * 64 + ((cv ^ ((row1 >> 1) & 3)) * 16));

    // A sources
    const char *pAh0 = nullptr, *pAh1 = nullptr, *pAl0 = nullptr, *pAl1 = nullptr;
    const float *pS0 = nullptr, *pS1 = nullptr;
    float rm0 = 0.f, rm1 = 0.f, rr0 = 0.f, rr1 = 0.f;
    if constexpr (MODE == 1) {
        const float* Sz = g_s + (size_t)z * TT * TS2;
        pS0 = Sz + (size_t)(aval0 ? bm + row0 : 0) * TS2 + cofs;
        pS1 = Sz + (size_t)(aval1 ? bm + row1 : 0) * TS2 + cofs;
        if (aval0) rm0 = g_rmax[(size_t)z * TT + bm + row0];
        if (aval1) rm1 = g_rmax[(size_t)z * TT + bm + row1];
    } else if constexpr (MODE == 2) {
        pS0 = g_h + (size_t)(aval0 ? bm + row0 : 0) * DD + cofs;
        pS1 = g_h + (size_t)(aval1 ? bm + row1 : 0) * DD + cofs;
        if (aval0) { rm0 = g_lnm[bm + row0]; rr0 = g_lnr[bm + row0]; }
        if (aval1) { rm1 = g_lnm[bm + row1]; rr1 = g_lnr[bm + row1]; }
    } else {
        Ah += (size_t)z * sA;  Al += (size_t)z * sA;
        pAh0 = (const char*)(Ah + (size_t)(aval0 ? bm + row0 : 0) * lda) + cvb;
        pAh1 = (const char*)(Ah + (size_t)(aval1 ? bm + row1 : 0) * lda) + cvb;
        pAl0 = (const char*)(Al + (size_t)(aval0 ? bm + row0 : 0) * lda) + cvb;
        pAl1 = (const char*)(Al + (size_t)(aval1 ? bm + row1 : 0) * lda) + cvb;
    }

    float d[2][8][4];
    #pragma unroll
    for (int i = 0; i < 2; i++)
        #pragma unroll
        for (int j = 0; j < 8; j++)
            #pragma unroll
            for (int q = 0; q < 4; q++) d[i][j][q] = 0.f;

    // ldmatrix lane addressing (per-lane row + k-chunk)
    int group = lane >> 3, lrow = lane & 7;
    int a_row = wm * 32 + (group & 1) * 8 + lrow;
    int koA   = (group >> 1);                 // k chunk offset 0/1 (8 halves each)
    int b_row = wn * 64 + (group >> 1) * 8 + lrow;
    int koB   = (group & 1);
    int aS = (a_row >> 1) & 3;                // swizzle key; invariant under +16 rows
    int bS = (b_row >> 1) & 3;
    uint32_t aB0 = (uint32_t)(a_row * 64),       aB1 = (uint32_t)((a_row + 16) * 64);
    uint32_t bB[4];
    #pragma unroll
    for (int np = 0; np < 4; np++) bB[np] = (uint32_t)((b_row + np * 16) * 64);

    // issue cp.async for chunk c into stage stg (B always; A only MODE 0)
    auto issue = [&](int c, int stg) {
        uint32_t s0 = sb + (uint32_t)stg * STG_BYTES;
        size_t adv = (size_t)c * 64;          // 32 halves = 64 bytes
        if constexpr (MODE == 0) {
            cpa16(s0 + AH_OFF + st0, pAh0 + adv, aval0);
            cpa16(s0 + AH_OFF + st1, pAh1 + adv, aval1);
            cpa16(s0 + AL_OFF + st0, pAl0 + adv, aval0);
            cpa16(s0 + AL_OFF + st1, pAl1 + adv, aval1);
        }
        cpa16(s0 + BH_OFF + st0, pBh0 + adv, bval0);
        cpa16(s0 + BH_OFF + st1, pBh1 + adv, bval1);
        if constexpr (NPASS == 3) {
            cpa16(s0 + BL_OFF + st0, pBl0 + adv, bval0);
            cpa16(s0 + BL_OFF + st1, pBl1 + adv, bval1);
        }
        cpa_commit();
    };

    float q0[8], q1[8];
    auto loadraw = [&](int c, float* r0, float* r1) {
        int kc = c * 32;
        float4 x0 = *(const float4*)(pS0 + kc);
        float4 x1 = *(const float4*)(pS0 + kc + 4);
        float4 y0 = *(const float4*)(pS1 + kc);
        float4 y1 = *(const float4*)(pS1 + kc + 4);
        r0[0]=x0.x; r0[1]=x0.y; r0[2]=x0.z; r0[3]=x0.w;
        r0[4]=x1.x; r0[5]=x1.y; r0[6]=x1.z; r0[7]=x1.w;
        r1[0]=y0.x; r1[1]=y0.y; r1[2]=y0.z; r1[3]=y0.w;
        r1[4]=y1.x; r1[5]=y1.y; r1[6]=y1.z; r1[7]=y1.w;
    };
    auto packstore = [&](int c, int stg, const float* r0, const float* r1) {
        float p[8];
        uint4 h0, l0, h1, l1;
        if constexpr (MODE == 1) {
            #pragma unroll
            for (int i = 0; i < 8; i++) p[i] = aval0 ? __expf(r0[i] - rm0) : 0.f;
            pack8(p, h0, l0);
            #pragma unroll
            for (int i = 0; i < 8; i++) p[i] = aval1 ? __expf(r1[i] - rm1) : 0.f;
            pack8(p, h1, l1);
        } else {
            int kc = c * 32;
            const float* gk = lng + kc + cofs;
            const float* bk = lnb + kc + cofs;
            #pragma unroll
            for (int i = 0; i < 8; i++)
                p[i] = aval0 ? (r0[i] - rm0) * rr0 * gk[i] + bk[i] : 0.f;
            pack8(p, h0, l0);
            #pragma unroll
            for (int i = 0; i < 8; i++)
                p[i] = aval1 ? (r1[i] - rm1) * rr1 * gk[i] + bk[i] : 0.f;
            pack8(p, h1, l1);
        }
        char* as = smdyn + (size_t)stg * STG_BYTES;
        *(uint4*)(as + AH_OFF + st0) = h0;
        *(uint4*)(as + AL_OFF + st0) = l0;
        *(uint4*)(as + AH_OFF + st1) = h1;
        *(uint4*)(as + AL_OFF + st1) = l1;
    };

    int nit = K >> 5;                         // >= 8 for all our shapes
    if constexpr (MODE != 0) {
        loadraw(0, q0, q1); packstore(0, 0, q0, q1);
        loadraw(1, q0, q1); packstore(1, 1, q0, q1);
    }
    issue(0, 0);
    issue(1, 1);

    int stg_c = 0;                            // c % 3
    for (int c = 0; c < nit; c++) {
        if (c + 1 < nit) {
            asm volatile("cp.async.wait_group 1;" ::: "memory");
        } else {
            asm volatile("cp.async.wait_group 0;" ::: "memory");
        }
        __syncthreads();                      // publish stage c; free stage c-1

        int stg_n = stg_c + 2; if (stg_n >= 3) stg_n -= 3;   // (c+2) % 3
        bool have2 = (c + 2 < nit);
        if (have2) {
            issue(c + 2, stg_n);
            if constexpr (MODE != 0) loadraw(c + 2, q0, q1);
        }

        uint32_t cb = sb + (uint32_t)stg_c * STG_BYTES;
        #pragma unroll
        for (int ks = 0; ks < 32; ks += 16) {
            int kc = ks >> 3;                 // 0 or 2
            uint32_t a_hf[2][4], a_lf[2][4];
            {
                uint32_t sw = (uint32_t)(((kc + koA) ^ aS) << 4);
                uint32_t o0 = cb + aB0 + sw, o1 = cb + aB1 + sw;
                ldsm4(a_hf[0], o0 + AH_OFF);
                ldsm4(a_lf[0], o0 + AL_OFF);
                ldsm4(a_hf[1], o1 + AH_OFF);
                ldsm4(a_lf[1], o1 + AL_OFF);
            }
            uint32_t swb = (uint32_t)(((kc + koB) ^ bS) << 4);
            #pragma unroll
            for (int np = 0; np < 4; np++) {
                uint32_t b_hf[4], b_lf[4];
                uint32_t o = cb + bB[np] + swb;
                ldsm4(b_hf, o + BH_OFF);
                if constexpr (NPASS == 3) ldsm4(b_lf, o + BL_OFF);
                #pragma unroll
                for (int mt = 0; mt < 2; mt++)
                    #pragma unroll
                    for (int hq = 0; hq < 2; hq++)
                        mma16816(d[mt][np * 2 + hq], a_hf[mt], &b_hf[hq * 2]);
                #pragma unroll
                for (int mt = 0; mt < 2; mt++)
                    #pragma unroll
                    for (int hq = 0; hq < 2; hq++)
                        mma16816(d[mt][np * 2 + hq], a_lf[mt], &b_hf[hq * 2]);
                if constexpr (NPASS == 3) {
                    #pragma unroll
                    for (int mt = 0; mt < 2; mt++)
                        #pragma unroll
                        for (int hq = 0; hq < 2; hq++)
                            mma16816(d[mt][np * 2 + hq], a_hf[mt], &b_lf[hq * 2]);
                }
            }
        }

        if constexpr (MODE != 0) {
            if (have2) packstore(c + 2, stg_n, q0, q1);   // LDG latency hidden by MMAs
        }

        if (++stg_c >= 3) stg_c -= 3;
    }

    // epilogue
    #pragma unroll
    for (int mt = 0; mt < 2; mt++)
        #pragma unroll
        for (int nt = 0; nt < 8; nt++) {
            int r0 = bm + wm * 32 + mt * 16 + (lane >> 2);
            int c0 = bn + wn * 64 + nt * 8 + (lane & 3) * 2;
            float* dd = d[mt][nt];
            epi_store<EPI>(r0,     c0,     dd[0], M, N, bias, C, ldc, sC, z);
            epi_store<EPI>(r0,     c0 + 1, dd[1], M, N, bias, C, ldc, sC, z);
            epi_store<EPI>(r0 + 8, c0,     dd[2], M, N, bias, C, ldc, sC, z);
            epi_store<EPI>(r0 + 8, c0 + 1, dd[3], M, N, bias, C, ldc, sC, z);
        }
}

// ---- shared transpose+split body: src [K,N] fp32 -> dh/dl [N,K] half ----
template<int PERM>
__device__ __forceinline__ void tsplit_body(const float* __restrict__ src,
                                            hf* __restrict__ dh, hf* __restrict__ dl,
                                            int K, int N) {
    __shared__ float t[32][33];
    int n0 = blockIdx.x * 32, k0 = blockIdx.y * 32;
    int tx = threadIdx.x, ty = threadIdx.y;  // 32 x 8
    #pragma unroll
    for (int i = 0; i < 4; i++) {
        int k = k0 + ty + i * 8, n = n0 + tx;
        if (k < K && n < N) t[ty + i * 8][tx] = src[(size_t)k * N + n];
    }
    __syncthreads();
    #pragma unroll
    for (int i = 0; i < 4; i++) {
        int n = n0 + ty + i * 8, k = k0 + tx;
        if (n < N && k < K) {
            float v = t[tx][ty + i * 8];
            int nd = n;
            if (PERM) {
                int h = n / 768, r = n - h * 768;
                int f = r / 3, c = r - f * 3;
                nd = c * 2048 + h * 256 + f;
            }
            split_store(dh, dl, (size_t)nd * K + k, v);
        }
    }
}

// launch 0: qkv weights (z<LL) + bias permute (z==LL)
__global__ void tsplit_qkv(const float* __restrict__ src, const float* __restrict__ qb) {
    int zl = blockIdx.z;
    if (zl == LL) {
        int bid = blockIdx.y * gridDim.x + blockIdx.x;
        int idx = bid * 256 + threadIdx.y * 32 + threadIdx.x;
        if (idx < LL * HD3) {
            int l = idx / HD3, j = idx - l * HD3;
            int h = j / 768, r = j - h * 768;
            int f = r / 3, c = r - f * 3;
            g_qkvb[(size_t)l * HD3 + c * 2048 + h * 256 + f] = qb[idx];
        }
        return;
    }
    tsplit_body<1>(src + (size_t)zl * DD * HD3,
                   g_qkvTh + (size_t)zl * HD3 * DD, g_qkvTl + (size_t)zl * HD3 * DD,
                   DD, HD3);
}

// launch 1: proj (z<LL), w1 (z<2LL), w2 (z<3LL), score-pad fill (z==3LL)
__global__ void tsplit_rest(const float* __restrict__ pw,
                            const float* __restrict__ w1,
                            const float* __restrict__ w2) {
    int zl = blockIdx.z;
    if (zl < LL) {
        tsplit_body<0>(pw + (size_t)zl * OD * DD,
                       g_projTh + (size_t)zl * DD * OD, g_projTl + (size_t)zl * DD * OD,
                       OD, DD);
    } else if (zl < 2 * LL) {
        int l = zl - LL;
        tsplit_body<0>(w1 + (size_t)l * DD * ED,
                       g_w1Th + (size_t)l * ED * DD, g_w1Tl + (size_t)l * ED * DD,
                       DD, ED);
    } else if (zl < 3 * LL) {
        int l = zl - 2 * LL;
        tsplit_body<0>(w2 + (size_t)l * ED * DD,
                       g_w2Th + (size_t)l * DD * ED, g_w2Tl + (size_t)l * DD * ED,
                       ED, DD);
    } else {
        long nb = (long)gridDim.x * gridDim.y;
        long bid = (long)blockIdx.y * gridDim.x + blockIdx.x;
        long i0 = bid * 256 + threadIdx.y * 32 + threadIdx.x;
        const long PER = TS2 - TT;                              // 30
        const long TOT = (long)BHn * TT * PER;
        for (long i = i0; i < TOT; i += nb * 256) {
            long row = i / PER, j = i - row * PER;
            g_s[(size_t)row * TS2 + TT + j] = -1e30f;
        }
    }
}

// ---- LN row stats (+ optional embed materialization into g_h for layer 0) ----
__global__ void ln_stats(const float* __restrict__ x, const float* __restrict__ cls,
                         const float* __restrict__ dict, int first) {
    int row = blockIdx.x * 8 + (threadIdx.x >> 5);   // 8 warps, one row each
    int lane = threadIdx.x & 31;
    float v[8];
    if (first) {
        int b = row / TT, t = row - b * TT;
        const float* src;
        if (t < NTOK)        src = x + ((size_t)b * NTOK + t) * DD;
        else if (t == NTOK)  src = cls;
        else                 src = dict;
        float4 a0 = *(const float4*)(src + lane * 8);
        float4 a1 = *(const float4*)(src + lane * 8 + 4);
        v[0]=a0.x; v[1]=a0.y; v[2]=a0.z; v[3]=a0.w;
        v[4]=a1.x; v[5]=a1.y; v[6]=a1.z; v[7]=a1.w;
        float4* dst = (float4*)(g_h + (size_t)row * DD + lane * 8);
        dst[0] = a0; dst[1] = a1;
    } else {
        float4 a0 = *(const float4*)(g_h + (size_t)row * DD + lane * 8);
        float4 a1 = *(const float4*)(g_h + (size_t)row * DD + lane * 8 + 4);
        v[0]=a0.x; v[1]=a0.y; v[2]=a0.z; v[3]=a0.w;
        v[4]=a1.x; v[5]=a1.y; v[6]=a1.z; v[7]=a1.w;
    }
    float s = 0.f, s2 = 0.f;
    #pragma unroll
    for (int i = 0; i < 8; i++) { s += v[i]; s2 += v[i] * v[i]; }
    #pragma unroll
    for (int o = 16; o > 0; o >>= 1) {
        s  += __shfl_xor_sync(0xFFFFFFFFu, s,  o);
        s2 += __shfl_xor_sync(0xFFFFFFFFu, s2, o);
    }
    if (lane == 0) {
        float mean = s * (1.0f / DD);
        float var  = s2 * (1.0f / DD) - mean * mean;
        g_lnm[row] = mean;
        g_lnr[row] = rsqrtf(var + 1e-5f);
    }
}

// ---- transpose V: [bh][t][f] -> vT [bh][f][t(pad KATT)] (hi only) ----
__global__ void transpose_v() {
    __shared__ hf th[32][33];
    int bh = blockIdx.z;
    int f0 = blockIdx.x * 32, t0 = blockIdx.y * 32;
    int tx = threadIdx.x, ty = threadIdx.y;   // 32 x 8
    const hf* vh = g_vh + (size_t)bh * TT * DD;
    #pragma unroll
    for (int i = 0; i < 4; i++) {
        int t = t0 + ty + i * 8;
        hf a = __float2half(0.f);
        if (t < TT) a = vh[(size_t)t * DD + f0 + tx];
        th[ty + i * 8][tx] = a;
    }
    __syncthreads();
    hf* dH = g_vTh + (size_t)bh * DD * KATT;
    #pragma unroll
    for (int i = 0; i < 4; i++) {
        int f = f0 + ty + i * 8, t = t0 + tx;
        dH[(size_t)f * KATT + t] = th[tx][ty + i * 8];
    }
}

// ---- attention row reduce: max + 1/sum(exp) over each score row ----
__global__ void attn_reduce() {
    int row = blockIdx.x;                       // bh*TT + t
    const float* p = g_s + (size_t)row * TS2;
    int tid = threadIdx.x;
    float v[5];
    float mx = -1e30f;
    #pragma unroll
    for (int it = 0; it < 5; it++) {
        int j = tid + it * 256;
        if (j < TT) { v[it] = p[j]; mx = fmaxf(mx, v[it]); }
    }
    __shared__ float red_m[8], red_s[8];
    #pragma unroll
    for (int o = 16; o > 0; o >>= 1) mx = fmaxf(mx, __shfl_xor_sync(0xFFFFFFFFu, mx, o));
    if ((tid & 31) == 0) red_m[tid >> 5] = mx;
    __syncthreads();
    if (tid < 32) {
        float a = (tid < 8) ? red_m[tid] : -1e30f;
        #pragma unroll
        for (int o = 4; o > 0; o >>= 1) a = fmaxf(a, __shfl_xor_sync(0xFFFFFFFFu, a, o));
        if (tid == 0) red_m[0] = a;
    }
    __syncthreads();
    mx = red_m[0];
    float sum = 0.f;
    #pragma unroll
    for (int it = 0; it < 5; it++) {
        int j = tid + it * 256;
        if (j < TT) sum += __expf(v[it] - mx);
    }
    #pragma unroll
    for (int o = 16; o > 0; o >>= 1) sum += __shfl_xor_sync(0xFFFFFFFFu, sum, o);
    if ((tid & 31) == 0) red_s[tid >> 5] = sum;
    __syncthreads();
    if (tid < 32) {
        float a = (tid < 8) ? red_s[tid] : 0.f;
        #pragma unroll
        for (int o = 4; o > 0; o >>= 1) a += __shfl_xor_sync(0xFFFFFFFFu, a, o);
        if (tid == 0) { g_rmax[row] = mx; g_rinv[row] = 1.0f / a; }
    }
}

// ---- final output split ----
__global__ void out_kernel(float* __restrict__ out) {
    long i = (long)blockIdx.x * blockDim.x + threadIdx.x;
    if (i >= (long)MM * DD) return;
    int d = (int)(i % DD);
    long r = i / DD;
    int t = (int)(r % TT);
    int b = (int)(r / TT);
    float v = g_h[i];
    if (t < NTOK)        out[((long)b * NTOK + t) * DD + d] = v;
    else if (t == NTOK)  out[(long)BB * NTOK * DD + (long)b * DD + d] = v;
    else                 out[(long)BB * NTOK * DD + (long)BB * DD + (long)b * DD + d] = v;
}

extern "C" void kernel_launch(void* const* d_in, const int* in_sizes, int n_in,
                              void* d_out, int out_size) {
    const float* x      = (const float*)d_in[0];
    const float* cls    = (const float*)d_in[1];
    const float* dict   = (const float*)d_in[2];
    const float* ln1_g  = (const float*)d_in[3];
    const float* ln1_b  = (const float*)d_in[4];
    const float* qkv_w  = (const float*)d_in[5];
    const float* qkv_b  = (const float*)d_in[6];
    const float* proj_w = (const float*)d_in[7];
    const float* proj_b = (const float*)d_in[8];
    const float* ln2_g  = (const float*)d_in[9];
    const float* ln2_b  = (const float*)d_in[10];
    const float* mlp_w1 = (const float*)d_in[11];
    const float* mlp_b1 = (const float*)d_in[12];
    const float* mlp_w2 = (const float*)d_in[13];
    const float* mlp_b2 = (const float*)d_in[14];

    cudaFuncSetAttribute(mma_gemm<0,0,2>, cudaFuncAttributeMaxDynamicSharedMemorySize, SMEM_DYN);
    cudaFuncSetAttribute(mma_gemm<1,2,3>, cudaFuncAttributeMaxDynamicSharedMemorySize, SMEM_DYN);
    cudaFuncSetAttribute(mma_gemm<2,1,2>, cudaFuncAttributeMaxDynamicSharedMemorySize, SMEM_DYN);
    cudaFuncSetAttribute(mma_gemm<3,0,3>, cudaFuncAttributeMaxDynamicSharedMemorySize, SMEM_DYN);
    cudaFuncSetAttribute(mma_gemm<4,2,3>, cudaFuncAttributeMaxDynamicSharedMemorySize, SMEM_DYN);
    cudaFuncSetAttribute(mma_gemm<5,0,3>, cudaFuncAttributeMaxDynamicSharedMemorySize, SMEM_DYN);

    float *gh, *gs, *qkvb;
    hf *qh, *ql, *kh, *vTh, *oh, *ol, *mh, *ml;
    hf *qkvTh, *qkvTl, *projTh, *projTl, *w1Th, *w1Tl, *w2Th, *w2Tl;
    cudaGetSymbolAddress((void**)&gh,  g_h);
    cudaGetSymbolAddress((void**)&gs,  g_s);
    cudaGetSymbolAddress((void**)&qkvb, g_qkvb);
    cudaGetSymbolAddress((void**)&qh,  g_qh);
    cudaGetSymbolAddress((void**)&ql,  g_ql);
    cudaGetSymbolAddress((void**)&kh,  g_kh);
    cudaGetSymbolAddress((void**)&vTh, g_vTh);
    cudaGetSymbolAddress((void**)&oh,  g_oh);
    cudaGetSymbolAddress((void**)&ol,  g_ol);
    cudaGetSymbolAddress((void**)&mh,  g_mh);
    cudaGetSymbolAddress((void**)&ml,  g_ml);
    cudaGetSymbolAddress((void**)&qkvTh, g_qkvTh);
    cudaGetSymbolAddress((void**)&qkvTl, g_qkvTl);
    cudaGetSymbolAddress((void**)&projTh, g_projTh);
    cudaGetSymbolAddress((void**)&projTl, g_projTl);
    cudaGetSymbolAddress((void**)&w1Th, g_w1Th);
    cudaGetSymbolAddress((void**)&w1Tl, g_w1Tl);
    cudaGetSymbolAddress((void**)&w2Th, g_w2Th);
    cudaGetSymbolAddress((void**)&w2Tl, g_w2Tl);

    dim3 tb(32, 8);
    // launch 0, 1: weight prep
    tsplit_qkv <<<dim3(HD3/32, DD/32, LL+1), tb>>>(qkv_w, qkv_b);
    tsplit_rest<<<dim3(32, 64, 3*LL+1), tb>>>(proj_w, mlp_w1, mlp_w2);

    for (int l = 0; l < LL; l++) {
        // launch 2 (l=0): LN1 stats (+ embed for layer 0)
        ln_stats<<<MM/8, 256>>>(x, cls, dict, l == 0 ? 1 : 0);

        // launch 3 (l=0): QKV GEMM with fused LN A-load  <- ncu capture target
        mma_gemm<1,2,3><<<dim3(HD3/128, (MM+127)/128, 1), 256, SMEM_DYN>>>(
            nullptr, nullptr, 0, 0,
            qkvTh + (size_t)l*HD3*DD, qkvTl + (size_t)l*HD3*DD, DD, 0,
            qkvb + (size_t)l*HD3, ln1_g + (size_t)l*DD, ln1_b + (size_t)l*DD,
            nullptr, 0, 0, MM, HD3, DD);

        transpose_v<<<dim3(DD/32, KATT/32, BHn), tb>>>();

        // scores = Q K^T (2-pass: K hi only), batched over 64 heads
        mma_gemm<0,0,2><<<dim3((TT+127)/128, (TT+127)/128, BHn), 256, SMEM_DYN>>>(
            qh, ql, DD, (long)TT*DD,
            kh, nullptr, DD, (long)TT*DD,
            nullptr, nullptr, nullptr, gs, TS2, (long)TT*TS2, TT, TT, DD);

        attn_reduce<<<BHn*TT, 256>>>();

        // O = exp(S-max) V * (1/sum): fused exp A-load, V hi only (2-pass)
        mma_gemm<2,1,2><<<dim3(DD/128, (TT+127)/128, BHn), 256, SMEM_DYN>>>(
            nullptr, nullptr, 0, 0,
            vTh, nullptr, KATT, (long)DD*KATT,
            nullptr, nullptr, nullptr, nullptr, 0, 0, TT, DD, KATT);

        // proj: [8208,2048] x [256,2048]^T -> fp32 h
        mma_gemm<3,0,3><<<dim3(DD/128, (MM+127)/128, 1), 256, SMEM_DYN>>>(
            oh, ol, OD, 0,
            projTh + (size_t)l*DD*OD, projTl + (size_t)l*DD*OD, OD, 0,
            proj_b + (size_t)l*DD, nullptr, nullptr, gh, DD, 0, MM, DD, OD);

        // LN2 stats
        ln_stats<<<MM/8, 256>>>(x, cls, dict, 0);

        // mlp1 with fused LN A-load, + gelu -> m split
        mma_gemm<4,2,3><<<dim3(ED/128, (MM+127)/128, 1), 256, SMEM_DYN>>>(
            nullptr, nullptr, 0, 0,
            w1Th + (size_t)l*ED*DD, w1Tl + (size_t)l*ED*DD, DD, 0,
            mlp_b1 + (size_t)l*ED, ln2_g + (size_t)l*DD, ln2_b + (size_t)l*DD,
            nullptr, 0, 0, MM, ED, DD);

        // mlp2 + gelu -> fp32 h
        mma_gemm<5,0,3><<<dim3(DD/128, (MM+127)/128, 1), 256, SMEM_DYN>>>(
            mh, ml, ED, 0,
            w2Th + (size_t)l*DD*ED, w2Tl + (size_t)l*DD*ED, ED, 0,
            mlp_b2 + (size_t)l*DD, nullptr, nullptr, gh, DD, 0, MM, DD, ED);
    }

    long total = (long)MM * DD;
    out_kernel<<<(unsigned)((total + 255) / 256), 256>>>((float*)d_out);
}

// round 10
// speedup vs baseline: 1.4431x; 1.1319x over previous
#include <cuda_runtime.h>
#include <cuda_fp16.h>
#include <math.h>
#include <stdint.h>

// ---- problem constants ----
#define BB 8
#define NTOK 1024
#define TT 1026            // N + cls + dict
#define DD 256
#define HH 8
#define LL 6
#define HD3 6144           // H*D*3
#define OD 2048            // H*D
#define ED 1024            // EXP*D
#define MM (BB*TT)         // 8208 rows
#define BHn (BB*HH)        // 64
#define TS2 1056           // padded fp32 score row stride (= padded attention K)
#define KATT 1056          // padded key count for WV GEMM

typedef __half hf;

// ---- scratch (device globals; no allocs allowed) ----
__device__ __align__(16) float g_h [(size_t)MM*DD];
__device__ __align__(16) float g_s [(size_t)BHn*TT*TS2];
__device__ __align__(16) float g_rmax[(size_t)BHn*TT];
__device__ __align__(16) float g_rinv[(size_t)BHn*TT];
__device__ __align__(16) float g_lnm[(size_t)MM];
__device__ __align__(16) float g_lnr[(size_t)MM];
__device__ __align__(16) float g_qkvb[(size_t)LL*HD3];
__device__ __align__(16) hf g_qh[(size_t)BHn*TT*DD];
__device__ __align__(16) hf g_kh[(size_t)BHn*TT*DD];
__device__ __align__(16) hf g_vh[(size_t)BHn*TT*DD];
__device__ __align__(16) hf g_vTh[(size_t)BHn*DD*KATT];
__device__ __align__(16) hf g_oh[(size_t)MM*OD];
__device__ __align__(16) hf g_ol[(size_t)MM*OD];
__device__ __align__(16) hf g_mh[(size_t)MM*ED];
__device__ __align__(16) hf g_ml[(size_t)MM*ED];
// transposed + split weights [N,K] per layer
__device__ __align__(16) hf g_qkvTh[(size_t)LL*HD3*DD];
__device__ __align__(16) hf g_qkvTl[(size_t)LL*HD3*DD];
__device__ __align__(16) hf g_projTh[(size_t)LL*DD*OD];
__device__ __align__(16) hf g_projTl[(size_t)LL*DD*OD];
__device__ __align__(16) hf g_w1Th[(size_t)LL*ED*DD];
__device__ __align__(16) hf g_w1Tl[(size_t)LL*ED*DD];
__device__ __align__(16) hf g_w2Th[(size_t)LL*DD*ED];
__device__ __align__(16) hf g_w2Tl[(size_t)LL*DD*ED];

__device__ __forceinline__ float gelu_exact(float x) {
    return 0.5f * x * (1.0f + erff(x * 0.70710678118654752440f));
}

__device__ __forceinline__ uint32_t smem_u32(const void* p) {
    uint32_t a;
    asm("{ .reg .u64 t; cvta.to.shared.u64 t, %1; cvt.u32.u64 %0, t; }" : "=r"(a) : "l"(p));
    return a;
}

__device__ __forceinline__ void ldsm4(uint32_t* r, uint32_t addr) {
    asm volatile("ldmatrix.sync.aligned.m8n8.x4.shared.b16 {%0,%1,%2,%3}, [%4];"
                 : "=r"(r[0]), "=r"(r[1]), "=r"(r[2]), "=r"(r[3]) : "r"(addr));
}

__device__ __forceinline__ void mma16816(float* d, const uint32_t* a, const uint32_t* b) {
    asm volatile(
        "mma.sync.aligned.m16n8k16.row.col.f32.f16.f16.f32 "
        "{%0,%1,%2,%3}, {%4,%5,%6,%7}, {%8,%9}, {%0,%1,%2,%3};"
        : "+f"(d[0]), "+f"(d[1]), "+f"(d[2]), "+f"(d[3])
        : "r"(a[0]), "r"(a[1]), "r"(a[2]), "r"(a[3]), "r"(b[0]), "r"(b[1]));
}

__device__ __forceinline__ void cpa16(uint32_t dst, const void* src, bool v) {
    int sz = v ? 16 : 0;
    asm volatile("cp.async.cg.shared.global [%0], [%1], 16, %2;"
                 :: "r"(dst), "l"(src), "r"(sz) : "memory");
}
__device__ __forceinline__ void cpa_commit() {
    asm volatile("cp.async.commit_group;" ::: "memory");
}

__device__ __forceinline__ void split_store(hf* dh, hf* dl, size_t off, float v) {
    hf h = __float2half_rn(v);
    dh[off] = h;
    dl[off] = __float2half_rn(v - __half2float(h));
}

// pack 8 fp32 into hi/lo half uint4s
__device__ __forceinline__ void pack8(const float* p, uint4& h, uint4& l) {
    __half2 hh[4], ll[4];
    #pragma unroll
    for (int i = 0; i < 4; i++) {
        __half a = __float2half_rn(p[2*i]);
        __half b = __float2half_rn(p[2*i+1]);
        hh[i] = __halves2half2(a, b);
        ll[i] = __halves2half2(__float2half_rn(p[2*i]   - __half2float(a)),
                               __float2half_rn(p[2*i+1] - __half2float(b)));
    }
    h = *(uint4*)hh;
    l = *(uint4*)ll;
}
// hi only
__device__ __forceinline__ void pack8h(const float* p, uint4& h) {
    __half2 hh[4];
    #pragma unroll
    for (int i = 0; i < 4; i++)
        hh[i] = __halves2half2(__float2half_rn(p[2*i]), __float2half_rn(p[2*i+1]));
    h = *(uint4*)hh;
}

// per-element epilogue
template<int EPI>
__device__ __forceinline__ void epi_store(int gm, int gn, float v, int M, int N,
                                          const float* __restrict__ bias,
                                          float* __restrict__ C, int ldc, long sC, int z) {
    if (gm >= M || gn >= N) return;
    if constexpr (EPI == 0) {                 // scores -> fp32 (ldc=TS2)
        C[(size_t)z * sC + (size_t)gm * ldc + gn] = v;
    } else if constexpr (EPI == 1) {          // qkv scatter (permuted cols: c*2048+h*256+f)
        v += bias[gn];
        int c = gn >> 11;
        int rem = gn & 2047;
        int h = rem >> 8, f = rem & 255;
        int b = gm / TT, t = gm - b * TT;
        int bh = b * HH + h;
        size_t o = ((size_t)bh * TT + t) * DD + f;
        if (c == 2) {
            g_vh[o] = __float2half_rn(v);     // hi only
        } else {
            v *= 0.0625f;                     // 1/sqrt(256)
            if (c == 0) g_qh[o] = __float2half_rn(v);  // hi only (1-pass scores)
            else        g_kh[o] = __float2half_rn(v);
        }
    } else if constexpr (EPI == 2) {          // WV -> normalize by 1/rowsum, split to o
        v *= g_rinv[(size_t)z * TT + gm];
        int b = z >> 3, head = z & 7;
        split_store(g_oh, g_ol, ((size_t)b * TT + gm) * OD + (size_t)head * DD + gn, v);
    } else if constexpr (EPI == 3) {          // proj -> fp32 + bias
        C[(size_t)gm * ldc + gn] = v + bias[gn];
    } else if constexpr (EPI == 4) {          // mlp1: bias+gelu -> m split
        split_store(g_mh, g_ml, (size_t)gm * ED + gn, gelu_exact(v + bias[gn]));
    } else {                                  // mlp2: bias+gelu -> fp32
        C[(size_t)gm * ldc + gn] = gelu_exact(v + bias[gn]);
    }
}

// ============ HMMA fp16 split GEMM: 128x128 block, BK=32, cp.async 3-stage ============
// Tile layout: 64B rows (32 halves), 16B-chunk XOR swizzle:
//   chunk c of row r lives at r*64 + ((c ^ ((r>>1)&3)) * 16)
// MODE 0: A (hi[/lo]) via cp.async.
// MODE 1: A = exp(score - rowmax) from g_s on the fly (stride TS2, batch z).
// MODE 2: A = LayerNorm(g_h row) via g_lnm/g_lnr + lng/lnb, split on the fly.
// NPASS 1: Ah*Bh.  NPASS 2: +Al*Bh.  NPASS 3: +Ah*Bl.
#define AH_OFF 0
#define AL_OFF 8192
#define BH_OFF 16384
#define BL_OFF 24576
#define STG_BYTES 32768
#define SMEM_DYN (3*STG_BYTES)

template<int EPI, int MODE, int NPASS>
__global__ void __launch_bounds__(256, 2) mma_gemm(
    const hf* __restrict__ Ah, const hf* __restrict__ Al, int lda, long sA,
    const hf* __restrict__ Bh, const hf* __restrict__ Bl, int ldb, long sB,
    const float* __restrict__ bias,
    const float* __restrict__ lng, const float* __restrict__ lnb,
    float* __restrict__ C, int ldc, long sC,
    int M, int N, int K)
{
    extern __shared__ char smdyn[];
    uint32_t sb = smem_u32(smdyn);

    int tid = threadIdx.x, lane = tid & 31, wid = tid >> 5;
    int wm = wid >> 1, wn = wid & 1;
    int z = blockIdx.z;
    Bh += (size_t)z * sB;
    if constexpr (NPASS == 3) Bl += (size_t)z * sB;
    int bm = blockIdx.y * 128, bn = blockIdx.x * 128;

    int row0 = tid >> 2, row1 = row0 + 64;
    int cv  = tid & 3;                        // 16B chunk index
    int cvb = cv * 16;                        // byte offset in source row
    int cofs = cv * 8;                        // element offset (8 elems)
    bool aval0 = (bm + row0) < M, aval1 = (bm + row1) < M;
    bool bval0 = (bn + row0) < N, bval1 = (bn + row1) < N;
    const char* pBh0 = (const char*)(Bh + (size_t)(bval0 ? bn + row0 : 0) * ldb) + cvb;
    const char* pBh1 = (const char*)(Bh + (size_t)(bval1 ? bn + row1 : 0) * ldb) + cvb;
    const char* pBl0 = nullptr; const char* pBl1 = nullptr;
    if constexpr (NPASS == 3) {
        pBl0 = (const char*)(Bl + (size_t)(bval0 ? bn + row0 : 0) * ldb) + cvb;
        pBl1 = (const char*)(Bl + (size_t)(bval1 ? bn + row1 : 0) * ldb) + cvb;
    }
    // swizzled smem offsets for the two rows this thread fills
    uint32_t st0 = (uint32_t)(row0 * 64 + ((cv ^ ((row0 >> 1) & 3)) * 16));
    uint32_t st1 = (uint32_t)(row1 * 64 + ((cv ^ ((row1 >> 1) & 3)) * 16));

    // A sources
    const char *pAh0 = nullptr, *pAh1 = nullptr, *pAl0 = nullptr, *pAl1 = nullptr;
    const float *pS0 = nullptr, *pS1 = nullptr;
    float rm0 = 0.f, rm1 = 0.f, rr0 = 0.f, rr1 = 0.f;
    if constexpr (MODE == 1) {
        const float* Sz = g_s + (size_t)z * TT * TS2;
        pS0 = Sz + (size_t)(aval0 ? bm + row0 : 0) * TS2 + cofs;
        pS1 = Sz + (size_t)(aval1 ? bm + row1 : 0) * TS2 + cofs;
        if (aval0) rm0 = g_rmax[(size_t)z * TT + bm + row0];
        if (aval1) rm1 = g_rmax[(size_t)z * TT + bm + row1];
    } else if constexpr (MODE == 2) {
        pS0 = g_h + (size_t)(aval0 ? bm + row0 : 0) * DD + cofs;
        pS1 = g_h + (size_t)(aval1 ? bm + row1 : 0) * DD + cofs;
        if (aval0) { rm0 = g_lnm[bm + row0]; rr0 = g_lnr[bm + row0]; }
        if (aval1) { rm1 = g_lnm[bm + row1]; rr1 = g_lnr[bm + row1]; }
    } else {
        Ah += (size_t)z * sA;
        pAh0 = (const char*)(Ah + (size_t)(aval0 ? bm + row0 : 0) * lda) + cvb;
        pAh1 = (const char*)(Ah + (size_t)(aval1 ? bm + row1 : 0) * lda) + cvb;
        if constexpr (NPASS >= 2) {
            Al += (size_t)z * sA;
            pAl0 = (const char*)(Al + (size_t)(aval0 ? bm + row0 : 0) * lda) + cvb;
            pAl1 = (const char*)(Al + (size_t)(aval1 ? bm + row1 : 0) * lda) + cvb;
        }
    }

    float d[2][8][4];
    #pragma unroll
    for (int i = 0; i < 2; i++)
        #pragma unroll
        for (int j = 0; j < 8; j++)
            #pragma unroll
            for (int q = 0; q < 4; q++) d[i][j][q] = 0.f;

    // ldmatrix lane addressing (per-lane row + k-chunk)
    int group = lane >> 3, lrow = lane & 7;
    int a_row = wm * 32 + (group & 1) * 8 + lrow;
    int koA   = (group >> 1);                 // k chunk offset 0/1 (8 halves each)
    int b_row = wn * 64 + (group >> 1) * 8 + lrow;
    int koB   = (group & 1);
    int aS = (a_row >> 1) & 3;                // swizzle key; invariant under +16 rows
    int bS = (b_row >> 1) & 3;
    uint32_t aB0 = (uint32_t)(a_row * 64),       aB1 = (uint32_t)((a_row + 16) * 64);
    uint32_t bB[4];
    #pragma unroll
    for (int np = 0; np < 4; np++) bB[np] = (uint32_t)((b_row + np * 16) * 64);

    // issue cp.async for chunk c into stage stg (B always; A only MODE 0)
    auto issue = [&](int c, int stg) {
        uint32_t s0 = sb + (uint32_t)stg * STG_BYTES;
        size_t adv = (size_t)c * 64;          // 32 halves = 64 bytes
        if constexpr (MODE == 0) {
            cpa16(s0 + AH_OFF + st0, pAh0 + adv, aval0);
            cpa16(s0 + AH_OFF + st1, pAh1 + adv, aval1);
            if constexpr (NPASS >= 2) {
                cpa16(s0 + AL_OFF + st0, pAl0 + adv, aval0);
                cpa16(s0 + AL_OFF + st1, pAl1 + adv, aval1);
            }
        }
        cpa16(s0 + BH_OFF + st0, pBh0 + adv, bval0);
        cpa16(s0 + BH_OFF + st1, pBh1 + adv, bval1);
        if constexpr (NPASS == 3) {
            cpa16(s0 + BL_OFF + st0, pBl0 + adv, bval0);
            cpa16(s0 + BL_OFF + st1, pBl1 + adv, bval1);
        }
        cpa_commit();
    };

    float q0[8], q1[8];
    auto loadraw = [&](int c, float* r0, float* r1) {
        int kc = c * 32;
        float4 x0 = *(const float4*)(pS0 + kc);
        float4 x1 = *(const float4*)(pS0 + kc + 4);
        float4 y0 = *(const float4*)(pS1 + kc);
        float4 y1 = *(const float4*)(pS1 + kc + 4);
        r0[0]=x0.x; r0[1]=x0.y; r0[2]=x0.z; r0[3]=x0.w;
        r0[4]=x1.x; r0[5]=x1.y; r0[6]=x1.z; r0[7]=x1.w;
        r1[0]=y0.x; r1[1]=y0.y; r1[2]=y0.z; r1[3]=y0.w;
        r1[4]=y1.x; r1[5]=y1.y; r1[6]=y1.z; r1[7]=y1.w;
    };
    auto packstore = [&](int c, int stg, const float* r0, const float* r1) {
        float p[8];
        char* as = smdyn + (size_t)stg * STG_BYTES;
        if constexpr (MODE == 1) {
            #pragma unroll
            for (int i = 0; i < 8; i++) p[i] = aval0 ? __expf(r0[i] - rm0) : 0.f;
            if constexpr (NPASS >= 2) {
                uint4 h0, l0;
                pack8(p, h0, l0);
                *(uint4*)(as + AH_OFF + st0) = h0;
                *(uint4*)(as + AL_OFF + st0) = l0;
            } else {
                uint4 h0; pack8h(p, h0);
                *(uint4*)(as + AH_OFF + st0) = h0;
            }
            #pragma unroll
            for (int i = 0; i < 8; i++) p[i] = aval1 ? __expf(r1[i] - rm1) : 0.f;
            if constexpr (NPASS >= 2) {
                uint4 h1, l1;
                pack8(p, h1, l1);
                *(uint4*)(as + AH_OFF + st1) = h1;
                *(uint4*)(as + AL_OFF + st1) = l1;
            } else {
                uint4 h1; pack8h(p, h1);
                *(uint4*)(as + AH_OFF + st1) = h1;
            }
        } else {  // MODE == 2 (LN; always split)
            int kc = c * 32;
            const float* gk = lng + kc + cofs;
            const float* bk = lnb + kc + cofs;
            uint4 h0, l0, h1, l1;
            #pragma unroll
            for (int i = 0; i < 8; i++)
                p[i] = aval0 ? (r0[i] - rm0) * rr0 * gk[i] + bk[i] : 0.f;
            pack8(p, h0, l0);
            #pragma unroll
            for (int i = 0; i < 8; i++)
                p[i] = aval1 ? (r1[i] - rm1) * rr1 * gk[i] + bk[i] : 0.f;
            pack8(p, h1, l1);
            *(uint4*)(as + AH_OFF + st0) = h0;
            *(uint4*)(as + AL_OFF + st0) = l0;
            *(uint4*)(as + AH_OFF + st1) = h1;
            *(uint4*)(as + AL_OFF + st1) = l1;
        }
    };

    int nit = K >> 5;                         // >= 8 for all our shapes
    if constexpr (MODE != 0) {
        loadraw(0, q0, q1); packstore(0, 0, q0, q1);
        loadraw(1, q0, q1); packstore(1, 1, q0, q1);
    }
    issue(0, 0);
    issue(1, 1);

    int stg_c = 0;                            // c % 3
    for (int c = 0; c < nit; c++) {
        if (c + 1 < nit) {
            asm volatile("cp.async.wait_group 1;" ::: "memory");
        } else {
            asm volatile("cp.async.wait_group 0;" ::: "memory");
        }
        __syncthreads();                      // publish stage c; free stage c-1

        int stg_n = stg_c + 2; if (stg_n >= 3) stg_n -= 3;   // (c+2) % 3
        bool have2 = (c + 2 < nit);
        if (have2) {
            issue(c + 2, stg_n);
            if constexpr (MODE != 0) loadraw(c + 2, q0, q1);
        }

        uint32_t cb = sb + (uint32_t)stg_c * STG_BYTES;
        #pragma unroll
        for (int ks = 0; ks < 32; ks += 16) {
            int kc = ks >> 3;                 // 0 or 2
            uint32_t a_hf[2][4], a_lf[2][4];
            {
                uint32_t sw = (uint32_t)(((kc + koA) ^ aS) << 4);
                uint32_t o0 = cb + aB0 + sw, o1 = cb + aB1 + sw;
                ldsm4(a_hf[0], o0 + AH_OFF);
                ldsm4(a_hf[1], o1 + AH_OFF);
                if constexpr (NPASS >= 2) {
                    ldsm4(a_lf[0], o0 + AL_OFF);
                    ldsm4(a_lf[1], o1 + AL_OFF);
                }
            }
            uint32_t swb = (uint32_t)(((kc + koB) ^ bS) << 4);
            #pragma unroll
            for (int np = 0; np < 4; np++) {
                uint32_t b_hf[4], b_lf[4];
                uint32_t o = cb + bB[np] + swb;
                ldsm4(b_hf, o + BH_OFF);
                if constexpr (NPASS == 3) ldsm4(b_lf, o + BL_OFF);
                #pragma unroll
                for (int mt = 0; mt < 2; mt++)
                    #pragma unroll
                    for (int hq = 0; hq < 2; hq++)
                        mma16816(d[mt][np * 2 + hq], a_hf[mt], &b_hf[hq * 2]);
                if constexpr (NPASS >= 2) {
                    #pragma unroll
                    for (int mt = 0; mt < 2; mt++)
                        #pragma unroll
                        for (int hq = 0; hq < 2; hq++)
                            mma16816(d[mt][np * 2 + hq], a_lf[mt], &b_hf[hq * 2]);
                }
                if constexpr (NPASS == 3) {
                    #pragma unroll
                    for (int mt = 0; mt < 2; mt++)
                        #pragma unroll
                        for (int hq = 0; hq < 2; hq++)
                            mma16816(d[mt][np * 2 + hq], a_hf[mt], &b_lf[hq * 2]);
                }
            }
        }

        if constexpr (MODE != 0) {
            if (have2) packstore(c + 2, stg_n, q0, q1);   // LDG latency hidden by MMAs
        }

        if (++stg_c >= 3) stg_c -= 3;
    }

    // epilogue
    #pragma unroll
    for (int mt = 0; mt < 2; mt++)
        #pragma unroll
        for (int nt = 0; nt < 8; nt++) {
            int r0 = bm + wm * 32 + mt * 16 + (lane >> 2);
            int c0 = bn + wn * 64 + nt * 8 + (lane & 3) * 2;
            float* dd = d[mt][nt];
            epi_store<EPI>(r0,     c0,     dd[0], M, N, bias, C, ldc, sC, z);
            epi_store<EPI>(r0,     c0 + 1, dd[1], M, N, bias, C, ldc, sC, z);
            epi_store<EPI>(r0 + 8, c0,     dd[2], M, N, bias, C, ldc, sC, z);
            epi_store<EPI>(r0 + 8, c0 + 1, dd[3], M, N, bias, C, ldc, sC, z);
        }
}

// ---- shared transpose+split body: src [K,N] fp32 -> dh/dl [N,K] half ----
template<int PERM>
__device__ __forceinline__ void tsplit_body(const float* __restrict__ src,
                                            hf* __restrict__ dh, hf* __restrict__ dl,
                                            int K, int N) {
    __shared__ float t[32][33];
    int n0 = blockIdx.x * 32, k0 = blockIdx.y * 32;
    int tx = threadIdx.x, ty = threadIdx.y;  // 32 x 8
    #pragma unroll
    for (int i = 0; i < 4; i++) {
        int k = k0 + ty + i * 8, n = n0 + tx;
        if (k < K && n < N) t[ty + i * 8][tx] = src[(size_t)k * N + n];
    }
    __syncthreads();
    #pragma unroll
    for (int i = 0; i < 4; i++) {
        int n = n0 + ty + i * 8, k = k0 + tx;
        if (n < N && k < K) {
            float v = t[tx][ty + i * 8];
            int nd = n;
            if (PERM) {
                int h = n / 768, r = n - h * 768;
                int f = r / 3, c = r - f * 3;
                nd = c * 2048 + h * 256 + f;
            }
            split_store(dh, dl, (size_t)nd * K + k, v);
        }
    }
}

// launch 0: qkv weights (z<LL) + bias permute (z==LL)
__global__ void tsplit_qkv(const float* __restrict__ src, const float* __restrict__ qb) {
    int zl = blockIdx.z;
    if (zl == LL) {
        int bid = blockIdx.y * gridDim.x + blockIdx.x;
        int idx = bid * 256 + threadIdx.y * 32 + threadIdx.x;
        if (idx < LL * HD3) {
            int l = idx / HD3, j = idx - l * HD3;
            int h = j / 768, r = j - h * 768;
            int f = r / 3, c = r - f * 3;
            g_qkvb[(size_t)l * HD3 + c * 2048 + h * 256 + f] = qb[idx];
        }
        return;
    }
    tsplit_body<1>(src + (size_t)zl * DD * HD3,
                   g_qkvTh + (size_t)zl * HD3 * DD, g_qkvTl + (size_t)zl * HD3 * DD,
                   DD, HD3);
}

// launch 1: proj (z<LL), w1 (z<2LL), w2 (z<3LL), score-pad fill (z==3LL)
__global__ void tsplit_rest(const float* __restrict__ pw,
                            const float* __restrict__ w1,
                            const float* __restrict__ w2) {
    int zl = blockIdx.z;
    if (zl < LL) {
        tsplit_body<0>(pw + (size_t)zl * OD * DD,
                       g_projTh + (size_t)zl * DD * OD, g_projTl + (size_t)zl * DD * OD,
                       OD, DD);
    } else if (zl < 2 * LL) {
        int l = zl - LL;
        tsplit_body<0>(w1 + (size_t)l * DD * ED,
                       g_w1Th + (size_t)l * ED * DD, g_w1Tl + (size_t)l * ED * DD,
                       DD, ED);
    } else if (zl < 3 * LL) {
        int l = zl - 2 * LL;
        tsplit_body<0>(w2 + (size_t)l * ED * DD,
                       g_w2Th + (size_t)l * DD * ED, g_w2Tl + (size_t)l * DD * ED,
                       ED, DD);
    } else {
        long nb = (long)gridDim.x * gridDim.y;
        long bid = (long)blockIdx.y * gridDim.x + blockIdx.x;
        long i0 = bid * 256 + threadIdx.y * 32 + threadIdx.x;
        const long PER = TS2 - TT;                              // 30
        const long TOT = (long)BHn * TT * PER;
        for (long i = i0; i < TOT; i += nb * 256) {
            long row = i / PER, j = i - row * PER;
            g_s[(size_t)row * TS2 + TT + j] = -1e30f;
        }
    }
}

// ---- LN row stats (+ optional embed materialization into g_h for layer 0) ----
__global__ void ln_stats(const float* __restrict__ x, const float* __restrict__ cls,
                         const float* __restrict__ dict, int first) {
    int row = blockIdx.x * 8 + (threadIdx.x >> 5);   // 8 warps, one row each
    int lane = threadIdx.x & 31;
    float v[8];
    if (first) {
        int b = row / TT, t = row - b * TT;
        const float* src;
        if (t < NTOK)        src = x + ((size_t)b * NTOK + t) * DD;
        else if (t == NTOK)  src = cls;
        else                 src = dict;
        float4 a0 = *(const float4*)(src + lane * 8);
        float4 a1 = *(const float4*)(src + lane * 8 + 4);
        v[0]=a0.x; v[1]=a0.y; v[2]=a0.z; v[3]=a0.w;
        v[4]=a1.x; v[5]=a1.y; v[6]=a1.z; v[7]=a1.w;
        float4* dst = (float4*)(g_h + (size_t)row * DD + lane * 8);
        dst[0] = a0; dst[1] = a1;
    } else {
        float4 a0 = *(const float4*)(g_h + (size_t)row * DD + lane * 8);
        float4 a1 = *(const float4*)(g_h + (size_t)row * DD + lane * 8 + 4);
        v[0]=a0.x; v[1]=a0.y; v[2]=a0.z; v[3]=a0.w;
        v[4]=a1.x; v[5]=a1.y; v[6]=a1.z; v[7]=a1.w;
    }
    float s = 0.f, s2 = 0.f;
    #pragma unroll
    for (int i = 0; i < 8; i++) { s += v[i]; s2 += v[i] * v[i]; }
    #pragma unroll
    for (int o = 16; o > 0; o >>= 1) {
        s  += __shfl_xor_sync(0xFFFFFFFFu, s,  o);
        s2 += __shfl_xor_sync(0xFFFFFFFFu, s2, o);
    }
    if (lane == 0) {
        float mean = s * (1.0f / DD);
        float var  = s2 * (1.0f / DD) - mean * mean;
        g_lnm[row] = mean;
        g_lnr[row] = rsqrtf(var + 1e-5f);
    }
}

// ---- transpose V: [bh][t][f] -> vT [bh][f][t(pad KATT)] (hi only) ----
__global__ void transpose_v() {
    __shared__ hf th[32][33];
    int bh = blockIdx.z;
    int f0 = blockIdx.x * 32, t0 = blockIdx.y * 32;
    int tx = threadIdx.x, ty = threadIdx.y;   // 32 x 8
    const hf* vh = g_vh + (size_t)bh * TT * DD;
    #pragma unroll
    for (int i = 0; i < 4; i++) {
        int t = t0 + ty + i * 8;
        hf a = __float2half(0.f);
        if (t < TT) a = vh[(size_t)t * DD + f0 + tx];
        th[ty + i * 8][tx] = a;
    }
    __syncthreads();
    hf* dH = g_vTh + (size_t)bh * DD * KATT;
    #pragma unroll
    for (int i = 0; i < 4; i++) {
        int f = f0 + ty + i * 8, t = t0 + tx;
        dH[(size_t)f * KATT + t] = th[tx][ty + i * 8];
    }
}

// ---- attention row reduce: max + 1/sum(exp) over each score row ----
__global__ void attn_reduce() {
    int row = blockIdx.x;                       // bh*TT + t
    const float* p = g_s + (size_t)row * TS2;
    int tid = threadIdx.x;
    float v[5];
    float mx = -1e30f;
    #pragma unroll
    for (int it = 0; it < 5; it++) {
        int j = tid + it * 256;
        if (j < TT) { v[it] = p[j]; mx = fmaxf(mx, v[it]); }
    }
    __shared__ float red_m[8], red_s[8];
    #pragma unroll
    for (int o = 16; o > 0; o >>= 1) mx = fmaxf(mx, __shfl_xor_sync(0xFFFFFFFFu, mx, o));
    if ((tid & 31) == 0) red_m[tid >> 5] = mx;
    __syncthreads();
    if (tid < 32) {
        float a = (tid < 8) ? red_m[tid] : -1e30f;
        #pragma unroll
        for (int o = 4; o > 0; o >>= 1) a = fmaxf(a, __shfl_xor_sync(0xFFFFFFFFu, a, o));
        if (tid == 0) red_m[0] = a;
    }
    __syncthreads();
    mx = red_m[0];
    float sum = 0.f;
    #pragma unroll
    for (int it = 0; it < 5; it++) {
        int j = tid + it * 256;
        if (j < TT) sum += __expf(v[it] - mx);
    }
    #pragma unroll
    for (int o = 16; o > 0; o >>= 1) sum += __shfl_xor_sync(0xFFFFFFFFu, sum, o);
    if ((tid & 31) == 0) red_s[tid >> 5] = sum;
    __syncthreads();
    if (tid < 32) {
        float a = (tid < 8) ? red_s[tid] : 0.f;
        #pragma unroll
        for (int o = 4; o > 0; o >>= 1) a += __shfl_xor_sync(0xFFFFFFFFu, a, o);
        if (tid == 0) { g_rmax[row] = mx; g_rinv[row] = 1.0f / a; }
    }
}

// ---- final output split ----
__global__ void out_kernel(float* __restrict__ out) {
    long i = (long)blockIdx.x * blockDim.x + threadIdx.x;
    if (i >= (long)MM * DD) return;
    int d = (int)(i % DD);
    long r = i / DD;
    int t = (int)(r % TT);
    int b = (int)(r / TT);
    float v = g_h[i];
    if (t < NTOK)        out[((long)b * NTOK + t) * DD + d] = v;
    else if (t == NTOK)  out[(long)BB * NTOK * DD + (long)b * DD + d] = v;
    else                 out[(long)BB * NTOK * DD + (long)BB * DD + (long)b * DD + d] = v;
}

extern "C" void kernel_launch(void* const* d_in, const int* in_sizes, int n_in,
                              void* d_out, int out_size) {
    const float* x      = (const float*)d_in[0];
    const float* cls    = (const float*)d_in[1];
    const float* dict   = (const float*)d_in[2];
    const float* ln1_g  = (const float*)d_in[3];
    const float* ln1_b  = (const float*)d_in[4];
    const float* qkv_w  = (const float*)d_in[5];
    const float* qkv_b  = (const float*)d_in[6];
    const float* proj_w = (const float*)d_in[7];
    const float* proj_b = (const float*)d_in[8];
    const float* ln2_g  = (const float*)d_in[9];
    const float* ln2_b  = (const float*)d_in[10];
    const float* mlp_w1 = (const float*)d_in[11];
    const float* mlp_b1 = (const float*)d_in[12];
    const float* mlp_w2 = (const float*)d_in[13];
    const float* mlp_b2 = (const float*)d_in[14];

    cudaFuncSetAttribute(mma_gemm<0,0,1>, cudaFuncAttributeMaxDynamicSharedMemorySize, SMEM_DYN);
    cudaFuncSetAttribute(mma_gemm<1,2,3>, cudaFuncAttributeMaxDynamicSharedMemorySize, SMEM_DYN);
    cudaFuncSetAttribute(mma_gemm<2,1,1>, cudaFuncAttributeMaxDynamicSharedMemorySize, SMEM_DYN);
    cudaFuncSetAttribute(mma_gemm<3,0,3>, cudaFuncAttributeMaxDynamicSharedMemorySize, SMEM_DYN);
    cudaFuncSetAttribute(mma_gemm<4,2,3>, cudaFuncAttributeMaxDynamicSharedMemorySize, SMEM_DYN);
    cudaFuncSetAttribute(mma_gemm<5,0,3>, cudaFuncAttributeMaxDynamicSharedMemorySize, SMEM_DYN);

    float *gh, *gs, *qkvb;
    hf *qh, *kh, *vTh, *oh, *ol, *mh, *ml;
    hf *qkvTh, *qkvTl, *projTh, *projTl, *w1Th, *w1Tl, *w2Th, *w2Tl;
    cudaGetSymbolAddress((void**)&gh,  g_h);
    cudaGetSymbolAddress((void**)&gs,  g_s);
    cudaGetSymbolAddress((void**)&qkvb, g_qkvb);
    cudaGetSymbolAddress((void**)&qh,  g_qh);
    cudaGetSymbolAddress((void**)&kh,  g_kh);
    cudaGetSymbolAddress((void**)&vTh, g_vTh);
    cudaGetSymbolAddress((void**)&oh,  g_oh);
    cudaGetSymbolAddress((void**)&ol,  g_ol);
    cudaGetSymbolAddress((void**)&mh,  g_mh);
    cudaGetSymbolAddress((void**)&ml,  g_ml);
    cudaGetSymbolAddress((void**)&qkvTh, g_qkvTh);
    cudaGetSymbolAddress((void**)&qkvTl, g_qkvTl);
    cudaGetSymbolAddress((void**)&projTh, g_projTh);
    cudaGetSymbolAddress((void**)&projTl, g_projTl);
    cudaGetSymbolAddress((void**)&w1Th, g_w1Th);
    cudaGetSymbolAddress((void**)&w1Tl, g_w1Tl);
    cudaGetSymbolAddress((void**)&w2Th, g_w2Th);
    cudaGetSymbolAddress((void**)&w2Tl, g_w2Tl);

    dim3 tb(32, 8);
    // launch 0, 1: weight prep
    tsplit_qkv <<<dim3(HD3/32, DD/32, LL+1), tb>>>(qkv_w, qkv_b);
    tsplit_rest<<<dim3(32, 64, 3*LL+1), tb>>>(proj_w, mlp_w1, mlp_w2);

    for (int l = 0; l < LL; l++) {
        // launch 2 (l=0): LN1 stats (+ embed for layer 0)
        ln_stats<<<MM/8, 256>>>(x, cls, dict, l == 0 ? 1 : 0);

        // launch 3 (l=0): QKV GEMM with fused LN A-load  <- ncu capture target
        mma_gemm<1,2,3><<<dim3(HD3/128, (MM+127)/128, 1), 256, SMEM_DYN>>>(
            nullptr, nullptr, 0, 0,
            qkvTh + (size_t)l*HD3*DD, qkvTl + (size_t)l*HD3*DD, DD, 0,
            qkvb + (size_t)l*HD3, ln1_g + (size_t)l*DD, ln1_b + (size_t)l*DD,
            nullptr, 0, 0, MM, HD3, DD);

        transpose_v<<<dim3(DD/32, KATT/32, BHn), tb>>>();

        // scores = Qh Kh^T (single pass), batched over 64 heads
        mma_gemm<0,0,1><<<dim3((TT+127)/128, (TT+127)/128, BHn), 256, SMEM_DYN>>>(
            qh, nullptr, DD, (long)TT*DD,
            kh, nullptr, DD, (long)TT*DD,
            nullptr, nullptr, nullptr, gs, TS2, (long)TT*TS2, TT, TT, DD);

        attn_reduce<<<BHn*TT, 256>>>();

        // O = exp(S-max) V * (1/sum): fused exp A-load, single pass
        mma_gemm<2,1,1><<<dim3(DD/128, (TT+127)/128, BHn), 256, SMEM_DYN>>>(
            nullptr, nullptr, 0, 0,
            vTh, nullptr, KATT, (long)DD*KATT,
            nullptr, nullptr, nullptr, nullptr, 0, 0, TT, DD, KATT);

        // proj: [8208,2048] x [256,2048]^T -> fp32 h
        mma_gemm<3,0,3><<<dim3(DD/128, (MM+127)/128, 1), 256, SMEM_DYN>>>(
            oh, ol, OD, 0,
            projTh + (size_t)l*DD*OD, projTl + (size_t)l*DD*OD, OD, 0,
            proj_b + (size_t)l*DD, nullptr, nullptr, gh, DD, 0, MM, DD, OD);

        // LN2 stats
        ln_stats<<<MM/8, 256>>>(x, cls, dict, 0);

        // mlp1 with fused LN A-load, + gelu -> m split
        mma_gemm<4,2,3><<<dim3(ED/128, (MM+127)/128, 1), 256, SMEM_DYN>>>(
            nullptr, nullptr, 0, 0,
            w1Th + (size_t)l*ED*DD, w1Tl + (size_t)l*ED*DD, DD, 0,
            mlp_b1 + (size_t)l*ED, ln2_g + (size_t)l*DD, ln2_b + (size_t)l*DD,
            nullptr, 0, 0, MM, ED, DD);

        // mlp2 + gelu -> fp32 h
        mma_gemm<5,0,3><<<dim3(DD/128, (MM+127)/128, 1), 256, SMEM_DYN>>>(
            mh, ml, ED, 0,
            w2Th + (size_t)l*DD*ED, w2Tl + (size_t)l*DD*ED, ED, 0,
            mlp_b2 + (size_t)l*DD, nullptr, nullptr, gh, DD, 0, MM, DD, ED);
    }

    long total = (long)MM * DD;
    out_kernel<<<(unsigned)((total + 255) / 256), 256>>>((float*)d_out);
}

// round 11
// speedup vs baseline: 1.5823x; 1.0964x over previous
#include <cuda_runtime.h>
#include <cuda_fp16.h>
#include <math.h>
#include <stdint.h>

// ---- problem constants ----
#define BB 8
#define NTOK 1024
#define TT 1026            // N + cls + dict
#define DD 256
#define HH 8
#define LL 6
#define HD3 6144           // H*D*3
#define OD 2048            // H*D
#define ED 1024            // EXP*D
#define MM (BB*TT)         // 8208 rows
#define BHn (BB*HH)        // 64
#define TS2 1056           // padded fp32 score row stride (= padded attention K)
#define KATT 1056          // padded key count for WV GEMM

typedef __half hf;

// ---- scratch (device globals; no allocs allowed) ----
__device__ __align__(16) float g_h [(size_t)MM*DD];
__device__ __align__(16) float g_s [(size_t)BHn*TT*TS2];
__device__ __align__(16) float g_lnm[(size_t)MM];
__device__ __align__(16) float g_lnr[(size_t)MM];
__device__ __align__(16) float g_qkvb[(size_t)LL*HD3];
__device__ __align__(16) hf g_qh[(size_t)BHn*TT*DD];
__device__ __align__(16) hf g_kh[(size_t)BHn*TT*DD];
__device__ __align__(16) hf g_vh[(size_t)BHn*TT*DD];
__device__ __align__(16) hf g_vTh[(size_t)BHn*DD*KATT];
__device__ __align__(16) hf g_oh[(size_t)MM*OD];
__device__ __align__(16) hf g_ol[(size_t)MM*OD];
__device__ __align__(16) hf g_mh[(size_t)MM*ED];
__device__ __align__(16) hf g_ml[(size_t)MM*ED];
// transposed + split weights [N,K] per layer
__device__ __align__(16) hf g_qkvTh[(size_t)LL*HD3*DD];
__device__ __align__(16) hf g_qkvTl[(size_t)LL*HD3*DD];
__device__ __align__(16) hf g_projTh[(size_t)LL*DD*OD];
__device__ __align__(16) hf g_projTl[(size_t)LL*DD*OD];
__device__ __align__(16) hf g_w1Th[(size_t)LL*ED*DD];
__device__ __align__(16) hf g_w1Tl[(size_t)LL*ED*DD];
__device__ __align__(16) hf g_w2Th[(size_t)LL*DD*ED];
__device__ __align__(16) hf g_w2Tl[(size_t)LL*DD*ED];

__device__ __forceinline__ float gelu_exact(float x) {
    return 0.5f * x * (1.0f + erff(x * 0.70710678118654752440f));
}

__device__ __forceinline__ uint32_t smem_u32(const void* p) {
    uint32_t a;
    asm("{ .reg .u64 t; cvta.to.shared.u64 t, %1; cvt.u32.u64 %0, t; }" : "=r"(a) : "l"(p));
    return a;
}

__device__ __forceinline__ void ldsm4(uint32_t* r, uint32_t addr) {
    asm volatile("ldmatrix.sync.aligned.m8n8.x4.shared.b16 {%0,%1,%2,%3}, [%4];"
                 : "=r"(r[0]), "=r"(r[1]), "=r"(r[2]), "=r"(r[3]) : "r"(addr));
}

__device__ __forceinline__ void mma16816(float* d, const uint32_t* a, const uint32_t* b) {
    asm volatile(
        "mma.sync.aligned.m16n8k16.row.col.f32.f16.f16.f32 "
        "{%0,%1,%2,%3}, {%4,%5,%6,%7}, {%8,%9}, {%0,%1,%2,%3};"
        : "+f"(d[0]), "+f"(d[1]), "+f"(d[2]), "+f"(d[3])
        : "r"(a[0]), "r"(a[1]), "r"(a[2]), "r"(a[3]), "r"(b[0]), "r"(b[1]));
}

__device__ __forceinline__ void cpa16(uint32_t dst, const void* src, bool v) {
    int sz = v ? 16 : 0;
    asm volatile("cp.async.cg.shared.global [%0], [%1], 16, %2;"
                 :: "r"(dst), "l"(src), "r"(sz) : "memory");
}
__device__ __forceinline__ void cpa_commit() {
    asm volatile("cp.async.commit_group;" ::: "memory");
}

__device__ __forceinline__ void split_store(hf* dh, hf* dl, size_t off, float v) {
    hf h = __float2half_rn(v);
    dh[off] = h;
    dl[off] = __float2half_rn(v - __half2float(h));
}

// pack 8 fp32 into hi/lo half uint4s
__device__ __forceinline__ void pack8(const float* p, uint4& h, uint4& l) {
    __half2 hh[4], ll[4];
    #pragma unroll
    for (int i = 0; i < 4; i++) {
        __half a = __float2half_rn(p[2*i]);
        __half b = __float2half_rn(p[2*i+1]);
        hh[i] = __halves2half2(a, b);
        ll[i] = __halves2half2(__float2half_rn(p[2*i]   - __half2float(a)),
                               __float2half_rn(p[2*i+1] - __half2float(b)));
    }
    h = *(uint4*)hh;
    l = *(uint4*)ll;
}
// hi only
__device__ __forceinline__ void pack8h(const float* p, uint4& h) {
    __half2 hh[4];
    #pragma unroll
    for (int i = 0; i < 4; i++)
        hh[i] = __halves2half2(__float2half_rn(p[2*i]), __float2half_rn(p[2*i+1]));
    h = *(uint4*)hh;
}

// per-element epilogue
template<int EPI>
__device__ __forceinline__ void epi_store(int gm, int gn, float v, int M, int N,
                                          const float* __restrict__ bias,
                                          float* __restrict__ C, int ldc, long sC, int z) {
    if (gm >= M || gn >= N) return;
    if constexpr (EPI == 0) {                 // scores -> fp32 (ldc=TS2)
        C[(size_t)z * sC + (size_t)gm * ldc + gn] = v;
    } else if constexpr (EPI == 1) {          // qkv scatter (permuted cols: c*2048+h*256+f)
        v += bias[gn];
        int c = gn >> 11;
        int rem = gn & 2047;
        int h = rem >> 8, f = rem & 255;
        int b = gm / TT, t = gm - b * TT;
        int bh = b * HH + h;
        size_t o = ((size_t)bh * TT + t) * DD + f;
        if (c == 2) {
            g_vh[o] = __float2half_rn(v);     // hi only
        } else {
            v *= 0.0625f;                     // 1/sqrt(256)
            if (c == 0) g_qh[o] = __float2half_rn(v);
            else        g_kh[o] = __float2half_rn(v);
        }
    } else if constexpr (EPI == 2) {          // WV (already normalized) -> split to o
        int b = z >> 3, head = z & 7;
        split_store(g_oh, g_ol, ((size_t)b * TT + gm) * OD + (size_t)head * DD + gn, v);
    } else if constexpr (EPI == 3) {          // proj -> fp32 + bias
        C[(size_t)gm * ldc + gn] = v + bias[gn];
    } else if constexpr (EPI == 4) {          // mlp1: bias+gelu -> m split
        split_store(g_mh, g_ml, (size_t)gm * ED + gn, gelu_exact(v + bias[gn]));
    } else {                                  // mlp2: bias+gelu -> fp32
        C[(size_t)gm * ldc + gn] = gelu_exact(v + bias[gn]);
    }
}

// ============ HMMA fp16 split GEMM: 128x128 block, BK=32, cp.async 3-stage ============
// Tile layout: 64B rows (32 halves), 16B-chunk XOR swizzle:
//   chunk c of row r lives at r*64 + ((c ^ ((r>>1)&3)) * 16)
// MODE 0: A (hi[/lo]) via cp.async.
// MODE 1: A = exp(score) from g_s on the fly; per-row sum(exp) accumulated inline
//         (no max subtraction needed: |S| << 1), epilogue divides by row sum.
// MODE 2: A = LayerNorm(g_h row) via g_lnm/g_lnr + lng/lnb, split on the fly.
// NPASS 1: Ah*Bh.  NPASS 2: +Al*Bh.  NPASS 3: +Ah*Bl.
#define AH_OFF 0
#define AL_OFF 8192
#define BH_OFF 16384
#define BL_OFF 24576
#define STG_BYTES 32768
#define SMEM_DYN (3*STG_BYTES)

template<int EPI, int MODE, int NPASS>
__global__ void __launch_bounds__(256, 2) mma_gemm(
    const hf* __restrict__ Ah, const hf* __restrict__ Al, int lda, long sA,
    const hf* __restrict__ Bh, const hf* __restrict__ Bl, int ldb, long sB,
    const float* __restrict__ bias,
    const float* __restrict__ lng, const float* __restrict__ lnb,
    float* __restrict__ C, int ldc, long sC,
    int M, int N, int K)
{
    extern __shared__ char smdyn[];
    uint32_t sb = smem_u32(smdyn);

    int tid = threadIdx.x, lane = tid & 31, wid = tid >> 5;
    int wm = wid >> 1, wn = wid & 1;
    int z = blockIdx.z;
    Bh += (size_t)z * sB;
    if constexpr (NPASS == 3) Bl += (size_t)z * sB;
    int bm = blockIdx.y * 128, bn = blockIdx.x * 128;

    int row0 = tid >> 2, row1 = row0 + 64;
    int cv  = tid & 3;                        // 16B chunk index
    int cvb = cv * 16;                        // byte offset in source row
    int cofs = cv * 8;                        // element offset (8 elems)
    bool aval0 = (bm + row0) < M, aval1 = (bm + row1) < M;
    bool bval0 = (bn + row0) < N, bval1 = (bn + row1) < N;
    const char* pBh0 = (const char*)(Bh + (size_t)(bval0 ? bn + row0 : 0) * ldb) + cvb;
    const char* pBh1 = (const char*)(Bh + (size_t)(bval1 ? bn + row1 : 0) * ldb) + cvb;
    const char* pBl0 = nullptr; const char* pBl1 = nullptr;
    if constexpr (NPASS == 3) {
        pBl0 = (const char*)(Bl + (size_t)(bval0 ? bn + row0 : 0) * ldb) + cvb;
        pBl1 = (const char*)(Bl + (size_t)(bval1 ? bn + row1 : 0) * ldb) + cvb;
    }
    // swizzled smem offsets for the two rows this thread fills
    uint32_t st0 = (uint32_t)(row0 * 64 + ((cv ^ ((row0 >> 1) & 3)) * 16));
    uint32_t st1 = (uint32_t)(row1 * 64 + ((cv ^ ((row1 >> 1) & 3)) * 16));

    // A sources
    const char *pAh0 = nullptr, *pAh1 = nullptr, *pAl0 = nullptr, *pAl1 = nullptr;
    const float *pS0 = nullptr, *pS1 = nullptr;
    float rm0 = 0.f, rm1 = 0.f, rr0 = 0.f, rr1 = 0.f;
    float se0 = 0.f, se1 = 0.f;               // MODE 1: per-thread partial row sums
    if constexpr (MODE == 1) {
        const float* Sz = g_s + (size_t)z * TT * TS2;
        pS0 = Sz + (size_t)(aval0 ? bm + row0 : 0) * TS2 + cofs;
        pS1 = Sz + (size_t)(aval1 ? bm + row1 : 0) * TS2 + cofs;
    } else if constexpr (MODE == 2) {
        pS0 = g_h + (size_t)(aval0 ? bm + row0 : 0) * DD + cofs;
        pS1 = g_h + (size_t)(aval1 ? bm + row1 : 0) * DD + cofs;
        if (aval0) { rm0 = g_lnm[bm + row0]; rr0 = g_lnr[bm + row0]; }
        if (aval1) { rm1 = g_lnm[bm + row1]; rr1 = g_lnr[bm + row1]; }
    } else {
        Ah += (size_t)z * sA;
        pAh0 = (const char*)(Ah + (size_t)(aval0 ? bm + row0 : 0) * lda) + cvb;
        pAh1 = (const char*)(Ah + (size_t)(aval1 ? bm + row1 : 0) * lda) + cvb;
        if constexpr (NPASS >= 2) {
            Al += (size_t)z * sA;
            pAl0 = (const char*)(Al + (size_t)(aval0 ? bm + row0 : 0) * lda) + cvb;
            pAl1 = (const char*)(Al + (size_t)(aval1 ? bm + row1 : 0) * lda) + cvb;
        }
    }

    float d[2][8][4];
    #pragma unroll
    for (int i = 0; i < 2; i++)
        #pragma unroll
        for (int j = 0; j < 8; j++)
            #pragma unroll
            for (int q = 0; q < 4; q++) d[i][j][q] = 0.f;

    // ldmatrix lane addressing (per-lane row + k-chunk)
    int group = lane >> 3, lrow = lane & 7;
    int a_row = wm * 32 + (group & 1) * 8 + lrow;
    int koA   = (group >> 1);                 // k chunk offset 0/1 (8 halves each)
    int b_row = wn * 64 + (group >> 1) * 8 + lrow;
    int koB   = (group & 1);
    int aS = (a_row >> 1) & 3;                // swizzle key; invariant under +16 rows
    int bS = (b_row >> 1) & 3;
    uint32_t aB0 = (uint32_t)(a_row * 64),       aB1 = (uint32_t)((a_row + 16) * 64);
    uint32_t bB[4];
    #pragma unroll
    for (int np = 0; np < 4; np++) bB[np] = (uint32_t)((b_row + np * 16) * 64);

    // issue cp.async for chunk c into stage stg (B always; A only MODE 0)
    auto issue = [&](int c, int stg) {
        uint32_t s0 = sb + (uint32_t)stg * STG_BYTES;
        size_t adv = (size_t)c * 64;          // 32 halves = 64 bytes
        if constexpr (MODE == 0) {
            cpa16(s0 + AH_OFF + st0, pAh0 + adv, aval0);
            cpa16(s0 + AH_OFF + st1, pAh1 + adv, aval1);
            if constexpr (NPASS >= 2) {
                cpa16(s0 + AL_OFF + st0, pAl0 + adv, aval0);
                cpa16(s0 + AL_OFF + st1, pAl1 + adv, aval1);
            }
        }
        cpa16(s0 + BH_OFF + st0, pBh0 + adv, bval0);
        cpa16(s0 + BH_OFF + st1, pBh1 + adv, bval1);
        if constexpr (NPASS == 3) {
            cpa16(s0 + BL_OFF + st0, pBl0 + adv, bval0);
            cpa16(s0 + BL_OFF + st1, pBl1 + adv, bval1);
        }
        cpa_commit();
    };

    float q0[8], q1[8];
    auto loadraw = [&](int c, float* r0, float* r1) {
        int kc = c * 32;
        float4 x0 = *(const float4*)(pS0 + kc);
        float4 x1 = *(const float4*)(pS0 + kc + 4);
        float4 y0 = *(const float4*)(pS1 + kc);
        float4 y1 = *(const float4*)(pS1 + kc + 4);
        r0[0]=x0.x; r0[1]=x0.y; r0[2]=x0.z; r0[3]=x0.w;
        r0[4]=x1.x; r0[5]=x1.y; r0[6]=x1.z; r0[7]=x1.w;
        r1[0]=y0.x; r1[1]=y0.y; r1[2]=y0.z; r1[3]=y0.w;
        r1[4]=y1.x; r1[5]=y1.y; r1[6]=y1.z; r1[7]=y1.w;
    };
    auto packstore = [&](int c, int stg, const float* r0, const float* r1) {
        float p[8];
        char* as = smdyn + (size_t)stg * STG_BYTES;
        if constexpr (MODE == 1) {
            #pragma unroll
            for (int i = 0; i < 8; i++) {
                p[i] = aval0 ? __expf(r0[i]) : 0.f;   // pads are -1e30 -> exp = 0
                se0 += p[i];
            }
            uint4 h0; pack8h(p, h0);
            *(uint4*)(as + AH_OFF + st0) = h0;
            #pragma unroll
            for (int i = 0; i < 8; i++) {
                p[i] = aval1 ? __expf(r1[i]) : 0.f;
                se1 += p[i];
            }
            uint4 h1; pack8h(p, h1);
            *(uint4*)(as + AH_OFF + st1) = h1;
        } else {  // MODE == 2 (LN; always split)
            int kc = c * 32;
            const float* gk = lng + kc + cofs;
            const float* bk = lnb + kc + cofs;
            uint4 h0, l0, h1, l1;
            #pragma unroll
            for (int i = 0; i < 8; i++)
                p[i] = aval0 ? (r0[i] - rm0) * rr0 * gk[i] + bk[i] : 0.f;
            pack8(p, h0, l0);
            #pragma unroll
            for (int i = 0; i < 8; i++)
                p[i] = aval1 ? (r1[i] - rm1) * rr1 * gk[i] + bk[i] : 0.f;
            pack8(p, h1, l1);
            *(uint4*)(as + AH_OFF + st0) = h0;
            *(uint4*)(as + AL_OFF + st0) = l0;
            *(uint4*)(as + AH_OFF + st1) = h1;
            *(uint4*)(as + AL_OFF + st1) = l1;
        }
    };

    int nit = K >> 5;                         // >= 8 for all our shapes
    if constexpr (MODE != 0) {
        loadraw(0, q0, q1); packstore(0, 0, q0, q1);
        loadraw(1, q0, q1); packstore(1, 1, q0, q1);
    }
    issue(0, 0);
    issue(1, 1);

    int stg_c = 0;                            // c % 3
    for (int c = 0; c < nit; c++) {
        if (c + 1 < nit) {
            asm volatile("cp.async.wait_group 1;" ::: "memory");
        } else {
            asm volatile("cp.async.wait_group 0;" ::: "memory");
        }
        __syncthreads();                      // publish stage c; free stage c-1

        int stg_n = stg_c + 2; if (stg_n >= 3) stg_n -= 3;   // (c+2) % 3
        bool have2 = (c + 2 < nit);
        if (have2) {
            issue(c + 2, stg_n);
            if constexpr (MODE != 0) loadraw(c + 2, q0, q1);
        }

        uint32_t cb = sb + (uint32_t)stg_c * STG_BYTES;
        #pragma unroll
        for (int ks = 0; ks < 32; ks += 16) {
            int kc = ks >> 3;                 // 0 or 2
            uint32_t a_hf[2][4], a_lf[2][4];
            {
                uint32_t sw = (uint32_t)(((kc + koA) ^ aS) << 4);
                uint32_t o0 = cb + aB0 + sw, o1 = cb + aB1 + sw;
                ldsm4(a_hf[0], o0 + AH_OFF);
                ldsm4(a_hf[1], o1 + AH_OFF);
                if constexpr (NPASS >= 2) {
                    ldsm4(a_lf[0], o0 + AL_OFF);
                    ldsm4(a_lf[1], o1 + AL_OFF);
                }
            }
            uint32_t swb = (uint32_t)(((kc + koB) ^ bS) << 4);
            #pragma unroll
            for (int np = 0; np < 4; np++) {
                uint32_t b_hf[4], b_lf[4];
                uint32_t o = cb + bB[np] + swb;
                ldsm4(b_hf, o + BH_OFF);
                if constexpr (NPASS == 3) ldsm4(b_lf, o + BL_OFF);
                #pragma unroll
                for (int mt = 0; mt < 2; mt++)
                    #pragma unroll
                    for (int hq = 0; hq < 2; hq++)
                        mma16816(d[mt][np * 2 + hq], a_hf[mt], &b_hf[hq * 2]);
                if constexpr (NPASS >= 2) {
                    #pragma unroll
                    for (int mt = 0; mt < 2; mt++)
                        #pragma unroll
                        for (int hq = 0; hq < 2; hq++)
                            mma16816(d[mt][np * 2 + hq], a_lf[mt], &b_hf[hq * 2]);
                }
                if constexpr (NPASS == 3) {
                    #pragma unroll
                    for (int mt = 0; mt < 2; mt++)
                        #pragma unroll
                        for (int hq = 0; hq < 2; hq++)
                            mma16816(d[mt][np * 2 + hq], a_hf[mt], &b_lf[hq * 2]);
                }
            }
        }

        if constexpr (MODE != 0) {
            if (have2) packstore(c + 2, stg_n, q0, q1);   // LDG latency hidden by MMAs
        }

        if (++stg_c >= 3) stg_c -= 3;
    }

    // MODE 1: finish per-row sums -> smem rowinv[128]
    float* rowinv_sm = (float*)smdyn;         // reuse stage memory (all reads done)
    if constexpr (MODE == 1) {
        se0 += __shfl_xor_sync(0xFFFFFFFFu, se0, 1);
        se0 += __shfl_xor_sync(0xFFFFFFFFu, se0, 2);
        se1 += __shfl_xor_sync(0xFFFFFFFFu, se1, 1);
        se1 += __shfl_xor_sync(0xFFFFFFFFu, se1, 2);
        __syncthreads();
        if ((tid & 3) == 0) {
            rowinv_sm[row0] = 1.0f / fmaxf(se0, 1e-37f);
            rowinv_sm[row1] = 1.0f / fmaxf(se1, 1e-37f);
        }
        __syncthreads();
    }

    // epilogue
    #pragma unroll
    for (int mt = 0; mt < 2; mt++) {
        float sA0 = 1.f, sA1 = 1.f;
        if constexpr (MODE == 1) {
            int rl = wm * 32 + mt * 16 + (lane >> 2);
            sA0 = rowinv_sm[rl];
            sA1 = rowinv_sm[rl + 8];
        }
        #pragma unroll
        for (int nt = 0; nt < 8; nt++) {
            int r0 = bm + wm * 32 + mt * 16 + (lane >> 2);
            int c0 = bn + wn * 64 + nt * 8 + (lane & 3) * 2;
            float* dd = d[mt][nt];
            epi_store<EPI>(r0,     c0,     dd[0] * sA0, M, N, bias, C, ldc, sC, z);
            epi_store<EPI>(r0,     c0 + 1, dd[1] * sA0, M, N, bias, C, ldc, sC, z);
            epi_store<EPI>(r0 + 8, c0,     dd[2] * sA1, M, N, bias, C, ldc, sC, z);
            epi_store<EPI>(r0 + 8, c0 + 1, dd[3] * sA1, M, N, bias, C, ldc, sC, z);
        }
    }
}

// ---- shared transpose+split body: src [K,N] fp32 -> dh/dl [N,K] half ----
template<int PERM>
__device__ __forceinline__ void tsplit_body(const float* __restrict__ src,
                                            hf* __restrict__ dh, hf* __restrict__ dl,
                                            int K, int N) {
    __shared__ float t[32][33];
    int n0 = blockIdx.x * 32, k0 = blockIdx.y * 32;
    int tx = threadIdx.x, ty = threadIdx.y;  // 32 x 8
    #pragma unroll
    for (int i = 0; i < 4; i++) {
        int k = k0 + ty + i * 8, n = n0 + tx;
        if (k < K && n < N) t[ty + i * 8][tx] = src[(size_t)k * N + n];
    }
    __syncthreads();
    #pragma unroll
    for (int i = 0; i < 4; i++) {
        int n = n0 + ty + i * 8, k = k0 + tx;
        if (n < N && k < K) {
            float v = t[tx][ty + i * 8];
            int nd = n;
            if (PERM) {
                int h = n / 768, r = n - h * 768;
                int f = r / 3, c = r - f * 3;
                nd = c * 2048 + h * 256 + f;
            }
            split_store(dh, dl, (size_t)nd * K + k, v);
        }
    }
}

// launch 0: qkv weights (z<LL) + bias permute (z==LL)
__global__ void tsplit_qkv(const float* __restrict__ src, const float* __restrict__ qb) {
    int zl = blockIdx.z;
    if (zl == LL) {
        int bid = blockIdx.y * gridDim.x + blockIdx.x;
        int idx = bid * 256 + threadIdx.y * 32 + threadIdx.x;
        if (idx < LL * HD3) {
            int l = idx / HD3, j = idx - l * HD3;
            int h = j / 768, r = j - h * 768;
            int f = r / 3, c = r - f * 3;
            g_qkvb[(size_t)l * HD3 + c * 2048 + h * 256 + f] = qb[idx];
        }
        return;
    }
    tsplit_body<1>(src + (size_t)zl * DD * HD3,
                   g_qkvTh + (size_t)zl * HD3 * DD, g_qkvTl + (size_t)zl * HD3 * DD,
                   DD, HD3);
}

// launch 1: proj (z<LL), w1 (z<2LL), w2 (z<3LL), score-pad fill (z==3LL)
__global__ void tsplit_rest(const float* __restrict__ pw,
                            const float* __restrict__ w1,
                            const float* __restrict__ w2) {
    int zl = blockIdx.z;
    if (zl < LL) {
        tsplit_body<0>(pw + (size_t)zl * OD * DD,
                       g_projTh + (size_t)zl * DD * OD, g_projTl + (size_t)zl * DD * OD,
                       OD, DD);
    } else if (zl < 2 * LL) {
        int l = zl - LL;
        tsplit_body<0>(w1 + (size_t)l * DD * ED,
                       g_w1Th + (size_t)l * ED * DD, g_w1Tl + (size_t)l * ED * DD,
                       DD, ED);
    } else if (zl < 3 * LL) {
        int l = zl - 2 * LL;
        tsplit_body<0>(w2 + (size_t)l * ED * DD,
                       g_w2Th + (size_t)l * DD * ED, g_w2Tl + (size_t)l * DD * ED,
                       ED, DD);
    } else {
        long nb = (long)gridDim.x * gridDim.y;
        long bid = (long)blockIdx.y * gridDim.x + blockIdx.x;
        long i0 = bid * 256 + threadIdx.y * 32 + threadIdx.x;
        const long PER = TS2 - TT;                              // 30
        const long TOT = (long)BHn * TT * PER;
        for (long i = i0; i < TOT; i += nb * 256) {
            long row = i / PER, j = i - row * PER;
            g_s[(size_t)row * TS2 + TT + j] = -1e30f;
        }
    }
}

// ---- LN row stats (+ optional embed materialization into g_h for layer 0) ----
__global__ void ln_stats(const float* __restrict__ x, const float* __restrict__ cls,
                         const float* __restrict__ dict, int first) {
    int row = blockIdx.x * 8 + (threadIdx.x >> 5);   // 8 warps, one row each
    int lane = threadIdx.x & 31;
    float v[8];
    if (first) {
        int b = row / TT, t = row - b * TT;
        const float* src;
        if (t < NTOK)        src = x + ((size_t)b * NTOK + t) * DD;
        else if (t == NTOK)  src = cls;
        else                 src = dict;
        float4 a0 = *(const float4*)(src + lane * 8);
        float4 a1 = *(const float4*)(src + lane * 8 + 4);
        v[0]=a0.x; v[1]=a0.y; v[2]=a0.z; v[3]=a0.w;
        v[4]=a1.x; v[5]=a1.y; v[6]=a1.z; v[7]=a1.w;
        float4* dst = (float4*)(g_h + (size_t)row * DD + lane * 8);
        dst[0] = a0; dst[1] = a1;
    } else {
        float4 a0 = *(const float4*)(g_h + (size_t)row * DD + lane * 8);
        float4 a1 = *(const float4*)(g_h + (size_t)row * DD + lane * 8 + 4);
        v[0]=a0.x; v[1]=a0.y; v[2]=a0.z; v[3]=a0.w;
        v[4]=a1.x; v[5]=a1.y; v[6]=a1.z; v[7]=a1.w;
    }
    float s = 0.f, s2 = 0.f;
    #pragma unroll
    for (int i = 0; i < 8; i++) { s += v[i]; s2 += v[i] * v[i]; }
    #pragma unroll
    for (int o = 16; o > 0; o >>= 1) {
        s  += __shfl_xor_sync(0xFFFFFFFFu, s,  o);
        s2 += __shfl_xor_sync(0xFFFFFFFFu, s2, o);
    }
    if (lane == 0) {
        float mean = s * (1.0f / DD);
        float var  = s2 * (1.0f / DD) - mean * mean;
        g_lnm[row] = mean;
        g_lnr[row] = rsqrtf(var + 1e-5f);
    }
}

// ---- transpose V: [bh][t][f] -> vT [bh][f][t(pad KATT)] (hi only) ----
__global__ void transpose_v() {
    __shared__ hf th[32][33];
    int bh = blockIdx.z;
    int f0 = blockIdx.x * 32, t0 = blockIdx.y * 32;
    int tx = threadIdx.x, ty = threadIdx.y;   // 32 x 8
    const hf* vh = g_vh + (size_t)bh * TT * DD;
    #pragma unroll
    for (int i = 0; i < 4; i++) {
        int t = t0 + ty + i * 8;
        hf a = __float2half(0.f);
        if (t < TT) a = vh[(size_t)t * DD + f0 + tx];
        th[ty + i * 8][tx] = a;
    }
    __syncthreads();
    hf* dH = g_vTh + (size_t)bh * DD * KATT;
    #pragma unroll
    for (int i = 0; i < 4; i++) {
        int f = f0 + ty + i * 8, t = t0 + tx;
        dH[(size_t)f * KATT + t] = th[tx][ty + i * 8];
    }
}

// ---- final output split ----
__global__ void out_kernel(float* __restrict__ out) {
    long i = (long)blockIdx.x * blockDim.x + threadIdx.x;
    if (i >= (long)MM * DD) return;
    int d = (int)(i % DD);
    long r = i / DD;
    int t = (int)(r % TT);
    int b = (int)(r / TT);
    float v = g_h[i];
    if (t < NTOK)        out[((long)b * NTOK + t) * DD + d] = v;
    else if (t == NTOK)  out[(long)BB * NTOK * DD + (long)b * DD + d] = v;
    else                 out[(long)BB * NTOK * DD + (long)BB * DD + (long)b * DD + d] = v;
}

extern "C" void kernel_launch(void* const* d_in, const int* in_sizes, int n_in,
                              void* d_out, int out_size) {
    const float* x      = (const float*)d_in[0];
    const float* cls    = (const float*)d_in[1];
    const float* dict   = (const float*)d_in[2];
    const float* ln1_g  = (const float*)d_in[3];
    const float* ln1_b  = (const float*)d_in[4];
    const float* qkv_w  = (const float*)d_in[5];
    const float* qkv_b  = (const float*)d_in[6];
    const float* proj_w = (const float*)d_in[7];
    const float* proj_b = (const float*)d_in[8];
    const float* ln2_g  = (const float*)d_in[9];
    const float* ln2_b  = (const float*)d_in[10];
    const float* mlp_w1 = (const float*)d_in[11];
    const float* mlp_b1 = (const float*)d_in[12];
    const float* mlp_w2 = (const float*)d_in[13];
    const float* mlp_b2 = (const float*)d_in[14];

    cudaFuncSetAttribute(mma_gemm<0,0,1>, cudaFuncAttributeMaxDynamicSharedMemorySize, SMEM_DYN);
    cudaFuncSetAttribute(mma_gemm<1,2,3>, cudaFuncAttributeMaxDynamicSharedMemorySize, SMEM_DYN);
    cudaFuncSetAttribute(mma_gemm<2,1,1>, cudaFuncAttributeMaxDynamicSharedMemorySize, SMEM_DYN);
    cudaFuncSetAttribute(mma_gemm<3,0,3>, cudaFuncAttributeMaxDynamicSharedMemorySize, SMEM_DYN);
    cudaFuncSetAttribute(mma_gemm<4,2,3>, cudaFuncAttributeMaxDynamicSharedMemorySize, SMEM_DYN);
    cudaFuncSetAttribute(mma_gemm<5,0,3>, cudaFuncAttributeMaxDynamicSharedMemorySize, SMEM_DYN);

    float *gh, *gs, *qkvb;
    hf *qh, *kh, *vTh, *oh, *ol, *mh, *ml;
    hf *qkvTh, *qkvTl, *projTh, *projTl, *w1Th, *w1Tl, *w2Th, *w2Tl;
    cudaGetSymbolAddress((void**)&gh,  g_h);
    cudaGetSymbolAddress((void**)&gs,  g_s);
    cudaGetSymbolAddress((void**)&qkvb, g_qkvb);
    cudaGetSymbolAddress((void**)&qh,  g_qh);
    cudaGetSymbolAddress((void**)&kh,  g_kh);
    cudaGetSymbolAddress((void**)&vTh, g_vTh);
    cudaGetSymbolAddress((void**)&oh,  g_oh);
    cudaGetSymbolAddress((void**)&ol,  g_ol);
    cudaGetSymbolAddress((void**)&mh,  g_mh);
    cudaGetSymbolAddress((void**)&ml,  g_ml);
    cudaGetSymbolAddress((void**)&qkvTh, g_qkvTh);
    cudaGetSymbolAddress((void**)&qkvTl, g_qkvTl);
    cudaGetSymbolAddress((void**)&projTh, g_projTh);
    cudaGetSymbolAddress((void**)&projTl, g_projTl);
    cudaGetSymbolAddress((void**)&w1Th, g_w1Th);
    cudaGetSymbolAddress((void**)&w1Tl, g_w1Tl);
    cudaGetSymbolAddress((void**)&w2Th, g_w2Th);
    cudaGetSymbolAddress((void**)&w2Tl, g_w2Tl);

    dim3 tb(32, 8);
    // launch 0, 1: weight prep
    tsplit_qkv <<<dim3(HD3/32, DD/32, LL+1), tb>>>(qkv_w, qkv_b);
    tsplit_rest<<<dim3(32, 64, 3*LL+1), tb>>>(proj_w, mlp_w1, mlp_w2);

    for (int l = 0; l < LL; l++) {
        // launch 2 (l=0): LN1 stats (+ embed for layer 0)
        ln_stats<<<MM/8, 256>>>(x, cls, dict, l == 0 ? 1 : 0);

        // launch 3 (l=0): QKV GEMM with fused LN A-load  <- ncu capture target
        mma_gemm<1,2,3><<<dim3(HD3/128, (MM+127)/128, 1), 256, SMEM_DYN>>>(
            nullptr, nullptr, 0, 0,
            qkvTh + (size_t)l*HD3*DD, qkvTl + (size_t)l*HD3*DD, DD, 0,
            qkvb + (size_t)l*HD3, ln1_g + (size_t)l*DD, ln1_b + (size_t)l*DD,
            nullptr, 0, 0, MM, HD3, DD);

        transpose_v<<<dim3(DD/32, KATT/32, BHn), tb>>>();

        // scores = Qh Kh^T (single pass), batched over 64 heads
        mma_gemm<0,0,1><<<dim3((TT+127)/128, (TT+127)/128, BHn), 256, SMEM_DYN>>>(
            qh, nullptr, DD, (long)TT*DD,
            kh, nullptr, DD, (long)TT*DD,
            nullptr, nullptr, nullptr, gs, TS2, (long)TT*TS2, TT, TT, DD);

        // O = softmax(S) V: exp + inline row-sum + normalize, all in the WV GEMM
        mma_gemm<2,1,1><<<dim3(DD/128, (TT+127)/128, BHn), 256, SMEM_DYN>>>(
            nullptr, nullptr, 0, 0,
            vTh, nullptr, KATT, (long)DD*KATT,
            nullptr, nullptr, nullptr, nullptr, 0, 0, TT, DD, KATT);

        // proj: [8208,2048] x [256,2048]^T -> fp32 h
        mma_gemm<3,0,3><<<dim3(DD/128, (MM+127)/128, 1), 256, SMEM_DYN>>>(
            oh, ol, OD, 0,
            projTh + (size_t)l*DD*OD, projTl + (size_t)l*DD*OD, OD, 0,
            proj_b + (size_t)l*DD, nullptr, nullptr, gh, DD, 0, MM, DD, OD);

        // LN2 stats
        ln_stats<<<MM/8, 256>>>(x, cls, dict, 0);

        // mlp1 with fused LN A-load, + gelu -> m split
        mma_gemm<4,2,3><<<dim3(ED/128, (MM+127)/128, 1), 256, SMEM_DYN>>>(
            nullptr, nullptr, 0, 0,
            w1Th + (size_t)l*ED*DD, w1Tl + (size_t)l*ED*DD, DD, 0,
            mlp_b1 + (size_t)l*ED, ln2_g + (size_t)l*DD, ln2_b + (size_t)l*DD,
            nullptr, 0, 0, MM, ED, DD);

        // mlp2 + gelu -> fp32 h
        mma_gemm<5,0,3><<<dim3(DD/128, (MM+127)/128, 1), 256, SMEM_DYN>>>(
            mh, ml, ED, 0,
            w2Th + (size_t)l*DD*ED, w2Tl + (size_t)l*DD*ED, ED, 0,
            mlp_b2 + (size_t)l*DD, nullptr, nullptr, gh, DD, 0, MM, DD, ED);
    }

    long total = (long)MM * DD;
    out_kernel<<<(unsigned)((total + 255) / 256), 256>>>((float*)d_out);
}

// round 13
// speedup vs baseline: 1.9340x; 1.2223x over previous
#include <cuda_runtime.h>
#include <cuda_fp16.h>
#include <math.h>
#include <stdint.h>

// ---- problem constants ----
#define BB 8
#define NTOK 1024
#define TT 1026            // N + cls + dict
#define DD 256
#define HH 8
#define LL 6
#define HD3 6144           // H*D*3
#define OD 2048            // H*D
#define ED 1024            // EXP*D
#define MM (BB*TT)         // 8208 rows
#define BHn (BB*HH)        // 64
#define KATT 1056          // padded key count (prob row stride / WV K)

typedef __half hf;

// ---- scratch (device globals; no allocs allowed) ----
__device__ __align__(16) float g_h [(size_t)MM*DD];
__device__ __align__(16) float g_rsum[(size_t)BHn*TT];
__device__ __align__(16) float g_lnm[(size_t)MM];
__device__ __align__(16) float g_lnr[(size_t)MM];
__device__ __align__(16) float g_qkvb[(size_t)LL*HD3];
__device__ __align__(16) hf g_ph[(size_t)BHn*TT*KATT];   // exp(scores), fp16
__device__ __align__(16) hf g_qh[(size_t)BHn*TT*DD];
__device__ __align__(16) hf g_kh[(size_t)BHn*TT*DD];
__device__ __align__(16) hf g_vh[(size_t)BHn*TT*DD];
__device__ __align__(16) hf g_vTh[(size_t)BHn*DD*KATT];
__device__ __align__(16) hf g_oh[(size_t)MM*OD];
__device__ __align__(16) hf g_ol[(size_t)MM*OD];
__device__ __align__(16) hf g_mh[(size_t)MM*ED];
__device__ __align__(16) hf g_ml[(size_t)MM*ED];
// transposed + split weights [N,K] per layer
__device__ __align__(16) hf g_qkvTh[(size_t)LL*HD3*DD];
__device__ __align__(16) hf g_qkvTl[(size_t)LL*HD3*DD];
__device__ __align__(16) hf g_projTh[(size_t)LL*DD*OD];
__device__ __align__(16) hf g_projTl[(size_t)LL*DD*OD];
__device__ __align__(16) hf g_w1Th[(size_t)LL*ED*DD];
__device__ __align__(16) hf g_w1Tl[(size_t)LL*ED*DD];
__device__ __align__(16) hf g_w2Th[(size_t)LL*DD*ED];
__device__ __align__(16) hf g_w2Tl[(size_t)LL*DD*ED];

__device__ __forceinline__ float gelu_exact(float x) {
    return 0.5f * x * (1.0f + erff(x * 0.70710678118654752440f));
}

__device__ __forceinline__ uint32_t smem_u32(const void* p) {
    uint32_t a;
    asm("{ .reg .u64 t; cvta.to.shared.u64 t, %1; cvt.u32.u64 %0, t; }" : "=r"(a) : "l"(p));
    return a;
}

__device__ __forceinline__ void ldsm4(uint32_t* r, uint32_t addr) {
    asm volatile("ldmatrix.sync.aligned.m8n8.x4.shared.b16 {%0,%1,%2,%3}, [%4];"
                 : "=r"(r[0]), "=r"(r[1]), "=r"(r[2]), "=r"(r[3]) : "r"(addr));
}

__device__ __forceinline__ void mma16816(float* d, const uint32_t* a, const uint32_t* b) {
    asm volatile(
        "mma.sync.aligned.m16n8k16.row.col.f32.f16.f16.f32 "
        "{%0,%1,%2,%3}, {%4,%5,%6,%7}, {%8,%9}, {%0,%1,%2,%3};"
        : "+f"(d[0]), "+f"(d[1]), "+f"(d[2]), "+f"(d[3])
        : "r"(a[0]), "r"(a[1]), "r"(a[2]), "r"(a[3]), "r"(b[0]), "r"(b[1]));
}

__device__ __forceinline__ void cpa16(uint32_t dst, const void* src, bool v) {
    int sz = v ? 16 : 0;
    asm volatile("cp.async.cg.shared.global [%0], [%1], 16, %2;"
                 :: "r"(dst), "l"(src), "r"(sz) : "memory");
}
__device__ __forceinline__ void cpa_commit() {
    asm volatile("cp.async.commit_group;" ::: "memory");
}

__device__ __forceinline__ void split_store(hf* dh, hf* dl, size_t off, float v) {
    hf h = __float2half_rn(v);
    dh[off] = h;
    dl[off] = __float2half_rn(v - __half2float(h));
}

// pack 8 fp32 into hi/lo half uint4s
__device__ __forceinline__ void pack8(const float* p, uint4& h, uint4& l) {
    __half2 hh[4], ll[4];
    #pragma unroll
    for (int i = 0; i < 4; i++) {
        __half a = __float2half_rn(p[2*i]);
        __half b = __float2half_rn(p[2*i+1]);
        hh[i] = __halves2half2(a, b);
        ll[i] = __halves2half2(__float2half_rn(p[2*i]   - __half2float(a)),
                               __float2half_rn(p[2*i+1] - __half2float(b)));
    }
    h = *(uint4*)hh;
    l = *(uint4*)ll;
}

// per-element epilogue (EPI != 0 paths)
template<int EPI>
__device__ __forceinline__ void epi_store(int gm, int gn, float v, int M, int N,
                                          const float* __restrict__ bias,
                                          float* __restrict__ C, int ldc, long sC, int z) {
    if (gm >= M || gn >= N) return;
    if constexpr (EPI == 1) {                 // qkv scatter (permuted cols: c*2048+h*256+f)
        v += bias[gn];
        int c = gn >> 11;
        int rem = gn & 2047;
        int h = rem >> 8, f = rem & 255;
        int b = gm / TT, t = gm - b * TT;
        int bh = b * HH + h;
        size_t o = ((size_t)bh * TT + t) * DD + f;
        if (c == 2) {
            g_vh[o] = __float2half_rn(v);     // hi only
        } else {
            v *= 0.0625f;                     // 1/sqrt(256)
            if (c == 0) g_qh[o] = __float2half_rn(v);
            else        g_kh[o] = __float2half_rn(v);
        }
    } else if constexpr (EPI == 2) {          // WV (pre-normalized by caller) -> split to o
        int b = z >> 3, head = z & 7;
        split_store(g_oh, g_ol, ((size_t)b * TT + gm) * OD + (size_t)head * DD + gn, v);
    } else if constexpr (EPI == 3) {          // proj -> fp32 + bias
        C[(size_t)gm * ldc + gn] = v + bias[gn];
    } else if constexpr (EPI == 4) {          // mlp1: bias+gelu -> m split
        split_store(g_mh, g_ml, (size_t)gm * ED + gn, gelu_exact(v + bias[gn]));
    } else {                                  // mlp2: bias+gelu -> fp32
        C[(size_t)gm * ldc + gn] = gelu_exact(v + bias[gn]);
    }
}

// ============ HMMA fp16 split GEMM: 128x128 block, BK=32, cp.async 3-stage ============
// Tile layout: 64B rows (32 halves), 16B-chunk XOR swizzle:
//   chunk c of row r lives at r*64 + ((c ^ ((r>>1)&3)) * 16)
// MODE 0: A (hi[/lo]) via cp.async.
// MODE 2: A = LayerNorm(g_h row) via g_lnm/g_lnr + lng/lnb, split on the fly.
// NPASS 1: Ah*Bh.  NPASS 2: +Al*Bh.  NPASS 3: +Ah*Bl.
// EPI 0: probs epilogue — exp(S) -> fp16 g_ph + atomic row-sums into g_rsum.
// EPI 2: epilogue normalizes by 1/g_rsum before storing.
#define AH_OFF 0
#define AL_OFF 8192
#define BH_OFF 16384
#define BL_OFF 24576
#define STG_BYTES 32768
#define SMEM_DYN (3*STG_BYTES)

template<int EPI, int MODE, int NPASS>
__global__ void __launch_bounds__(256, 2) mma_gemm(
    const hf* __restrict__ Ah, const hf* __restrict__ Al, int lda, long sA,
    const hf* __restrict__ Bh, const hf* __restrict__ Bl, int ldb, long sB,
    const float* __restrict__ bias,
    const float* __restrict__ lng, const float* __restrict__ lnb,
    float* __restrict__ C, int ldc, long sC,
    int M, int N, int K)
{
    extern __shared__ char smdyn[];
    uint32_t sb = smem_u32(smdyn);

    int tid = threadIdx.x, lane = tid & 31, wid = tid >> 5;
    int wm = wid >> 1, wn = wid & 1;
    int z = blockIdx.z;
    Bh += (size_t)z * sB;
    if constexpr (NPASS == 3) Bl += (size_t)z * sB;
    int bm = blockIdx.y * 128, bn = blockIdx.x * 128;

    int row0 = tid >> 2, row1 = row0 + 64;
    int cv  = tid & 3;                        // 16B chunk index
    int cvb = cv * 16;                        // byte offset in source row
    int cofs = cv * 8;                        // element offset (8 elems)
    bool aval0 = (bm + row0) < M, aval1 = (bm + row1) < M;
    bool bval0 = (bn + row0) < N, bval1 = (bn + row1) < N;
    const char* pBh0 = (const char*)(Bh + (size_t)(bval0 ? bn + row0 : 0) * ldb) + cvb;
    const char* pBh1 = (const char*)(Bh + (size_t)(bval1 ? bn + row1 : 0) * ldb) + cvb;
    const char* pBl0 = nullptr; const char* pBl1 = nullptr;
    if constexpr (NPASS == 3) {
        pBl0 = (const char*)(Bl + (size_t)(bval0 ? bn + row0 : 0) * ldb) + cvb;
        pBl1 = (const char*)(Bl + (size_t)(bval1 ? bn + row1 : 0) * ldb) + cvb;
    }
    // swizzled smem offsets for the two rows this thread fills
    uint32_t st0 = (uint32_t)(row0 * 64 + ((cv ^ ((row0 >> 1) & 3)) * 16));
    uint32_t st1 = (uint32_t)(row1 * 64 + ((cv ^ ((row1 >> 1) & 3)) * 16));

    // A sources
    const char *pAh0 = nullptr, *pAh1 = nullptr, *pAl0 = nullptr, *pAl1 = nullptr;
    const float *pS0 = nullptr, *pS1 = nullptr;
    float rm0 = 0.f, rm1 = 0.f, rr0 = 0.f, rr1 = 0.f;
    if constexpr (MODE == 2) {
        pS0 = g_h + (size_t)(aval0 ? bm + row0 : 0) * DD + cofs;
        pS1 = g_h + (size_t)(aval1 ? bm + row1 : 0) * DD + cofs;
        if (aval0) { rm0 = g_lnm[bm + row0]; rr0 = g_lnr[bm + row0]; }
        if (aval1) { rm1 = g_lnm[bm + row1]; rr1 = g_lnr[bm + row1]; }
    } else {
        Ah += (size_t)z * sA;
        pAh0 = (const char*)(Ah + (size_t)(aval0 ? bm + row0 : 0) * lda) + cvb;
        pAh1 = (const char*)(Ah + (size_t)(aval1 ? bm + row1 : 0) * lda) + cvb;
        if constexpr (NPASS >= 2) {
            Al += (size_t)z * sA;
            pAl0 = (const char*)(Al + (size_t)(aval0 ? bm + row0 : 0) * lda) + cvb;
            pAl1 = (const char*)(Al + (size_t)(aval1 ? bm + row1 : 0) * lda) + cvb;
        }
    }

    float d[2][8][4];
    #pragma unroll
    for (int i = 0; i < 2; i++)
        #pragma unroll
        for (int j = 0; j < 8; j++)
            #pragma unroll
            for (int q = 0; q < 4; q++) d[i][j][q] = 0.f;

    // ldmatrix lane addressing (per-lane row + k-chunk)
    int group = lane >> 3, lrow = lane & 7;
    int a_row = wm * 32 + (group & 1) * 8 + lrow;
    int koA   = (group >> 1);                 // k chunk offset 0/1 (8 halves each)
    int b_row = wn * 64 + (group >> 1) * 8 + lrow;
    int koB   = (group & 1);
    int aS = (a_row >> 1) & 3;                // swizzle key; invariant under +16 rows
    int bS = (b_row >> 1) & 3;
    uint32_t aB0 = (uint32_t)(a_row * 64),       aB1 = (uint32_t)((a_row + 16) * 64);
    uint32_t bB[4];
    #pragma unroll
    for (int np = 0; np < 4; np++) bB[np] = (uint32_t)((b_row + np * 16) * 64);

    // issue cp.async for chunk c into stage stg (B always; A only MODE 0)
    auto issue = [&](int c, int stg) {
        uint32_t s0 = sb + (uint32_t)stg * STG_BYTES;
        size_t adv = (size_t)c * 64;          // 32 halves = 64 bytes
        if constexpr (MODE == 0) {
            cpa16(s0 + AH_OFF + st0, pAh0 + adv, aval0);
            cpa16(s0 + AH_OFF + st1, pAh1 + adv, aval1);
            if constexpr (NPASS >= 2) {
                cpa16(s0 + AL_OFF + st0, pAl0 + adv, aval0);
                cpa16(s0 + AL_OFF + st1, pAl1 + adv, aval1);
            }
        }
        cpa16(s0 + BH_OFF + st0, pBh0 + adv, bval0);
        cpa16(s0 + BH_OFF + st1, pBh1 + adv, bval1);
        if constexpr (NPASS == 3) {
            cpa16(s0 + BL_OFF + st0, pBl0 + adv, bval0);
            cpa16(s0 + BL_OFF + st1, pBl1 + adv, bval1);
        }
        cpa_commit();
    };

    float q0[8], q1[8];
    auto loadraw = [&](int c, float* r0, float* r1) {
        int kc = c * 32;
        float4 x0 = *(const float4*)(pS0 + kc);
        float4 x1 = *(const float4*)(pS0 + kc + 4);
        float4 y0 = *(const float4*)(pS1 + kc);
        float4 y1 = *(const float4*)(pS1 + kc + 4);
        r0[0]=x0.x; r0[1]=x0.y; r0[2]=x0.z; r0[3]=x0.w;
        r0[4]=x1.x; r0[5]=x1.y; r0[6]=x1.z; r0[7]=x1.w;
        r1[0]=y0.x; r1[1]=y0.y; r1[2]=y0.z; r1[3]=y0.w;
        r1[4]=y1.x; r1[5]=y1.y; r1[6]=y1.z; r1[7]=y1.w;
    };
    auto packstore = [&](int c, int stg, const float* r0, const float* r1) {
        // MODE 2 only: LayerNorm transform, hi/lo split
        float p[8];
        char* as = smdyn + (size_t)stg * STG_BYTES;
        int kc = c * 32;
        const float* gk = lng + kc + cofs;
        const float* bk = lnb + kc + cofs;
        uint4 h0, l0, h1, l1;
        #pragma unroll
        for (int i = 0; i < 8; i++)
            p[i] = aval0 ? (r0[i] - rm0) * rr0 * gk[i] + bk[i] : 0.f;
        pack8(p, h0, l0);
        #pragma unroll
        for (int i = 0; i < 8; i++)
            p[i] = aval1 ? (r1[i] - rm1) * rr1 * gk[i] + bk[i] : 0.f;
        pack8(p, h1, l1);
        *(uint4*)(as + AH_OFF + st0) = h0;
        *(uint4*)(as + AL_OFF + st0) = l0;
        *(uint4*)(as + AH_OFF + st1) = h1;
        *(uint4*)(as + AL_OFF + st1) = l1;
    };

    int nit = K >> 5;                         // >= 8 for all our shapes
    if constexpr (MODE == 2) {
        loadraw(0, q0, q1); packstore(0, 0, q0, q1);
        loadraw(1, q0, q1); packstore(1, 1, q0, q1);
    }
    issue(0, 0);
    issue(1, 1);

    int stg_c = 0;                            // c % 3
    for (int c = 0; c < nit; c++) {
        if (c + 1 < nit) {
            asm volatile("cp.async.wait_group 1;" ::: "memory");
        } else {
            asm volatile("cp.async.wait_group 0;" ::: "memory");
        }
        __syncthreads();                      // publish stage c; free stage c-1

        int stg_n = stg_c + 2; if (stg_n >= 3) stg_n -= 3;   // (c+2) % 3
        bool have2 = (c + 2 < nit);
        if (have2) {
            issue(c + 2, stg_n);
            if constexpr (MODE == 2) loadraw(c + 2, q0, q1);
        }

        uint32_t cb = sb + (uint32_t)stg_c * STG_BYTES;
        #pragma unroll
        for (int ks = 0; ks < 32; ks += 16) {
            int kc = ks >> 3;                 // 0 or 2
            uint32_t a_hf[2][4], a_lf[2][4];
            {
                uint32_t sw = (uint32_t)(((kc + koA) ^ aS) << 4);
                uint32_t o0 = cb + aB0 + sw, o1 = cb + aB1 + sw;
                ldsm4(a_hf[0], o0 + AH_OFF);
                ldsm4(a_hf[1], o1 + AH_OFF);
                if constexpr (NPASS >= 2) {
                    ldsm4(a_lf[0], o0 + AL_OFF);
                    ldsm4(a_lf[1], o1 + AL_OFF);
                }
            }
            uint32_t swb = (uint32_t)(((kc + koB) ^ bS) << 4);
            #pragma unroll
            for (int np = 0; np < 4; np++) {
                uint32_t b_hf[4], b_lf[4];
                uint32_t o = cb + bB[np] + swb;
                ldsm4(b_hf, o + BH_OFF);
                if constexpr (NPASS == 3) ldsm4(b_lf, o + BL_OFF);
                #pragma unroll
                for (int mt = 0; mt < 2; mt++)
                    #pragma unroll
                    for (int hq = 0; hq < 2; hq++)
                        mma16816(d[mt][np * 2 + hq], a_hf[mt], &b_hf[hq * 2]);
                if constexpr (NPASS >= 2) {
                    #pragma unroll
                    for (int mt = 0; mt < 2; mt++)
                        #pragma unroll
                        for (int hq = 0; hq < 2; hq++)
                            mma16816(d[mt][np * 2 + hq], a_lf[mt], &b_hf[hq * 2]);
                }
                if constexpr (NPASS == 3) {
                    #pragma unroll
                    for (int mt = 0; mt < 2; mt++)
                        #pragma unroll
                        for (int hq = 0; hq < 2; hq++)
                            mma16816(d[mt][np * 2 + hq], a_hf[mt], &b_lf[hq * 2]);
                }
            }
        }

        if constexpr (MODE == 2) {
            if (have2) packstore(c + 2, stg_n, q0, q1);   // LDG latency hidden by MMAs
        }

        if (++stg_c >= 3) stg_c -= 3;
    }

    // ---- epilogue ----
    if constexpr (EPI == 0) {
        // probs: exp(S) -> fp16, atomic per-row sums
        hf* P = g_ph + (size_t)z * TT * KATT;
        #pragma unroll
        for (int mt = 0; mt < 2; mt++) {
            int gr0 = bm + wm * 32 + mt * 16 + (lane >> 2);
            int gr1 = gr0 + 8;
            float rs0 = 0.f, rs1 = 0.f;
            #pragma unroll
            for (int nt = 0; nt < 8; nt++) {
                int c0 = bn + wn * 64 + nt * 8 + (lane & 3) * 2;
                float* dd = d[mt][nt];
                bool cok = (c0 < N);           // N even => c0+1 also in-bounds
                if (gr0 < M && cok) {
                    float e0 = __expf(dd[0]), e1 = __expf(dd[1]);
                    rs0 += e0 + e1;
                    *(__half2*)(P + (size_t)gr0 * KATT + c0) =
                        __halves2half2(__float2half_rn(e0), __float2half_rn(e1));
                }
                if (gr1 < M && cok) {
                    float e2 = __expf(dd[2]), e3 = __expf(dd[3]);
                    rs1 += e2 + e3;
                    *(__half2*)(P + (size_t)gr1 * KATT + c0) =
                        __halves2half2(__float2half_rn(e2), __float2half_rn(e3));
                }
            }
            rs0 += __shfl_xor_sync(0xFFFFFFFFu, rs0, 1);
            rs0 += __shfl_xor_sync(0xFFFFFFFFu, rs0, 2);
            rs1 += __shfl_xor_sync(0xFFFFFFFFu, rs1, 1);
            rs1 += __shfl_xor_sync(0xFFFFFFFFu, rs1, 2);
            if ((lane & 3) == 0) {
                if (gr0 < M) atomicAdd(&g_rsum[(size_t)z * TT + gr0], rs0);
                if (gr1 < M) atomicAdd(&g_rsum[(size_t)z * TT + gr1], rs1);
            }
        }
    } else {
        #pragma unroll
        for (int mt = 0; mt < 2; mt++) {
            float sA0 = 1.f, sA1 = 1.f;
            if constexpr (EPI == 2) {
                int gr0 = bm + wm * 32 + mt * 16 + (lane >> 2);
                if (gr0 < M)     sA0 = 1.0f / g_rsum[(size_t)z * TT + gr0];
                if (gr0 + 8 < M) sA1 = 1.0f / g_rsum[(size_t)z * TT + gr0 + 8];
            }
            #pragma unroll
            for (int nt = 0; nt < 8; nt++) {
                int r0 = bm + wm * 32 + mt * 16 + (lane >> 2);
                int c0 = bn + wn * 64 + nt * 8 + (lane & 3) * 2;
                float* dd = d[mt][nt];
                epi_store<EPI>(r0,     c0,     dd[0] * sA0, M, N, bias, C, ldc, sC, z);
                epi_store<EPI>(r0,     c0 + 1, dd[1] * sA0, M, N, bias, C, ldc, sC, z);
                epi_store<EPI>(r0 + 8, c0,     dd[2] * sA1, M, N, bias, C, ldc, sC, z);
                epi_store<EPI>(r0 + 8, c0 + 1, dd[3] * sA1, M, N, bias, C, ldc, sC, z);
            }
        }
    }
}

// ---- shared transpose+split body: src [K,N] fp32 -> dh/dl [N,K] half ----
template<int PERM>
__device__ __forceinline__ void tsplit_body(const float* __restrict__ src,
                                            hf* __restrict__ dh, hf* __restrict__ dl,
                                            int K, int N) {
    __shared__ float t[32][33];
    int n0 = blockIdx.x * 32, k0 = blockIdx.y * 32;
    int tx = threadIdx.x, ty = threadIdx.y;  // 32 x 8
    #pragma unroll
    for (int i = 0; i < 4; i++) {
        int k = k0 + ty + i * 8, n = n0 + tx;
        if (k < K && n < N) t[ty + i * 8][tx] = src[(size_t)k * N + n];
    }
    __syncthreads();
    #pragma unroll
    for (int i = 0; i < 4; i++) {
        int n = n0 + ty + i * 8, k = k0 + tx;
        if (n < N && k < K) {
            float v = t[tx][ty + i * 8];
            int nd = n;
            if (PERM) {
                int h = n / 768, r = n - h * 768;
                int f = r / 3, c = r - f * 3;
                nd = c * 2048 + h * 256 + f;
            }
            split_store(dh, dl, (size_t)nd * K + k, v);
        }
    }
}

// launch 0: qkv weights (z<LL) + bias permute (z==LL)
__global__ void tsplit_qkv(const float* __restrict__ src, const float* __restrict__ qb) {
    int zl = blockIdx.z;
    if (zl == LL) {
        int bid = blockIdx.y * gridDim.x + blockIdx.x;
        int idx = bid * 256 + threadIdx.y * 32 + threadIdx.x;
        if (idx < LL * HD3) {
            int l = idx / HD3, j = idx - l * HD3;
            int h = j / 768, r = j - h * 768;
            int f = r / 3, c = r - f * 3;
            g_qkvb[(size_t)l * HD3 + c * 2048 + h * 256 + f] = qb[idx];
        }
        return;
    }
    tsplit_body<1>(src + (size_t)zl * DD * HD3,
                   g_qkvTh + (size_t)zl * HD3 * DD, g_qkvTl + (size_t)zl * HD3 * DD,
                   DD, HD3);
}

// launch 1: proj (z<LL), w1 (z<2LL), w2 (z<3LL), prob-pad zero fill (z==3LL)
__global__ void tsplit_rest(const float* __restrict__ pw,
                            const float* __restrict__ w1,
                            const float* __restrict__ w2) {
    int zl = blockIdx.z;
    if (zl < LL) {
        tsplit_body<0>(pw + (size_t)zl * OD * DD,
                       g_projTh + (size_t)zl * DD * OD, g_projTl + (size_t)zl * DD * OD,
                       OD, DD);
    } else if (zl < 2 * LL) {
        int l = zl - LL;
        tsplit_body<0>(w1 + (size_t)l * DD * ED,
                       g_w1Th + (size_t)l * ED * DD, g_w1Tl + (size_t)l * ED * DD,
                       DD, ED);
    } else if (zl < 3 * LL) {
        int l = zl - 2 * LL;
        tsplit_body<0>(w2 + (size_t)l * ED * DD,
                       g_w2Th + (size_t)l * DD * ED, g_w2Tl + (size_t)l * DD * ED,
                       ED, DD);
    } else {
        long nb = (long)gridDim.x * gridDim.y;
        long bid = (long)blockIdx.y * gridDim.x + blockIdx.x;
        long i0 = bid * 256 + threadIdx.y * 32 + threadIdx.x;
        const long PER = KATT - TT;                             // 30
        const long TOT = (long)BHn * TT * PER;
        hf z0 = __float2half(0.f);
        for (long i = i0; i < TOT; i += nb * 256) {
            long row = i / PER, j = i - row * PER;
            g_ph[(size_t)row * KATT + TT + j] = z0;
        }
    }
}

// ---- LN row stats (+ optional embed materialization into g_h for layer 0) ----
__global__ void ln_stats(const float* __restrict__ x, const float* __restrict__ cls,
                         const float* __restrict__ dict, int first) {
    int row = blockIdx.x * 8 + (threadIdx.x >> 5);   // 8 warps, one row each
    int lane = threadIdx.x & 31;
    float v[8];
    if (first) {
        int b = row / TT, t = row - b * TT;
        const float* src;
        if (t < NTOK)        src = x + ((size_t)b * NTOK + t) * DD;
        else if (t == NTOK)  src = cls;
        else                 src = dict;
        float4 a0 = *(const float4*)(src + lane * 8);
        float4 a1 = *(const float4*)(src + lane * 8 + 4);
        v[0]=a0.x; v[1]=a0.y; v[2]=a0.z; v[3]=a0.w;
        v[4]=a1.x; v[5]=a1.y; v[6]=a1.z; v[7]=a1.w;
        float4* dst = (float4*)(g_h + (size_t)row * DD + lane * 8);
        dst[0] = a0; dst[1] = a1;
    } else {
        float4 a0 = *(const float4*)(g_h + (size_t)row * DD + lane * 8);
        float4 a1 = *(const float4*)(g_h + (size_t)row * DD + lane * 8 + 4);
        v[0]=a0.x; v[1]=a0.y; v[2]=a0.z; v[3]=a0.w;
        v[4]=a1.x; v[5]=a1.y; v[6]=a1.z; v[7]=a1.w;
    }
    float s = 0.f, s2 = 0.f;
    #pragma unroll
    for (int i = 0; i < 8; i++) { s += v[i]; s2 += v[i] * v[i]; }
    #pragma unroll
    for (int o = 16; o > 0; o >>= 1) {
        s  += __shfl_xor_sync(0xFFFFFFFFu, s,  o);
        s2 += __shfl_xor_sync(0xFFFFFFFFu, s2, o);
    }
    if (lane == 0) {
        float mean = s * (1.0f / DD);
        float var  = s2 * (1.0f / DD) - mean * mean;
        g_lnm[row] = mean;
        g_lnr[row] = rsqrtf(var + 1e-5f);
    }
}

// ---- transpose V: [bh][t][f] -> vT [bh][f][t(pad KATT)] + zero g_rsum[bh] ----
__global__ void transpose_v() {
    __shared__ hf th[32][33];
    int bh = blockIdx.z;
    int f0 = blockIdx.x * 32, t0 = blockIdx.y * 32;
    int tx = threadIdx.x, ty = threadIdx.y;   // 32 x 8
    if (blockIdx.x == 0 && blockIdx.y == 0) {
        int tid = ty * 32 + tx;
        for (int i = tid; i < TT; i += 256) g_rsum[(size_t)bh * TT + i] = 0.f;
    }
    const hf* vh = g_vh + (size_t)bh * TT * DD;
    #pragma unroll
    for (int i = 0; i < 4; i++) {
        int t = t0 + ty + i * 8;
        hf a = __float2half(0.f);
        if (t < TT) a = vh[(size_t)t * DD + f0 + tx];
        th[ty + i * 8][tx] = a;
    }
    __syncthreads();
    hf* dH = g_vTh + (size_t)bh * DD * KATT;
    #pragma unroll
    for (int i = 0; i < 4; i++) {
        int f = f0 + ty + i * 8, t = t0 + tx;
        dH[(size_t)f * KATT + t] = th[tx][ty + i * 8];
    }
}

// ---- final output split ----
__global__ void out_kernel(float* __restrict__ out) {
    long i = (long)blockIdx.x * blockDim.x + threadIdx.x;
    if (i >= (long)MM * DD) return;
    int d = (int)(i % DD);
    long r = i / DD;
    int t = (int)(r % TT);
    int b = (int)(r / TT);
    float v = g_h[i];
    if (t < NTOK)        out[((long)b * NTOK + t) * DD + d] = v;
    else if (t == NTOK)  out[(long)BB * NTOK * DD + (long)b * DD + d] = v;
    else                 out[(long)BB * NTOK * DD + (long)BB * DD + (long)b * DD + d] = v;
}

extern "C" void kernel_launch(void* const* d_in, const int* in_sizes, int n_in,
                              void* d_out, int out_size) {
    const float* x      = (const float*)d_in[0];
    const float* cls    = (const float*)d_in[1];
    const float* dict   = (const float*)d_in[2];
    const float* ln1_g  = (const float*)d_in[3];
    const float* ln1_b  = (const float*)d_in[4];
    const float* qkv_w  = (const float*)d_in[5];
    const float* qkv_b  = (const float*)d_in[6];
    const float* proj_w = (const float*)d_in[7];
    const float* proj_b = (const float*)d_in[8];
    const float* ln2_g  = (const float*)d_in[9];
    const float* ln2_b  = (const float*)d_in[10];
    const float* mlp_w1 = (const float*)d_in[11];
    const float* mlp_b1 = (const float*)d_in[12];
    const float* mlp_w2 = (const float*)d_in[13];
    const float* mlp_b2 = (const float*)d_in[14];

    cudaFuncSetAttribute(mma_gemm<0,0,1>, cudaFuncAttributeMaxDynamicSharedMemorySize, SMEM_DYN);
    cudaFuncSetAttribute(mma_gemm<1,2,2>, cudaFuncAttributeMaxDynamicSharedMemorySize, SMEM_DYN);
    cudaFuncSetAttribute(mma_gemm<2,0,1>, cudaFuncAttributeMaxDynamicSharedMemorySize, SMEM_DYN);
    cudaFuncSetAttribute(mma_gemm<3,0,3>, cudaFuncAttributeMaxDynamicSharedMemorySize, SMEM_DYN);
    cudaFuncSetAttribute(mma_gemm<4,2,3>, cudaFuncAttributeMaxDynamicSharedMemorySize, SMEM_DYN);
    cudaFuncSetAttribute(mma_gemm<5,0,3>, cudaFuncAttributeMaxDynamicSharedMemorySize, SMEM_DYN);

    float *gh, *qkvb;
    hf *ph, *qh, *kh, *vTh, *oh, *ol, *mh, *ml;
    hf *qkvTh, *qkvTl, *projTh, *projTl, *w1Th, *w1Tl, *w2Th, *w2Tl;
    cudaGetSymbolAddress((void**)&gh,  g_h);
    cudaGetSymbolAddress((void**)&qkvb, g_qkvb);
    cudaGetSymbolAddress((void**)&ph,  g_ph);
    cudaGetSymbolAddress((void**)&qh,  g_qh);
    cudaGetSymbolAddress((void**)&kh,  g_kh);
    cudaGetSymbolAddress((void**)&vTh, g_vTh);
    cudaGetSymbolAddress((void**)&oh,  g_oh);
    cudaGetSymbolAddress((void**)&ol,  g_ol);
    cudaGetSymbolAddress((void**)&mh,  g_mh);
    cudaGetSymbolAddress((void**)&ml,  g_ml);
    cudaGetSymbolAddress((void**)&qkvTh, g_qkvTh);
    cudaGetSymbolAddress((void**)&qkvTl, g_qkvTl);
    cudaGetSymbolAddress((void**)&projTh, g_projTh);
    cudaGetSymbolAddress((void**)&projTl, g_projTl);
    cudaGetSymbolAddress((void**)&w1Th, g_w1Th);
    cudaGetSymbolAddress((void**)&w1Tl, g_w1Tl);
    cudaGetSymbolAddress((void**)&w2Th, g_w2Th);
    cudaGetSymbolAddress((void**)&w2Tl, g_w2Tl);

    dim3 tb(32, 8);
    // launch 0, 1: weight prep (+ prob pad zero fill)
    tsplit_qkv <<<dim3(HD3/32, DD/32, LL+1), tb>>>(qkv_w, qkv_b);
    tsplit_rest<<<dim3(32, 64, 3*LL+1), tb>>>(proj_w, mlp_w1, mlp_w2);

    for (int l = 0; l < LL; l++) {
        // launch 2 (l=0): LN1 stats (+ embed for layer 0)
        ln_stats<<<MM/8, 256>>>(x, cls, dict, l == 0 ? 1 : 0);

        // launch 3 (l=0): QKV GEMM, fused LN A-load, 2-pass  <- ncu capture target
        mma_gemm<1,2,2><<<dim3(HD3/128, (MM+127)/128, 1), 256, SMEM_DYN>>>(
            nullptr, nullptr, 0, 0,
            qkvTh + (size_t)l*HD3*DD, qkvTl + (size_t)l*HD3*DD, DD, 0,
            qkvb + (size_t)l*HD3, ln1_g + (size_t)l*DD, ln1_b + (size_t)l*DD,
            nullptr, 0, 0, MM, HD3, DD);

        // V transpose + per-layer rowsum zeroing
        transpose_v<<<dim3(DD/32, KATT/32, BHn), tb>>>();

        // probs = exp(Qh Kh^T) -> fp16 + row sums, batched over 64 heads
        mma_gemm<0,0,1><<<dim3((TT+127)/128, (TT+127)/128, BHn), 256, SMEM_DYN>>>(
            qh, nullptr, DD, (long)TT*DD,
            kh, nullptr, DD, (long)TT*DD,
            nullptr, nullptr, nullptr, nullptr, 0, 0, TT, TT, DD);

        // O = P V / rowsum: plain fp16 GEMM, normalize in epilogue
        mma_gemm<2,0,1><<<dim3(DD/128, (TT+127)/128, BHn), 256, SMEM_DYN>>>(
            ph, nullptr, KATT, (long)TT*KATT,
            vTh, nullptr, KATT, (long)DD*KATT,
            nullptr, nullptr, nullptr, nullptr, 0, 0, TT, DD, KATT);

        // proj: [8208,2048] x [256,2048]^T -> fp32 h
        mma_gemm<3,0,3><<<dim3(DD/128, (MM+127)/128, 1), 256, SMEM_DYN>>>(
            oh, ol, OD, 0,
            projTh + (size_t)l*DD*OD, projTl + (size_t)l*DD*OD, OD, 0,
            proj_b + (size_t)l*DD, nullptr, nullptr, gh, DD, 0, MM, DD, OD);

        // LN2 stats
        ln_stats<<<MM/8, 256>>>(x, cls, dict, 0);

        // mlp1 with fused LN A-load, + gelu -> m split
        mma_gemm<4,2,3><<<dim3(ED/128, (MM+127)/128, 1), 256, SMEM_DYN>>>(
            nullptr, nullptr, 0, 0,
            w1Th + (size_t)l*ED*DD, w1Tl + (size_t)l*ED*DD, DD, 0,
            mlp_b1 + (size_t)l*ED, ln2_g + (size_t)l*DD, ln2_b + (size_t)l*DD,
            nullptr, 0, 0, MM, ED, DD);

        // mlp2 + gelu -> fp32 h
        mma_gemm<5,0,3><<<dim3(DD/128, (MM+127)/128, 1), 256, SMEM_DYN>>>(
            mh, ml, ED, 0,
            w2Th + (size_t)l*DD*ED, w2Tl + (size_t)l*DD*ED, ED, 0,
            mlp_b2 + (size_t)l*DD, nullptr, nullptr, gh, DD, 0, MM, DD, ED);
    }

    long total = (long)MM * DD;
    out_kernel<<<(unsigned)((total + 255) / 256), 256>>>((float*)d_out);
}

// round 14
// speedup vs baseline: 1.9980x; 1.0331x over previous
#include <cuda_runtime.h>
#include <cuda_fp16.h>
#include <math.h>
#include <stdint.h>

// ---- problem constants ----
#define BB 8
#define NTOK 1024
#define TT 1026            // N + cls + dict
#define DD 256
#define HH 8
#define LL 6
#define HD3 6144           // H*D*3
#define OD 2048            // H*D
#define ED 1024            // EXP*D
#define MM (BB*TT)         // 8208 rows
#define BHn (BB*HH)        // 64
#define KATT 1056          // padded key count (prob row stride / WV K)

typedef __half hf;

// ---- scratch (device globals; no allocs allowed) ----
__device__ __align__(16) float g_h [(size_t)MM*DD];
__device__ __align__(16) float g_rsum[(size_t)BHn*TT];
__device__ __align__(16) float g_lnm[(size_t)MM];
__device__ __align__(16) float g_lnr[(size_t)MM];
__device__ __align__(16) float g_qkvb[(size_t)LL*HD3];
__device__ __align__(16) hf g_ph[(size_t)BHn*TT*KATT];   // exp(scores), fp16
__device__ __align__(16) hf g_qh[(size_t)BHn*TT*DD];
__device__ __align__(16) hf g_kh[(size_t)BHn*TT*DD];
__device__ __align__(16) hf g_vh[(size_t)BHn*TT*DD];
__device__ __align__(16) hf g_vTh[(size_t)BHn*DD*KATT];
__device__ __align__(16) hf g_oh[(size_t)MM*OD];
__device__ __align__(16) hf g_ol[(size_t)MM*OD];
__device__ __align__(16) hf g_mh[(size_t)MM*ED];
__device__ __align__(16) hf g_ml[(size_t)MM*ED];
// transposed + split weights [N,K] per layer
__device__ __align__(16) hf g_qkvTh[(size_t)LL*HD3*DD];
__device__ __align__(16) hf g_qkvTl[(size_t)LL*HD3*DD];
__device__ __align__(16) hf g_projTh[(size_t)LL*DD*OD];
__device__ __align__(16) hf g_projTl[(size_t)LL*DD*OD];
__device__ __align__(16) hf g_w1Th[(size_t)LL*ED*DD];
__device__ __align__(16) hf g_w1Tl[(size_t)LL*ED*DD];
__device__ __align__(16) hf g_w2Th[(size_t)LL*DD*ED];
__device__ __align__(16) hf g_w2Tl[(size_t)LL*DD*ED];

__device__ __forceinline__ float gelu_exact(float x) {
    return 0.5f * x * (1.0f + erff(x * 0.70710678118654752440f));
}

__device__ __forceinline__ uint32_t smem_u32(const void* p) {
    uint32_t a;
    asm("{ .reg .u64 t; cvta.to.shared.u64 t, %1; cvt.u32.u64 %0, t; }" : "=r"(a) : "l"(p));
    return a;
}

__device__ __forceinline__ void ldsm4(uint32_t* r, uint32_t addr) {
    asm volatile("ldmatrix.sync.aligned.m8n8.x4.shared.b16 {%0,%1,%2,%3}, [%4];"
                 : "=r"(r[0]), "=r"(r[1]), "=r"(r[2]), "=r"(r[3]) : "r"(addr));
}

__device__ __forceinline__ void mma16816(float* d, const uint32_t* a, const uint32_t* b) {
    asm volatile(
        "mma.sync.aligned.m16n8k16.row.col.f32.f16.f16.f32 "
        "{%0,%1,%2,%3}, {%4,%5,%6,%7}, {%8,%9}, {%0,%1,%2,%3};"
        : "+f"(d[0]), "+f"(d[1]), "+f"(d[2]), "+f"(d[3])
        : "r"(a[0]), "r"(a[1]), "r"(a[2]), "r"(a[3]), "r"(b[0]), "r"(b[1]));
}

__device__ __forceinline__ void cpa16(uint32_t dst, const void* src, bool v) {
    int sz = v ? 16 : 0;
    asm volatile("cp.async.cg.shared.global [%0], [%1], 16, %2;"
                 :: "r"(dst), "l"(src), "r"(sz) : "memory");
}
__device__ __forceinline__ void cpa_commit() {
    asm volatile("cp.async.commit_group;" ::: "memory");
}

__device__ __forceinline__ void split_store(hf* dh, hf* dl, size_t off, float v) {
    hf h = __float2half_rn(v);
    dh[off] = h;
    dl[off] = __float2half_rn(v - __half2float(h));
}

// pack 8 fp32 into hi/lo half uint4s
__device__ __forceinline__ void pack8(const float* p, uint4& h, uint4& l) {
    __half2 hh[4], ll[4];
    #pragma unroll
    for (int i = 0; i < 4; i++) {
        __half a = __float2half_rn(p[2*i]);
        __half b = __float2half_rn(p[2*i+1]);
        hh[i] = __halves2half2(a, b);
        ll[i] = __halves2half2(__float2half_rn(p[2*i]   - __half2float(a)),
                               __float2half_rn(p[2*i+1] - __half2float(b)));
    }
    h = *(uint4*)hh;
    l = *(uint4*)ll;
}
// hi only
__device__ __forceinline__ void pack8h(const float* p, uint4& h) {
    __half2 hh[4];
    #pragma unroll
    for (int i = 0; i < 4; i++)
        hh[i] = __halves2half2(__float2half_rn(p[2*i]), __float2half_rn(p[2*i+1]));
    h = *(uint4*)hh;
}

// per-element epilogue (EPI != 0 paths)
template<int EPI>
__device__ __forceinline__ void epi_store(int gm, int gn, float v, int M, int N,
                                          const float* __restrict__ bias,
                                          float* __restrict__ C, int ldc, long sC, int z) {
    if (gm >= M || gn >= N) return;
    if constexpr (EPI == 1) {                 // qkv scatter (permuted cols: c*2048+h*256+f)
        v += bias[gn];
        int c = gn >> 11;
        int rem = gn & 2047;
        int h = rem >> 8, f = rem & 255;
        int b = gm / TT, t = gm - b * TT;
        int bh = b * HH + h;
        size_t o = ((size_t)bh * TT + t) * DD + f;
        if (c == 2) {
            g_vh[o] = __float2half_rn(v);     // hi only
        } else {
            v *= 0.0625f;                     // 1/sqrt(256)
            if (c == 0) g_qh[o] = __float2half_rn(v);
            else        g_kh[o] = __float2half_rn(v);
        }
    } else if constexpr (EPI == 2) {          // WV (pre-normalized by caller) -> split to o
        int b = z >> 3, head = z & 7;
        split_store(g_oh, g_ol, ((size_t)b * TT + gm) * OD + (size_t)head * DD + gn, v);
    } else if constexpr (EPI == 3) {          // proj -> fp32 + bias
        C[(size_t)gm * ldc + gn] = v + bias[gn];
    } else if constexpr (EPI == 4) {          // mlp1: bias+gelu -> m split
        split_store(g_mh, g_ml, (size_t)gm * ED + gn, gelu_exact(v + bias[gn]));
    } else {                                  // mlp2: bias+gelu -> fp32
        C[(size_t)gm * ldc + gn] = gelu_exact(v + bias[gn]);
    }
}

// ============ HMMA fp16 split GEMM: 128x128 block, BK=32, cp.async 3-stage ============
// Tile layout: 64B rows (32 halves), 16B-chunk XOR swizzle:
//   chunk c of row r lives at r*64 + ((c ^ ((r>>1)&3)) * 16)
// MODE 0: A (hi[/lo]) via cp.async.
// MODE 2: A = LayerNorm(g_h row) via g_lnm/g_lnr + lng/lnb on the fly
//         (hi/lo split only when NPASS >= 2).
// NPASS 1: Ah*Bh.  NPASS 2: +Al*Bh.  NPASS 3: +Ah*Bl.
// EPI 0: probs epilogue — exp(S) -> fp16 g_ph + atomic row-sums into g_rsum.
// EPI 2: epilogue normalizes by 1/g_rsum before storing.
#define AH_OFF 0
#define AL_OFF 8192
#define BH_OFF 16384
#define BL_OFF 24576
#define STG_BYTES 32768
#define SMEM_DYN (3*STG_BYTES)

template<int EPI, int MODE, int NPASS>
__global__ void __launch_bounds__(256, 2) mma_gemm(
    const hf* __restrict__ Ah, const hf* __restrict__ Al, int lda, long sA,
    const hf* __restrict__ Bh, const hf* __restrict__ Bl, int ldb, long sB,
    const float* __restrict__ bias,
    const float* __restrict__ lng, const float* __restrict__ lnb,
    float* __restrict__ C, int ldc, long sC,
    int M, int N, int K)
{
    extern __shared__ char smdyn[];
    uint32_t sb = smem_u32(smdyn);

    int tid = threadIdx.x, lane = tid & 31, wid = tid >> 5;
    int wm = wid >> 1, wn = wid & 1;
    int z = blockIdx.z;
    Bh += (size_t)z * sB;
    if constexpr (NPASS == 3) Bl += (size_t)z * sB;
    int bm = blockIdx.y * 128, bn = blockIdx.x * 128;

    int row0 = tid >> 2, row1 = row0 + 64;
    int cv  = tid & 3;                        // 16B chunk index
    int cvb = cv * 16;                        // byte offset in source row
    int cofs = cv * 8;                        // element offset (8 elems)
    bool aval0 = (bm + row0) < M, aval1 = (bm + row1) < M;
    bool bval0 = (bn + row0) < N, bval1 = (bn + row1) < N;
    const char* pBh0 = (const char*)(Bh + (size_t)(bval0 ? bn + row0 : 0) * ldb) + cvb;
    const char* pBh1 = (const char*)(Bh + (size_t)(bval1 ? bn + row1 : 0) * ldb) + cvb;
    const char* pBl0 = nullptr; const char* pBl1 = nullptr;
    if constexpr (NPASS == 3) {
        pBl0 = (const char*)(Bl + (size_t)(bval0 ? bn + row0 : 0) * ldb) + cvb;
        pBl1 = (const char*)(Bl + (size_t)(bval1 ? bn + row1 : 0) * ldb) + cvb;
    }
    // swizzled smem offsets for the two rows this thread fills
    uint32_t st0 = (uint32_t)(row0 * 64 + ((cv ^ ((row0 >> 1) & 3)) * 16));
    uint32_t st1 = (uint32_t)(row1 * 64 + ((cv ^ ((row1 >> 1) & 3)) * 16));

    // A sources
    const char *pAh0 = nullptr, *pAh1 = nullptr, *pAl0 = nullptr, *pAl1 = nullptr;
    const float *pS0 = nullptr, *pS1 = nullptr;
    float rm0 = 0.f, rm1 = 0.f, rr0 = 0.f, rr1 = 0.f;
    if constexpr (MODE == 2) {
        pS0 = g_h + (size_t)(aval0 ? bm + row0 : 0) * DD + cofs;
        pS1 = g_h + (size_t)(aval1 ? bm + row1 : 0) * DD + cofs;
        if (aval0) { rm0 = g_lnm[bm + row0]; rr0 = g_lnr[bm + row0]; }
        if (aval1) { rm1 = g_lnm[bm + row1]; rr1 = g_lnr[bm + row1]; }
    } else {
        Ah += (size_t)z * sA;
        pAh0 = (const char*)(Ah + (size_t)(aval0 ? bm + row0 : 0) * lda) + cvb;
        pAh1 = (const char*)(Ah + (size_t)(aval1 ? bm + row1 : 0) * lda) + cvb;
        if constexpr (NPASS >= 2) {
            Al += (size_t)z * sA;
            pAl0 = (const char*)(Al + (size_t)(aval0 ? bm + row0 : 0) * lda) + cvb;
            pAl1 = (const char*)(Al + (size_t)(aval1 ? bm + row1 : 0) * lda) + cvb;
        }
    }

    float d[2][8][4];
    #pragma unroll
    for (int i = 0; i < 2; i++)
        #pragma unroll
        for (int j = 0; j < 8; j++)
            #pragma unroll
            for (int q = 0; q < 4; q++) d[i][j][q] = 0.f;

    // ldmatrix lane addressing (per-lane row + k-chunk)
    int group = lane >> 3, lrow = lane & 7;
    int a_row = wm * 32 + (group & 1) * 8 + lrow;
    int koA   = (group >> 1);                 // k chunk offset 0/1 (8 halves each)
    int b_row = wn * 64 + (group >> 1) * 8 + lrow;
    int koB   = (group & 1);
    int aS = (a_row >> 1) & 3;                // swizzle key; invariant under +16 rows
    int bS = (b_row >> 1) & 3;
    uint32_t aB0 = (uint32_t)(a_row * 64),       aB1 = (uint32_t)((a_row + 16) * 64);
    uint32_t bB[4];
    #pragma unroll
    for (int np = 0; np < 4; np++) bB[np] = (uint32_t)((b_row + np * 16) * 64);

    // issue cp.async for chunk c into stage stg (B always; A only MODE 0)
    auto issue = [&](int c, int stg) {
        uint32_t s0 = sb + (uint32_t)stg * STG_BYTES;
        size_t adv = (size_t)c * 64;          // 32 halves = 64 bytes
        if constexpr (MODE == 0) {
            cpa16(s0 + AH_OFF + st0, pAh0 + adv, aval0);
            cpa16(s0 + AH_OFF + st1, pAh1 + adv, aval1);
            if constexpr (NPASS >= 2) {
                cpa16(s0 + AL_OFF + st0, pAl0 + adv, aval0);
                cpa16(s0 + AL_OFF + st1, pAl1 + adv, aval1);
            }
        }
        cpa16(s0 + BH_OFF + st0, pBh0 + adv, bval0);
        cpa16(s0 + BH_OFF + st1, pBh1 + adv, bval1);
        if constexpr (NPASS == 3) {
            cpa16(s0 + BL_OFF + st0, pBl0 + adv, bval0);
            cpa16(s0 + BL_OFF + st1, pBl1 + adv, bval1);
        }
        cpa_commit();
    };

    float q0[8], q1[8];
    auto loadraw = [&](int c, float* r0, float* r1) {
        int kc = c * 32;
        float4 x0 = *(const float4*)(pS0 + kc);
        float4 x1 = *(const float4*)(pS0 + kc + 4);
        float4 y0 = *(const float4*)(pS1 + kc);
        float4 y1 = *(const float4*)(pS1 + kc + 4);
        r0[0]=x0.x; r0[1]=x0.y; r0[2]=x0.z; r0[3]=x0.w;
        r0[4]=x1.x; r0[5]=x1.y; r0[6]=x1.z; r0[7]=x1.w;
        r1[0]=y0.x; r1[1]=y0.y; r1[2]=y0.z; r1[3]=y0.w;
        r1[4]=y1.x; r1[5]=y1.y; r1[6]=y1.z; r1[7]=y1.w;
    };
    auto packstore = [&](int c, int stg, const float* r0, const float* r1) {
        // MODE 2 only: LayerNorm transform; hi/lo split only when NPASS >= 2
        float p[8];
        char* as = smdyn + (size_t)stg * STG_BYTES;
        int kc = c * 32;
        const float* gk = lng + kc + cofs;
        const float* bk = lnb + kc + cofs;
        #pragma unroll
        for (int i = 0; i < 8; i++)
            p[i] = aval0 ? (r0[i] - rm0) * rr0 * gk[i] + bk[i] : 0.f;
        if constexpr (NPASS >= 2) {
            uint4 h0, l0;
            pack8(p, h0, l0);
            *(uint4*)(as + AH_OFF + st0) = h0;
            *(uint4*)(as + AL_OFF + st0) = l0;
        } else {
            uint4 h0; pack8h(p, h0);
            *(uint4*)(as + AH_OFF + st0) = h0;
        }
        #pragma unroll
        for (int i = 0; i < 8; i++)
            p[i] = aval1 ? (r1[i] - rm1) * rr1 * gk[i] + bk[i] : 0.f;
        if constexpr (NPASS >= 2) {
            uint4 h1, l1;
            pack8(p, h1, l1);
            *(uint4*)(as + AH_OFF + st1) = h1;
            *(uint4*)(as + AL_OFF + st1) = l1;
        } else {
            uint4 h1; pack8h(p, h1);
            *(uint4*)(as + AH_OFF + st1) = h1;
        }
    };

    int nit = K >> 5;                         // >= 8 for all our shapes
    if constexpr (MODE == 2) {
        loadraw(0, q0, q1); packstore(0, 0, q0, q1);
        loadraw(1, q0, q1); packstore(1, 1, q0, q1);
    }
    issue(0, 0);
    issue(1, 1);

    int stg_c = 0;                            // c % 3
    for (int c = 0; c < nit; c++) {
        if (c + 1 < nit) {
            asm volatile("cp.async.wait_group 1;" ::: "memory");
        } else {
            asm volatile("cp.async.wait_group 0;" ::: "memory");
        }
        __syncthreads();                      // publish stage c; free stage c-1

        int stg_n = stg_c + 2; if (stg_n >= 3) stg_n -= 3;   // (c+2) % 3
        bool have2 = (c + 2 < nit);
        if (have2) {
            issue(c + 2, stg_n);
            if constexpr (MODE == 2) loadraw(c + 2, q0, q1);
        }

        uint32_t cb = sb + (uint32_t)stg_c * STG_BYTES;
        #pragma unroll
        for (int ks = 0; ks < 32; ks += 16) {
            int kc = ks >> 3;                 // 0 or 2
            uint32_t a_hf[2][4], a_lf[2][4];
            {
                uint32_t sw = (uint32_t)(((kc + koA) ^ aS) << 4);
                uint32_t o0 = cb + aB0 + sw, o1 = cb + aB1 + sw;
                ldsm4(a_hf[0], o0 + AH_OFF);
                ldsm4(a_hf[1], o1 + AH_OFF);
                if constexpr (NPASS >= 2) {
                    ldsm4(a_lf[0], o0 + AL_OFF);
                    ldsm4(a_lf[1], o1 + AL_OFF);
                }
            }
            uint32_t swb = (uint32_t)(((kc + koB) ^ bS) << 4);
            #pragma unroll
            for (int np = 0; np < 4; np++) {
                uint32_t b_hf[4], b_lf[4];
                uint32_t o = cb + bB[np] + swb;
                ldsm4(b_hf, o + BH_OFF);
                if constexpr (NPASS == 3) ldsm4(b_lf, o + BL_OFF);
                #pragma unroll
                for (int mt = 0; mt < 2; mt++)
                    #pragma unroll
                    for (int hq = 0; hq < 2; hq++)
                        mma16816(d[mt][np * 2 + hq], a_hf[mt], &b_hf[hq * 2]);
                if constexpr (NPASS >= 2) {
                    #pragma unroll
                    for (int mt = 0; mt < 2; mt++)
                        #pragma unroll
                        for (int hq = 0; hq < 2; hq++)
                            mma16816(d[mt][np * 2 + hq], a_lf[mt], &b_hf[hq * 2]);
                }
                if constexpr (NPASS == 3) {
                    #pragma unroll
                    for (int mt = 0; mt < 2; mt++)
                        #pragma unroll
                        for (int hq = 0; hq < 2; hq++)
                            mma16816(d[mt][np * 2 + hq], a_hf[mt], &b_lf[hq * 2]);
                }
            }
        }

        if constexpr (MODE == 2) {
            if (have2) packstore(c + 2, stg_n, q0, q1);   // LDG latency hidden by MMAs
        }

        if (++stg_c >= 3) stg_c -= 3;
    }

    // ---- epilogue ----
    if constexpr (EPI == 0) {
        // probs: exp(S) -> fp16, atomic per-row sums
        hf* P = g_ph + (size_t)z * TT * KATT;
        #pragma unroll
        for (int mt = 0; mt < 2; mt++) {
            int gr0 = bm + wm * 32 + mt * 16 + (lane >> 2);
            int gr1 = gr0 + 8;
            float rs0 = 0.f, rs1 = 0.f;
            #pragma unroll
            for (int nt = 0; nt < 8; nt++) {
                int c0 = bn + wn * 64 + nt * 8 + (lane & 3) * 2;
                float* dd = d[mt][nt];
                bool cok = (c0 < N);           // N even => c0+1 also in-bounds
                if (gr0 < M && cok) {
                    float e0 = __expf(dd[0]), e1 = __expf(dd[1]);
                    rs0 += e0 + e1;
                    *(__half2*)(P + (size_t)gr0 * KATT + c0) =
                        __halves2half2(__float2half_rn(e0), __float2half_rn(e1));
                }
                if (gr1 < M && cok) {
                    float e2 = __expf(dd[2]), e3 = __expf(dd[3]);
                    rs1 += e2 + e3;
                    *(__half2*)(P + (size_t)gr1 * KATT + c0) =
                        __halves2half2(__float2half_rn(e2), __float2half_rn(e3));
                }
            }
            rs0 += __shfl_xor_sync(0xFFFFFFFFu, rs0, 1);
            rs0 += __shfl_xor_sync(0xFFFFFFFFu, rs0, 2);
            rs1 += __shfl_xor_sync(0xFFFFFFFFu, rs1, 1);
            rs1 += __shfl_xor_sync(0xFFFFFFFFu, rs1, 2);
            if ((lane & 3) == 0) {
                if (gr0 < M) atomicAdd(&g_rsum[(size_t)z * TT + gr0], rs0);
                if (gr1 < M) atomicAdd(&g_rsum[(size_t)z * TT + gr1], rs1);
            }
        }
    } else {
        #pragma unroll
        for (int mt = 0; mt < 2; mt++) {
            float sA0 = 1.f, sA1 = 1.f;
            if constexpr (EPI == 2) {
                int gr0 = bm + wm * 32 + mt * 16 + (lane >> 2);
                if (gr0 < M)     sA0 = 1.0f / g_rsum[(size_t)z * TT + gr0];
                if (gr0 + 8 < M) sA1 = 1.0f / g_rsum[(size_t)z * TT + gr0 + 8];
            }
            #pragma unroll
            for (int nt = 0; nt < 8; nt++) {
                int r0 = bm + wm * 32 + mt * 16 + (lane >> 2);
                int c0 = bn + wn * 64 + nt * 8 + (lane & 3) * 2;
                float* dd = d[mt][nt];
                epi_store<EPI>(r0,     c0,     dd[0] * sA0, M, N, bias, C, ldc, sC, z);
                epi_store<EPI>(r0,     c0 + 1, dd[1] * sA0, M, N, bias, C, ldc, sC, z);
                epi_store<EPI>(r0 + 8, c0,     dd[2] * sA1, M, N, bias, C, ldc, sC, z);
                epi_store<EPI>(r0 + 8, c0 + 1, dd[3] * sA1, M, N, bias, C, ldc, sC, z);
            }
        }
    }
}

// ---- shared transpose+split body: src [K,N] fp32 -> dh/dl [N,K] half ----
template<int PERM>
__device__ __forceinline__ void tsplit_body(const float* __restrict__ src,
                                            hf* __restrict__ dh, hf* __restrict__ dl,
                                            int K, int N) {
    __shared__ float t[32][33];
    int n0 = blockIdx.x * 32, k0 = blockIdx.y * 32;
    int tx = threadIdx.x, ty = threadIdx.y;  // 32 x 8
    #pragma unroll
    for (int i = 0; i < 4; i++) {
        int k = k0 + ty + i * 8, n = n0 + tx;
        if (k < K && n < N) t[ty + i * 8][tx] = src[(size_t)k * N + n];
    }
    __syncthreads();
    #pragma unroll
    for (int i = 0; i < 4; i++) {
        int n = n0 + ty + i * 8, k = k0 + tx;
        if (n < N && k < K) {
            float v = t[tx][ty + i * 8];
            int nd = n;
            if (PERM) {
                int h = n / 768, r = n - h * 768;
                int f = r / 3, c = r - f * 3;
                nd = c * 2048 + h * 256 + f;
            }
            split_store(dh, dl, (size_t)nd * K + k, v);
        }
    }
}

// launch 0: qkv weights (z<LL) + bias permute (z==LL)
__global__ void tsplit_qkv(const float* __restrict__ src, const float* __restrict__ qb) {
    int zl = blockIdx.z;
    if (zl == LL) {
        int bid = blockIdx.y * gridDim.x + blockIdx.x;
        int idx = bid * 256 + threadIdx.y * 32 + threadIdx.x;
        if (idx < LL * HD3) {
            int l = idx / HD3, j = idx - l * HD3;
            int h = j / 768, r = j - h * 768;
            int f = r / 3, c = r - f * 3;
            g_qkvb[(size_t)l * HD3 + c * 2048 + h * 256 + f] = qb[idx];
        }
        return;
    }
    tsplit_body<1>(src + (size_t)zl * DD * HD3,
                   g_qkvTh + (size_t)zl * HD3 * DD, g_qkvTl + (size_t)zl * HD3 * DD,
                   DD, HD3);
}

// launch 1: proj (z<LL), w1 (z<2LL), w2 (z<3LL), prob-pad zero fill (z==3LL)
__global__ void tsplit_rest(const float* __restrict__ pw,
                            const float* __restrict__ w1,
                            const float* __restrict__ w2) {
    int zl = blockIdx.z;
    if (zl < LL) {
        tsplit_body<0>(pw + (size_t)zl * OD * DD,
                       g_projTh + (size_t)zl * DD * OD, g_projTl + (size_t)zl * DD * OD,
                       OD, DD);
    } else if (zl < 2 * LL) {
        int l = zl - LL;
        tsplit_body<0>(w1 + (size_t)l * DD * ED,
                       g_w1Th + (size_t)l * ED * DD, g_w1Tl + (size_t)l * ED * DD,
                       DD, ED);
    } else if (zl < 3 * LL) {
        int l = zl - 2 * LL;
        tsplit_body<0>(w2 + (size_t)l * ED * DD,
                       g_w2Th + (size_t)l * DD * ED, g_w2Tl + (size_t)l * DD * ED,
                       ED, DD);
    } else {
        long nb = (long)gridDim.x * gridDim.y;
        long bid = (long)blockIdx.y * gridDim.x + blockIdx.x;
        long i0 = bid * 256 + threadIdx.y * 32 + threadIdx.x;
        const long PER = KATT - TT;                             // 30
        const long TOT = (long)BHn * TT * PER;
        hf z0 = __float2half(0.f);
        for (long i = i0; i < TOT; i += nb * 256) {
            long row = i / PER, j = i - row * PER;
            g_ph[(size_t)row * KATT + TT + j] = z0;
        }
    }
}

// ---- LN row stats (+ optional embed materialization into g_h for layer 0) ----
__global__ void ln_stats(const float* __restrict__ x, const float* __restrict__ cls,
                         const float* __restrict__ dict, int first) {
    int row = blockIdx.x * 8 + (threadIdx.x >> 5);   // 8 warps, one row each
    int lane = threadIdx.x & 31;
    float v[8];
    if (first) {
        int b = row / TT, t = row - b * TT;
        const float* src;
        if (t < NTOK)        src = x + ((size_t)b * NTOK + t) * DD;
        else if (t == NTOK)  src = cls;
        else                 src = dict;
        float4 a0 = *(const float4*)(src + lane * 8);
        float4 a1 = *(const float4*)(src + lane * 8 + 4);
        v[0]=a0.x; v[1]=a0.y; v[2]=a0.z; v[3]=a0.w;
        v[4]=a1.x; v[5]=a1.y; v[6]=a1.z; v[7]=a1.w;
        float4* dst = (float4*)(g_h + (size_t)row * DD + lane * 8);
        dst[0] = a0; dst[1] = a1;
    } else {
        float4 a0 = *(const float4*)(g_h + (size_t)row * DD + lane * 8);
        float4 a1 = *(const float4*)(g_h + (size_t)row * DD + lane * 8 + 4);
        v[0]=a0.x; v[1]=a0.y; v[2]=a0.z; v[3]=a0.w;
        v[4]=a1.x; v[5]=a1.y; v[6]=a1.z; v[7]=a1.w;
    }
    float s = 0.f, s2 = 0.f;
    #pragma unroll
    for (int i = 0; i < 8; i++) { s += v[i]; s2 += v[i] * v[i]; }
    #pragma unroll
    for (int o = 16; o > 0; o >>= 1) {
        s  += __shfl_xor_sync(0xFFFFFFFFu, s,  o);
        s2 += __shfl_xor_sync(0xFFFFFFFFu, s2, o);
    }
    if (lane == 0) {
        float mean = s * (1.0f / DD);
        float var  = s2 * (1.0f / DD) - mean * mean;
        g_lnm[row] = mean;
        g_lnr[row] = rsqrtf(var + 1e-5f);
    }
}

// ---- transpose V: [bh][t][f] -> vT [bh][f][t(pad KATT)] + zero g_rsum[bh] ----
__global__ void transpose_v() {
    __shared__ hf th[32][33];
    int bh = blockIdx.z;
    int f0 = blockIdx.x * 32, t0 = blockIdx.y * 32;
    int tx = threadIdx.x, ty = threadIdx.y;   // 32 x 8
    if (blockIdx.x == 0 && blockIdx.y == 0) {
        int tid = ty * 32 + tx;
        for (int i = tid; i < TT; i += 256) g_rsum[(size_t)bh * TT + i] = 0.f;
    }
    const hf* vh = g_vh + (size_t)bh * TT * DD;
    #pragma unroll
    for (int i = 0; i < 4; i++) {
        int t = t0 + ty + i * 8;
        hf a = __float2half(0.f);
        if (t < TT) a = vh[(size_t)t * DD + f0 + tx];
        th[ty + i * 8][tx] = a;
    }
    __syncthreads();
    hf* dH = g_vTh + (size_t)bh * DD * KATT;
    #pragma unroll
    for (int i = 0; i < 4; i++) {
        int f = f0 + ty + i * 8, t = t0 + tx;
        dH[(size_t)f * KATT + t] = th[tx][ty + i * 8];
    }
}

// ---- final output split ----
__global__ void out_kernel(float* __restrict__ out) {
    long i = (long)blockIdx.x * blockDim.x + threadIdx.x;
    if (i >= (long)MM * DD) return;
    int d = (int)(i % DD);
    long r = i / DD;
    int t = (int)(r % TT);
    int b = (int)(r / TT);
    float v = g_h[i];
    if (t < NTOK)        out[((long)b * NTOK + t) * DD + d] = v;
    else if (t == NTOK)  out[(long)BB * NTOK * DD + (long)b * DD + d] = v;
    else                 out[(long)BB * NTOK * DD + (long)BB * DD + (long)b * DD + d] = v;
}

extern "C" void kernel_launch(void* const* d_in, const int* in_sizes, int n_in,
                              void* d_out, int out_size) {
    const float* x      = (const float*)d_in[0];
    const float* cls    = (const float*)d_in[1];
    const float* dict   = (const float*)d_in[2];
    const float* ln1_g  = (const float*)d_in[3];
    const float* ln1_b  = (const float*)d_in[4];
    const float* qkv_w  = (const float*)d_in[5];
    const float* qkv_b  = (const float*)d_in[6];
    const float* proj_w = (const float*)d_in[7];
    const float* proj_b = (const float*)d_in[8];
    const float* ln2_g  = (const float*)d_in[9];
    const float* ln2_b  = (const float*)d_in[10];
    const float* mlp_w1 = (const float*)d_in[11];
    const float* mlp_b1 = (const float*)d_in[12];
    const float* mlp_w2 = (const float*)d_in[13];
    const float* mlp_b2 = (const float*)d_in[14];

    cudaFuncSetAttribute(mma_gemm<0,0,1>, cudaFuncAttributeMaxDynamicSharedMemorySize, SMEM_DYN);
    cudaFuncSetAttribute(mma_gemm<1,2,1>, cudaFuncAttributeMaxDynamicSharedMemorySize, SMEM_DYN);
    cudaFuncSetAttribute(mma_gemm<2,0,1>, cudaFuncAttributeMaxDynamicSharedMemorySize, SMEM_DYN);
    cudaFuncSetAttribute(mma_gemm<3,0,3>, cudaFuncAttributeMaxDynamicSharedMemorySize, SMEM_DYN);
    cudaFuncSetAttribute(mma_gemm<4,2,3>, cudaFuncAttributeMaxDynamicSharedMemorySize, SMEM_DYN);
    cudaFuncSetAttribute(mma_gemm<5,0,3>, cudaFuncAttributeMaxDynamicSharedMemorySize, SMEM_DYN);

    float *gh, *qkvb;
    hf *ph, *qh, *kh, *vTh, *oh, *ol, *mh, *ml;
    hf *qkvTh, *qkvTl, *projTh, *projTl, *w1Th, *w1Tl, *w2Th, *w2Tl;
    cudaGetSymbolAddress((void**)&gh,  g_h);
    cudaGetSymbolAddress((void**)&qkvb, g_qkvb);
    cudaGetSymbolAddress((void**)&ph,  g_ph);
    cudaGetSymbolAddress((void**)&qh,  g_qh);
    cudaGetSymbolAddress((void**)&kh,  g_kh);
    cudaGetSymbolAddress((void**)&vTh, g_vTh);
    cudaGetSymbolAddress((void**)&oh,  g_oh);
    cudaGetSymbolAddress((void**)&ol,  g_ol);
    cudaGetSymbolAddress((void**)&mh,  g_mh);
    cudaGetSymbolAddress((void**)&ml,  g_ml);
    cudaGetSymbolAddress((void**)&qkvTh, g_qkvTh);
    cudaGetSymbolAddress((void**)&qkvTl, g_qkvTl);
    cudaGetSymbolAddress((void**)&projTh, g_projTh);
    cudaGetSymbolAddress((void**)&projTl, g_projTl);
    cudaGetSymbolAddress((void**)&w1Th, g_w1Th);
    cudaGetSymbolAddress((void**)&w1Tl, g_w1Tl);
    cudaGetSymbolAddress((void**)&w2Th, g_w2Th);
    cudaGetSymbolAddress((void**)&w2Tl, g_w2Tl);

    dim3 tb(32, 8);
    // launch 0, 1: weight prep (+ prob pad zero fill)
    tsplit_qkv <<<dim3(HD3/32, DD/32, LL+1), tb>>>(qkv_w, qkv_b);
    tsplit_rest<<<dim3(32, 64, 3*LL+1), tb>>>(proj_w, mlp_w1, mlp_w2);

    for (int l = 0; l < LL; l++) {
        // launch 2 (l=0): LN1 stats (+ embed for layer 0)
        ln_stats<<<MM/8, 256>>>(x, cls, dict, l == 0 ? 1 : 0);

        // launch 3 (l=0): QKV GEMM, fused LN A-load, 1-pass  <- ncu capture target
        mma_gemm<1,2,1><<<dim3(HD3/128, (MM+127)/128, 1), 256, SMEM_DYN>>>(
            nullptr, nullptr, 0, 0,
            qkvTh + (size_t)l*HD3*DD, nullptr, DD, 0,
            qkvb + (size_t)l*HD3, ln1_g + (size_t)l*DD, ln1_b + (size_t)l*DD,
            nullptr, 0, 0, MM, HD3, DD);

        // V transpose + per-layer rowsum zeroing
        transpose_v<<<dim3(DD/32, KATT/32, BHn), tb>>>();

        // probs = exp(Qh Kh^T) -> fp16 + row sums, batched over 64 heads
        mma_gemm<0,0,1><<<dim3((TT+127)/128, (TT+127)/128, BHn), 256, SMEM_DYN>>>(
            qh, nullptr, DD, (long)TT*DD,
            kh, nullptr, DD, (long)TT*DD,
            nullptr, nullptr, nullptr, nullptr, 0, 0, TT, TT, DD);

        // O = P V / rowsum: plain fp16 GEMM, normalize in epilogue
        mma_gemm<2,0,1><<<dim3(DD/128, (TT+127)/128, BHn), 256, SMEM_DYN>>>(
            ph, nullptr, KATT, (long)TT*KATT,
            vTh, nullptr, KATT, (long)DD*KATT,
            nullptr, nullptr, nullptr, nullptr, 0, 0, TT, DD, KATT);

        // proj: [8208,2048] x [256,2048]^T -> fp32 h  (full 3-pass precision)
        mma_gemm<3,0,3><<<dim3(DD/128, (MM+127)/128, 1), 256, SMEM_DYN>>>(
            oh, ol, OD, 0,
            projTh + (size_t)l*DD*OD, projTl + (size_t)l*DD*OD, OD, 0,
            proj_b + (size_t)l*DD, nullptr, nullptr, gh, DD, 0, MM, DD, OD);

        // LN2 stats
        ln_stats<<<MM/8, 256>>>(x, cls, dict, 0);

        // mlp1 with fused LN A-load, + gelu -> m split (3-pass)
        mma_gemm<4,2,3><<<dim3(ED/128, (MM+127)/128, 1), 256, SMEM_DYN>>>(
            nullptr, nullptr, 0, 0,
            w1Th + (size_t)l*ED*DD, w1Tl + (size_t)l*ED*DD, DD, 0,
            mlp_b1 + (size_t)l*ED, ln2_g + (size_t)l*DD, ln2_b + (size_t)l*DD,
            nullptr, 0, 0, MM, ED, DD);

        // mlp2 + gelu -> fp32 h (3-pass)
        mma_gemm<5,0,3><<<dim3(DD/128, (MM+127)/128, 1), 256, SMEM_DYN>>>(
            mh, ml, ED, 0,
            w2Th + (size_t)l*DD*ED, w2Tl + (size_t)l*DD*ED, ED, 0,
            mlp_b2 + (size_t)l*DD, nullptr, nullptr, gh, DD, 0, MM, DD, ED);
    }

    long total = (long)MM * DD;
    out_kernel<<<(unsigned)((total + 255) / 256), 256>>>((float*)d_out);
}

// round 15
// speedup vs baseline: 2.1538x; 1.0780x over previous
#include <cuda_runtime.h>
#include <cuda_fp16.h>
#include <math.h>
#include <stdint.h>

// ---- problem constants ----
#define BB 8
#define NTOK 1024
#define TT 1026            // N + cls + dict
#define DD 256
#define HH 8
#define LL 6
#define HD3 6144           // H*D*3
#define OD 2048            // H*D
#define ED 1024            // EXP*D
#define MM (BB*TT)         // 8208 rows
#define BHn (BB*HH)        // 64
#define KATT 1056          // padded key count (prob row stride / WV K)

typedef __half hf;

// ---- scratch (device globals; no allocs allowed) ----
__device__ __align__(16) float g_h [(size_t)MM*DD];
__device__ __align__(16) float g_rsum[(size_t)BHn*TT];
__device__ __align__(16) float g_lnm[(size_t)MM];
__device__ __align__(16) float g_lnr[(size_t)MM];
__device__ __align__(16) float g_qkvb[(size_t)LL*HD3];
__device__ __align__(16) hf g_lnh[(size_t)MM*DD];        // LN output, hi fp16
__device__ __align__(16) hf g_ph[(size_t)BHn*TT*KATT];   // exp(scores), fp16
__device__ __align__(16) hf g_qh[(size_t)BHn*TT*DD];
__device__ __align__(16) hf g_kh[(size_t)BHn*TT*DD];
__device__ __align__(16) hf g_vh[(size_t)BHn*TT*DD];
__device__ __align__(16) hf g_vTh[(size_t)BHn*DD*KATT];
__device__ __align__(16) hf g_oh[(size_t)MM*OD];
__device__ __align__(16) hf g_ol[(size_t)MM*OD];
__device__ __align__(16) hf g_mh[(size_t)MM*ED];
__device__ __align__(16) hf g_ml[(size_t)MM*ED];
// transposed + split weights [N,K] per layer
__device__ __align__(16) hf g_qkvTh[(size_t)LL*HD3*DD];
__device__ __align__(16) hf g_qkvTl[(size_t)LL*HD3*DD];
__device__ __align__(16) hf g_projTh[(size_t)LL*DD*OD];
__device__ __align__(16) hf g_projTl[(size_t)LL*DD*OD];
__device__ __align__(16) hf g_w1Th[(size_t)LL*ED*DD];
__device__ __align__(16) hf g_w1Tl[(size_t)LL*ED*DD];
__device__ __align__(16) hf g_w2Th[(size_t)LL*DD*ED];
__device__ __align__(16) hf g_w2Tl[(size_t)LL*DD*ED];

__device__ __forceinline__ float gelu_exact(float x) {
    return 0.5f * x * (1.0f + erff(x * 0.70710678118654752440f));
}

__device__ __forceinline__ uint32_t smem_u32(const void* p) {
    uint32_t a;
    asm("{ .reg .u64 t; cvta.to.shared.u64 t, %1; cvt.u32.u64 %0, t; }" : "=r"(a) : "l"(p));
    return a;
}

__device__ __forceinline__ void ldsm4(uint32_t* r, uint32_t addr) {
    asm volatile("ldmatrix.sync.aligned.m8n8.x4.shared.b16 {%0,%1,%2,%3}, [%4];"
                 : "=r"(r[0]), "=r"(r[1]), "=r"(r[2]), "=r"(r[3]) : "r"(addr));
}

__device__ __forceinline__ void mma16816(float* d, const uint32_t* a, const uint32_t* b) {
    asm volatile(
        "mma.sync.aligned.m16n8k16.row.col.f32.f16.f16.f32 "
        "{%0,%1,%2,%3}, {%4,%5,%6,%7}, {%8,%9}, {%0,%1,%2,%3};"
        : "+f"(d[0]), "+f"(d[1]), "+f"(d[2]), "+f"(d[3])
        : "r"(a[0]), "r"(a[1]), "r"(a[2]), "r"(a[3]), "r"(b[0]), "r"(b[1]));
}

__device__ __forceinline__ void cpa16(uint32_t dst, const void* src, bool v) {
    int sz = v ? 16 : 0;
    asm volatile("cp.async.cg.shared.global [%0], [%1], 16, %2;"
                 :: "r"(dst), "l"(src), "r"(sz) : "memory");
}
__device__ __forceinline__ void cpa_commit() {
    asm volatile("cp.async.commit_group;" ::: "memory");
}

__device__ __forceinline__ void split_store(hf* dh, hf* dl, size_t off, float v) {
    hf h = __float2half_rn(v);
    dh[off] = h;
    dl[off] = __float2half_rn(v - __half2float(h));
}

// pack 8 fp32 into hi/lo half uint4s
__device__ __forceinline__ void pack8(const float* p, uint4& h, uint4& l) {
    __half2 hh[4], ll[4];
    #pragma unroll
    for (int i = 0; i < 4; i++) {
        __half a = __float2half_rn(p[2*i]);
        __half b = __float2half_rn(p[2*i+1]);
        hh[i] = __halves2half2(a, b);
        ll[i] = __halves2half2(__float2half_rn(p[2*i]   - __half2float(a)),
                               __float2half_rn(p[2*i+1] - __half2float(b)));
    }
    h = *(uint4*)hh;
    l = *(uint4*)ll;
}
// hi only
__device__ __forceinline__ void pack8h(const float* p, uint4& h) {
    __half2 hh[4];
    #pragma unroll
    for (int i = 0; i < 4; i++)
        hh[i] = __halves2half2(__float2half_rn(p[2*i]), __float2half_rn(p[2*i+1]));
    h = *(uint4*)hh;
}

// per-element epilogue (EPI != 0 paths)
template<int EPI>
__device__ __forceinline__ void epi_store(int gm, int gn, float v, int M, int N,
                                          const float* __restrict__ bias,
                                          float* __restrict__ C, int ldc, long sC, int z) {
    if (gm >= M || gn >= N) return;
    if constexpr (EPI == 1) {                 // qkv scatter (permuted cols: c*2048+h*256+f)
        v += bias[gn];
        int c = gn >> 11;
        int rem = gn & 2047;
        int h = rem >> 8, f = rem & 255;
        int b = gm / TT, t = gm - b * TT;
        int bh = b * HH + h;
        size_t o = ((size_t)bh * TT + t) * DD + f;
        if (c == 2) {
            g_vh[o] = __float2half_rn(v);     // hi only
        } else {
            v *= 0.0625f;                     // 1/sqrt(256)
            if (c == 0) g_qh[o] = __float2half_rn(v);
            else        g_kh[o] = __float2half_rn(v);
        }
    } else if constexpr (EPI == 2) {          // WV (pre-normalized by caller) -> split to o
        int b = z >> 3, head = z & 7;
        split_store(g_oh, g_ol, ((size_t)b * TT + gm) * OD + (size_t)head * DD + gn, v);
    } else if constexpr (EPI == 3) {          // proj -> fp32 + bias
        C[(size_t)gm * ldc + gn] = v + bias[gn];
    } else if constexpr (EPI == 4) {          // mlp1: bias+gelu -> m split
        split_store(g_mh, g_ml, (size_t)gm * ED + gn, gelu_exact(v + bias[gn]));
    } else {                                  // mlp2: bias+gelu -> fp32
        C[(size_t)gm * ldc + gn] = gelu_exact(v + bias[gn]);
    }
}

// ============ HMMA fp16 split GEMM: 128x128 block, BK=32, cp.async 3-stage ============
// Tile layout: 64B rows (32 halves), 16B-chunk XOR swizzle:
//   chunk c of row r lives at r*64 + ((c ^ ((r>>1)&3)) * 16)
// MODE 0: A (hi[/lo]) via cp.async.
// MODE 2: A = LayerNorm(g_h row) via g_lnm/g_lnr + lng/lnb on the fly
//         (hi/lo split; used only with NPASS >= 2 where MMAs hide the latency).
// NPASS 1: Ah*Bh.  NPASS 2: +Al*Bh.  NPASS 3: +Ah*Bl.
// EPI 0: probs epilogue — exp(S) -> fp16 g_ph + atomic row-sums into g_rsum.
// EPI 2: epilogue normalizes by 1/g_rsum before storing.
#define AH_OFF 0
#define AL_OFF 8192
#define BH_OFF 16384
#define BL_OFF 24576
#define STG_BYTES 32768
#define SMEM_DYN (3*STG_BYTES)

template<int EPI, int MODE, int NPASS>
__global__ void __launch_bounds__(256, 2) mma_gemm(
    const hf* __restrict__ Ah, const hf* __restrict__ Al, int lda, long sA,
    const hf* __restrict__ Bh, const hf* __restrict__ Bl, int ldb, long sB,
    const float* __restrict__ bias,
    const float* __restrict__ lng, const float* __restrict__ lnb,
    float* __restrict__ C, int ldc, long sC,
    int M, int N, int K)
{
    extern __shared__ char smdyn[];
    uint32_t sb = smem_u32(smdyn);

    int tid = threadIdx.x, lane = tid & 31, wid = tid >> 5;
    int wm = wid >> 1, wn = wid & 1;
    int z = blockIdx.z;
    Bh += (size_t)z * sB;
    if constexpr (NPASS == 3) Bl += (size_t)z * sB;
    int bm = blockIdx.y * 128, bn = blockIdx.x * 128;

    int row0 = tid >> 2, row1 = row0 + 64;
    int cv  = tid & 3;                        // 16B chunk index
    int cvb = cv * 16;                        // byte offset in source row
    int cofs = cv * 8;                        // element offset (8 elems)
    bool aval0 = (bm + row0) < M, aval1 = (bm + row1) < M;
    bool bval0 = (bn + row0) < N, bval1 = (bn + row1) < N;
    const char* pBh0 = (const char*)(Bh + (size_t)(bval0 ? bn + row0 : 0) * ldb) + cvb;
    const char* pBh1 = (const char*)(Bh + (size_t)(bval1 ? bn + row1 : 0) * ldb) + cvb;
    const char* pBl0 = nullptr; const char* pBl1 = nullptr;
    if constexpr (NPASS == 3) {
        pBl0 = (const char*)(Bl + (size_t)(bval0 ? bn + row0 : 0) * ldb) + cvb;
        pBl1 = (const char*)(Bl + (size_t)(bval1 ? bn + row1 : 0) * ldb) + cvb;
    }
    // swizzled smem offsets for the two rows this thread fills
    uint32_t st0 = (uint32_t)(row0 * 64 + ((cv ^ ((row0 >> 1) & 3)) * 16));
    uint32_t st1 = (uint32_t)(row1 * 64 + ((cv ^ ((row1 >> 1) & 3)) * 16));

    // A sources
    const char *pAh0 = nullptr, *pAh1 = nullptr, *pAl0 = nullptr, *pAl1 = nullptr;
    const float *pS0 = nullptr, *pS1 = nullptr;
    float rm0 = 0.f, rm1 = 0.f, rr0 = 0.f, rr1 = 0.f;
    if constexpr (MODE == 2) {
        pS0 = g_h + (size_t)(aval0 ? bm + row0 : 0) * DD + cofs;
        pS1 = g_h + (size_t)(aval1 ? bm + row1 : 0) * DD + cofs;
        if (aval0) { rm0 = g_lnm[bm + row0]; rr0 = g_lnr[bm + row0]; }
        if (aval1) { rm1 = g_lnm[bm + row1]; rr1 = g_lnr[bm + row1]; }
    } else {
        Ah += (size_t)z * sA;
        pAh0 = (const char*)(Ah + (size_t)(aval0 ? bm + row0 : 0) * lda) + cvb;
        pAh1 = (const char*)(Ah + (size_t)(aval1 ? bm + row1 : 0) * lda) + cvb;
        if constexpr (NPASS >= 2) {
            Al += (size_t)z * sA;
            pAl0 = (const char*)(Al + (size_t)(aval0 ? bm + row0 : 0) * lda) + cvb;
            pAl1 = (const char*)(Al + (size_t)(aval1 ? bm + row1 : 0) * lda) + cvb;
        }
    }

    float d[2][8][4];
    #pragma unroll
    for (int i = 0; i < 2; i++)
        #pragma unroll
        for (int j = 0; j < 8; j++)
            #pragma unroll
            for (int q = 0; q < 4; q++) d[i][j][q] = 0.f;

    // ldmatrix lane addressing (per-lane row + k-chunk)
    int group = lane >> 3, lrow = lane & 7;
    int a_row = wm * 32 + (group & 1) * 8 + lrow;
    int koA   = (group >> 1);                 // k chunk offset 0/1 (8 halves each)
    int b_row = wn * 64 + (group >> 1) * 8 + lrow;
    int koB   = (group & 1);
    int aS = (a_row >> 1) & 3;                // swizzle key; invariant under +16 rows
    int bS = (b_row >> 1) & 3;
    uint32_t aB0 = (uint32_t)(a_row * 64),       aB1 = (uint32_t)((a_row + 16) * 64);
    uint32_t bB[4];
    #pragma unroll
    for (int np = 0; np < 4; np++) bB[np] = (uint32_t)((b_row + np * 16) * 64);

    // issue cp.async for chunk c into stage stg (B always; A only MODE 0)
    auto issue = [&](int c, int stg) {
        uint32_t s0 = sb + (uint32_t)stg * STG_BYTES;
        size_t adv = (size_t)c * 64;          // 32 halves = 64 bytes
        if constexpr (MODE == 0) {
            cpa16(s0 + AH_OFF + st0, pAh0 + adv, aval0);
            cpa16(s0 + AH_OFF + st1, pAh1 + adv, aval1);
            if constexpr (NPASS >= 2) {
                cpa16(s0 + AL_OFF + st0, pAl0 + adv, aval0);
                cpa16(s0 + AL_OFF + st1, pAl1 + adv, aval1);
            }
        }
        cpa16(s0 + BH_OFF + st0, pBh0 + adv, bval0);
        cpa16(s0 + BH_OFF + st1, pBh1 + adv, bval1);
        if constexpr (NPASS == 3) {
            cpa16(s0 + BL_OFF + st0, pBl0 + adv, bval0);
            cpa16(s0 + BL_OFF + st1, pBl1 + adv, bval1);
        }
        cpa_commit();
    };

    float q0[8], q1[8];
    auto loadraw = [&](int c, float* r0, float* r1) {
        int kc = c * 32;
        float4 x0 = *(const float4*)(pS0 + kc);
        float4 x1 = *(const float4*)(pS0 + kc + 4);
        float4 y0 = *(const float4*)(pS1 + kc);
        float4 y1 = *(const float4*)(pS1 + kc + 4);
        r0[0]=x0.x; r0[1]=x0.y; r0[2]=x0.z; r0[3]=x0.w;
        r0[4]=x1.x; r0[5]=x1.y; r0[6]=x1.z; r0[7]=x1.w;
        r1[0]=y0.x; r1[1]=y0.y; r1[2]=y0.z; r1[3]=y0.w;
        r1[4]=y1.x; r1[5]=y1.y; r1[6]=y1.z; r1[7]=y1.w;
    };
    auto packstore = [&](int c, int stg, const float* r0, const float* r1) {
        // MODE 2 only: LayerNorm transform, hi/lo split
        float p[8];
        char* as = smdyn + (size_t)stg * STG_BYTES;
        int kc = c * 32;
        const float* gk = lng + kc + cofs;
        const float* bk = lnb + kc + cofs;
        uint4 h0, l0, h1, l1;
        #pragma unroll
        for (int i = 0; i < 8; i++)
            p[i] = aval0 ? (r0[i] - rm0) * rr0 * gk[i] + bk[i] : 0.f;
        pack8(p, h0, l0);
        #pragma unroll
        for (int i = 0; i < 8; i++)
            p[i] = aval1 ? (r1[i] - rm1) * rr1 * gk[i] + bk[i] : 0.f;
        pack8(p, h1, l1);
        *(uint4*)(as + AH_OFF + st0) = h0;
        *(uint4*)(as + AL_OFF + st0) = l0;
        *(uint4*)(as + AH_OFF + st1) = h1;
        *(uint4*)(as + AL_OFF + st1) = l1;
    };

    int nit = K >> 5;                         // >= 8 for all our shapes
    if constexpr (MODE == 2) {
        loadraw(0, q0, q1); packstore(0, 0, q0, q1);
        loadraw(1, q0, q1); packstore(1, 1, q0, q1);
    }
    issue(0, 0);
    issue(1, 1);

    int stg_c = 0;                            // c % 3
    for (int c = 0; c < nit; c++) {
        if (c + 1 < nit) {
            asm volatile("cp.async.wait_group 1;" ::: "memory");
        } else {
            asm volatile("cp.async.wait_group 0;" ::: "memory");
        }
        __syncthreads();                      // publish stage c; free stage c-1

        int stg_n = stg_c + 2; if (stg_n >= 3) stg_n -= 3;   // (c+2) % 3
        bool have2 = (c + 2 < nit);
        if (have2) {
            issue(c + 2, stg_n);
            if constexpr (MODE == 2) loadraw(c + 2, q0, q1);
        }

        uint32_t cb = sb + (uint32_t)stg_c * STG_BYTES;
        #pragma unroll
        for (int ks = 0; ks < 32; ks += 16) {
            int kc = ks >> 3;                 // 0 or 2
            uint32_t a_hf[2][4], a_lf[2][4];
            {
                uint32_t sw = (uint32_t)(((kc + koA) ^ aS) << 4);
                uint32_t o0 = cb + aB0 + sw, o1 = cb + aB1 + sw;
                ldsm4(a_hf[0], o0 + AH_OFF);
                ldsm4(a_hf[1], o1 + AH_OFF);
                if constexpr (NPASS >= 2) {
                    ldsm4(a_lf[0], o0 + AL_OFF);
                    ldsm4(a_lf[1], o1 + AL_OFF);
                }
            }
            uint32_t swb = (uint32_t)(((kc + koB) ^ bS) << 4);
            #pragma unroll
            for (int np = 0; np < 4; np++) {
                uint32_t b_hf[4], b_lf[4];
                uint32_t o = cb + bB[np] + swb;
                ldsm4(b_hf, o + BH_OFF);
                if constexpr (NPASS == 3) ldsm4(b_lf, o + BL_OFF);
                #pragma unroll
                for (int mt = 0; mt < 2; mt++)
                    #pragma unroll
                    for (int hq = 0; hq < 2; hq++)
                        mma16816(d[mt][np * 2 + hq], a_hf[mt], &b_hf[hq * 2]);
                if constexpr (NPASS >= 2) {
                    #pragma unroll
                    for (int mt = 0; mt < 2; mt++)
                        #pragma unroll
                        for (int hq = 0; hq < 2; hq++)
                            mma16816(d[mt][np * 2 + hq], a_lf[mt], &b_hf[hq * 2]);
                }
                if constexpr (NPASS == 3) {
                    #pragma unroll
                    for (int mt = 0; mt < 2; mt++)
                        #pragma unroll
                        for (int hq = 0; hq < 2; hq++)
                            mma16816(d[mt][np * 2 + hq], a_hf[mt], &b_lf[hq * 2]);
                }
            }
        }

        if constexpr (MODE == 2) {
            if (have2) packstore(c + 2, stg_n, q0, q1);   // LDG latency hidden by MMAs
        }

        if (++stg_c >= 3) stg_c -= 3;
    }

    // ---- epilogue ----
    if constexpr (EPI == 0) {
        // probs: exp(S) -> fp16, atomic per-row sums
        hf* P = g_ph + (size_t)z * TT * KATT;
        #pragma unroll
        for (int mt = 0; mt < 2; mt++) {
            int gr0 = bm + wm * 32 + mt * 16 + (lane >> 2);
            int gr1 = gr0 + 8;
            float rs0 = 0.f, rs1 = 0.f;
            #pragma unroll
            for (int nt = 0; nt < 8; nt++) {
                int c0 = bn + wn * 64 + nt * 8 + (lane & 3) * 2;
                float* dd = d[mt][nt];
                bool cok = (c0 < N);           // N even => c0+1 also in-bounds
                if (gr0 < M && cok) {
                    float e0 = __expf(dd[0]), e1 = __expf(dd[1]);
                    rs0 += e0 + e1;
                    *(__half2*)(P + (size_t)gr0 * KATT + c0) =
                        __halves2half2(__float2half_rn(e0), __float2half_rn(e1));
                }
                if (gr1 < M && cok) {
                    float e2 = __expf(dd[2]), e3 = __expf(dd[3]);
                    rs1 += e2 + e3;
                    *(__half2*)(P + (size_t)gr1 * KATT + c0) =
                        __halves2half2(__float2half_rn(e2), __float2half_rn(e3));
                }
            }
            rs0 += __shfl_xor_sync(0xFFFFFFFFu, rs0, 1);
            rs0 += __shfl_xor_sync(0xFFFFFFFFu, rs0, 2);
            rs1 += __shfl_xor_sync(0xFFFFFFFFu, rs1, 1);
            rs1 += __shfl_xor_sync(0xFFFFFFFFu, rs1, 2);
            if ((lane & 3) == 0) {
                if (gr0 < M) atomicAdd(&g_rsum[(size_t)z * TT + gr0], rs0);
                if (gr1 < M) atomicAdd(&g_rsum[(size_t)z * TT + gr1], rs1);
            }
        }
    } else {
        #pragma unroll
        for (int mt = 0; mt < 2; mt++) {
            float sA0 = 1.f, sA1 = 1.f;
            if constexpr (EPI == 2) {
                int gr0 = bm + wm * 32 + mt * 16 + (lane >> 2);
                if (gr0 < M)     sA0 = 1.0f / g_rsum[(size_t)z * TT + gr0];
                if (gr0 + 8 < M) sA1 = 1.0f / g_rsum[(size_t)z * TT + gr0 + 8];
            }
            #pragma unroll
            for (int nt = 0; nt < 8; nt++) {
                int r0 = bm + wm * 32 + mt * 16 + (lane >> 2);
                int c0 = bn + wn * 64 + nt * 8 + (lane & 3) * 2;
                float* dd = d[mt][nt];
                epi_store<EPI>(r0,     c0,     dd[0] * sA0, M, N, bias, C, ldc, sC, z);
                epi_store<EPI>(r0,     c0 + 1, dd[1] * sA0, M, N, bias, C, ldc, sC, z);
                epi_store<EPI>(r0 + 8, c0,     dd[2] * sA1, M, N, bias, C, ldc, sC, z);
                epi_store<EPI>(r0 + 8, c0 + 1, dd[3] * sA1, M, N, bias, C, ldc, sC, z);
            }
        }
    }
}

// ---- shared transpose+split body: src [K,N] fp32 -> dh/dl [N,K] half ----
template<int PERM>
__device__ __forceinline__ void tsplit_body(const float* __restrict__ src,
                                            hf* __restrict__ dh, hf* __restrict__ dl,
                                            int K, int N) {
    __shared__ float t[32][33];
    int n0 = blockIdx.x * 32, k0 = blockIdx.y * 32;
    int tx = threadIdx.x, ty = threadIdx.y;  // 32 x 8
    #pragma unroll
    for (int i = 0; i < 4; i++) {
        int k = k0 + ty + i * 8, n = n0 + tx;
        if (k < K && n < N) t[ty + i * 8][tx] = src[(size_t)k * N + n];
    }
    __syncthreads();
    #pragma unroll
    for (int i = 0; i < 4; i++) {
        int n = n0 + ty + i * 8, k = k0 + tx;
        if (n < N && k < K) {
            float v = t[tx][ty + i * 8];
            int nd = n;
            if (PERM) {
                int h = n / 768, r = n - h * 768;
                int f = r / 3, c = r - f * 3;
                nd = c * 2048 + h * 256 + f;
            }
            split_store(dh, dl, (size_t)nd * K + k, v);
        }
    }
}

// launch 0: qkv weights (z<LL) + bias permute (z==LL)
__global__ void tsplit_qkv(const float* __restrict__ src, const float* __restrict__ qb) {
    int zl = blockIdx.z;
    if (zl == LL) {
        int bid = blockIdx.y * gridDim.x + blockIdx.x;
        int idx = bid * 256 + threadIdx.y * 32 + threadIdx.x;
        if (idx < LL * HD3) {
            int l = idx / HD3, j = idx - l * HD3;
            int h = j / 768, r = j - h * 768;
            int f = r / 3, c = r - f * 3;
            g_qkvb[(size_t)l * HD3 + c * 2048 + h * 256 + f] = qb[idx];
        }
        return;
    }
    tsplit_body<1>(src + (size_t)zl * DD * HD3,
                   g_qkvTh + (size_t)zl * HD3 * DD, g_qkvTl + (size_t)zl * HD3 * DD,
                   DD, HD3);
}

// launch 1: proj (z<LL), w1 (z<2LL), w2 (z<3LL), prob-pad zero fill (z==3LL)
__global__ void tsplit_rest(const float* __restrict__ pw,
                            const float* __restrict__ w1,
                            const float* __restrict__ w2) {
    int zl = blockIdx.z;
    if (zl < LL) {
        tsplit_body<0>(pw + (size_t)zl * OD * DD,
                       g_projTh + (size_t)zl * DD * OD, g_projTl + (size_t)zl * DD * OD,
                       OD, DD);
    } else if (zl < 2 * LL) {
        int l = zl - LL;
        tsplit_body<0>(w1 + (size_t)l * DD * ED,
                       g_w1Th + (size_t)l * ED * DD, g_w1Tl + (size_t)l * ED * DD,
                       DD, ED);
    } else if (zl < 3 * LL) {
        int l = zl - 2 * LL;
        tsplit_body<0>(w2 + (size_t)l * ED * DD,
                       g_w2Th + (size_t)l * DD * ED, g_w2Tl + (size_t)l * DD * ED,
                       ED, DD);
    } else {
        long nb = (long)gridDim.x * gridDim.y;
        long bid = (long)blockIdx.y * gridDim.x + blockIdx.x;
        long i0 = bid * 256 + threadIdx.y * 32 + threadIdx.x;
        const long PER = KATT - TT;                             // 30
        const long TOT = (long)BHn * TT * PER;
        hf z0 = __float2half(0.f);
        for (long i = i0; i < TOT; i += nb * 256) {
            long row = i / PER, j = i - row * PER;
            g_ph[(size_t)row * KATT + TT + j] = z0;
        }
    }
}

// ---- LN row stats + materialized hi-fp16 LN output (+ embed for layer 0) ----
__global__ void ln_stats(const float* __restrict__ x, const float* __restrict__ cls,
                         const float* __restrict__ dict,
                         const float* __restrict__ lng, const float* __restrict__ lnb,
                         int first) {
    int row = blockIdx.x * 8 + (threadIdx.x >> 5);   // 8 warps, one row each
    int lane = threadIdx.x & 31;
    float v[8];
    if (first) {
        int b = row / TT, t = row - b * TT;
        const float* src;
        if (t < NTOK)        src = x + ((size_t)b * NTOK + t) * DD;
        else if (t == NTOK)  src = cls;
        else                 src = dict;
        float4 a0 = *(const float4*)(src + lane * 8);
        float4 a1 = *(const float4*)(src + lane * 8 + 4);
        v[0]=a0.x; v[1]=a0.y; v[2]=a0.z; v[3]=a0.w;
        v[4]=a1.x; v[5]=a1.y; v[6]=a1.z; v[7]=a1.w;
        float4* dst = (float4*)(g_h + (size_t)row * DD + lane * 8);
        dst[0] = a0; dst[1] = a1;
    } else {
        float4 a0 = *(const float4*)(g_h + (size_t)row * DD + lane * 8);
        float4 a1 = *(const float4*)(g_h + (size_t)row * DD + lane * 8 + 4);
        v[0]=a0.x; v[1]=a0.y; v[2]=a0.z; v[3]=a0.w;
        v[4]=a1.x; v[5]=a1.y; v[6]=a1.z; v[7]=a1.w;
    }
    float s = 0.f, s2 = 0.f;
    #pragma unroll
    for (int i = 0; i < 8; i++) { s += v[i]; s2 += v[i] * v[i]; }
    #pragma unroll
    for (int o = 16; o > 0; o >>= 1) {
        s  += __shfl_xor_sync(0xFFFFFFFFu, s,  o);
        s2 += __shfl_xor_sync(0xFFFFFFFFu, s2, o);
    }
    float mean = s * (1.0f / DD);
    float var  = s2 * (1.0f / DD) - mean * mean;
    float rr = rsqrtf(var + 1e-5f);
    if (lane == 0) { g_lnm[row] = mean; g_lnr[row] = rr; }
    // materialize LN output as hi fp16 (for MODE-0 QKV A)
    float4 g0 = *(const float4*)(lng + lane * 8);
    float4 g1 = *(const float4*)(lng + lane * 8 + 4);
    float4 b0 = *(const float4*)(lnb + lane * 8);
    float4 b1 = *(const float4*)(lnb + lane * 8 + 4);
    float p[8];
    p[0] = (v[0] - mean) * rr * g0.x + b0.x;
    p[1] = (v[1] - mean) * rr * g0.y + b0.y;
    p[2] = (v[2] - mean) * rr * g0.z + b0.z;
    p[3] = (v[3] - mean) * rr * g0.w + b0.w;
    p[4] = (v[4] - mean) * rr * g1.x + b1.x;
    p[5] = (v[5] - mean) * rr * g1.y + b1.y;
    p[6] = (v[6] - mean) * rr * g1.z + b1.z;
    p[7] = (v[7] - mean) * rr * g1.w + b1.w;
    uint4 h;
    pack8h(p, h);
    *(uint4*)(g_lnh + (size_t)row * DD + lane * 8) = h;
}

// ---- transpose V: [bh][t][f] -> vT [bh][f][t(pad KATT)] + zero g_rsum[bh] ----
__global__ void transpose_v() {
    __shared__ hf th[32][33];
    int bh = blockIdx.z;
    int f0 = blockIdx.x * 32, t0 = blockIdx.y * 32;
    int tx = threadIdx.x, ty = threadIdx.y;   // 32 x 8
    if (blockIdx.x == 0 && blockIdx.y == 0) {
        int tid = ty * 32 + tx;
        for (int i = tid; i < TT; i += 256) g_rsum[(size_t)bh * TT + i] = 0.f;
    }
    const hf* vh = g_vh + (size_t)bh * TT * DD;
    #pragma unroll
    for (int i = 0; i < 4; i++) {
        int t = t0 + ty + i * 8;
        hf a = __float2half(0.f);
        if (t < TT) a = vh[(size_t)t * DD + f0 + tx];
        th[ty + i * 8][tx] = a;
    }
    __syncthreads();
    hf* dH = g_vTh + (size_t)bh * DD * KATT;
    #pragma unroll
    for (int i = 0; i < 4; i++) {
        int f = f0 + ty + i * 8, t = t0 + tx;
        dH[(size_t)f * KATT + t] = th[tx][ty + i * 8];
    }
}

// ---- final output split ----
__global__ void out_kernel(float* __restrict__ out) {
    long i = (long)blockIdx.x * blockDim.x + threadIdx.x;
    if (i >= (long)MM * DD) return;
    int d = (int)(i % DD);
    long r = i / DD;
    int t = (int)(r % TT);
    int b = (int)(r / TT);
    float v = g_h[i];
    if (t < NTOK)        out[((long)b * NTOK + t) * DD + d] = v;
    else if (t == NTOK)  out[(long)BB * NTOK * DD + (long)b * DD + d] = v;
    else                 out[(long)BB * NTOK * DD + (long)BB * DD + (long)b * DD + d] = v;
}

extern "C" void kernel_launch(void* const* d_in, const int* in_sizes, int n_in,
                              void* d_out, int out_size) {
    const float* x      = (const float*)d_in[0];
    const float* cls    = (const float*)d_in[1];
    const float* dict   = (const float*)d_in[2];
    const float* ln1_g  = (const float*)d_in[3];
    const float* ln1_b  = (const float*)d_in[4];
    const float* qkv_w  = (const float*)d_in[5];
    const float* qkv_b  = (const float*)d_in[6];
    const float* proj_w = (const float*)d_in[7];
    const float* proj_b = (const float*)d_in[8];
    const float* ln2_g  = (const float*)d_in[9];
    const float* ln2_b  = (const float*)d_in[10];
    const float* mlp_w1 = (const float*)d_in[11];
    const float* mlp_b1 = (const float*)d_in[12];
    const float* mlp_w2 = (const float*)d_in[13];
    const float* mlp_b2 = (const float*)d_in[14];

    cudaFuncSetAttribute(mma_gemm<0,0,1>, cudaFuncAttributeMaxDynamicSharedMemorySize, SMEM_DYN);
    cudaFuncSetAttribute(mma_gemm<1,0,1>, cudaFuncAttributeMaxDynamicSharedMemorySize, SMEM_DYN);
    cudaFuncSetAttribute(mma_gemm<2,0,1>, cudaFuncAttributeMaxDynamicSharedMemorySize, SMEM_DYN);
    cudaFuncSetAttribute(mma_gemm<3,0,3>, cudaFuncAttributeMaxDynamicSharedMemorySize, SMEM_DYN);
    cudaFuncSetAttribute(mma_gemm<4,2,3>, cudaFuncAttributeMaxDynamicSharedMemorySize, SMEM_DYN);
    cudaFuncSetAttribute(mma_gemm<5,0,3>, cudaFuncAttributeMaxDynamicSharedMemorySize, SMEM_DYN);

    float *gh, *qkvb;
    hf *lnh, *ph, *qh, *kh, *vTh, *oh, *ol, *mh, *ml;
    hf *qkvTh, *projTh, *projTl, *w1Th, *w1Tl, *w2Th, *w2Tl;
    cudaGetSymbolAddress((void**)&gh,  g_h);
    cudaGetSymbolAddress((void**)&qkvb, g_qkvb);
    cudaGetSymbolAddress((void**)&lnh, g_lnh);
    cudaGetSymbolAddress((void**)&ph,  g_ph);
    cudaGetSymbolAddress((void**)&qh,  g_qh);
    cudaGetSymbolAddress((void**)&kh,  g_kh);
    cudaGetSymbolAddress((void**)&vTh, g_vTh);
    cudaGetSymbolAddress((void**)&oh,  g_oh);
    cudaGetSymbolAddress((void**)&ol,  g_ol);
    cudaGetSymbolAddress((void**)&mh,  g_mh);
    cudaGetSymbolAddress((void**)&ml,  g_ml);
    cudaGetSymbolAddress((void**)&qkvTh, g_qkvTh);
    cudaGetSymbolAddress((void**)&projTh, g_projTh);
    cudaGetSymbolAddress((void**)&projTl, g_projTl);
    cudaGetSymbolAddress((void**)&w1Th, g_w1Th);
    cudaGetSymbolAddress((void**)&w1Tl, g_w1Tl);
    cudaGetSymbolAddress((void**)&w2Th, g_w2Th);
    cudaGetSymbolAddress((void**)&w2Tl, g_w2Tl);

    dim3 tb(32, 8);
    // launch 0, 1: weight prep (+ prob pad zero fill)
    tsplit_qkv <<<dim3(HD3/32, DD/32, LL+1), tb>>>(qkv_w, qkv_b);
    tsplit_rest<<<dim3(32, 64, 3*LL+1), tb>>>(proj_w, mlp_w1, mlp_w2);

    for (int l = 0; l < LL; l++) {
        // launch 2 (l=0): LN1 stats + materialized hi-fp16 output
        ln_stats<<<MM/8, 256>>>(x, cls, dict,
                                ln1_g + (size_t)l*DD, ln1_b + (size_t)l*DD,
                                l == 0 ? 1 : 0);

        // launch 3 (l=0): QKV GEMM, MODE-0 A from g_lnh, 1-pass  <- ncu target
        mma_gemm<1,0,1><<<dim3(HD3/128, (MM+127)/128, 1), 256, SMEM_DYN>>>(
            lnh, nullptr, DD, 0,
            qkvTh + (size_t)l*HD3*DD, nullptr, DD, 0,
            qkvb + (size_t)l*HD3, nullptr, nullptr,
            nullptr, 0, 0, MM, HD3, DD);

        // V transpose + per-layer rowsum zeroing
        transpose_v<<<dim3(DD/32, KATT/32, BHn), tb>>>();

        // probs = exp(Qh Kh^T) -> fp16 + row sums, batched over 64 heads
        mma_gemm<0,0,1><<<dim3((TT+127)/128, (TT+127)/128, BHn), 256, SMEM_DYN>>>(
            qh, nullptr, DD, (long)TT*DD,
            kh, nullptr, DD, (long)TT*DD,
            nullptr, nullptr, nullptr, nullptr, 0, 0, TT, TT, DD);

        // O = P V / rowsum: plain fp16 GEMM, normalize in epilogue
        mma_gemm<2,0,1><<<dim3(DD/128, (TT+127)/128, BHn), 256, SMEM_DYN>>>(
            ph, nullptr, KATT, (long)TT*KATT,
            vTh, nullptr, KATT, (long)DD*KATT,
            nullptr, nullptr, nullptr, nullptr, 0, 0, TT, DD, KATT);

        // proj: [8208,2048] x [256,2048]^T -> fp32 h  (full 3-pass precision)
        mma_gemm<3,0,3><<<dim3(DD/128, (MM+127)/128, 1), 256, SMEM_DYN>>>(
            oh, ol, OD, 0,
            projTh + (size_t)l*DD*OD, projTl + (size_t)l*DD*OD, OD, 0,
            proj_b + (size_t)l*DD, nullptr, nullptr, gh, DD, 0, MM, DD, OD);

        // LN2 stats (+ lnh materialization, unused by mlp1 but harmless)
        ln_stats<<<MM/8, 256>>>(x, cls, dict,
                                ln2_g + (size_t)l*DD, ln2_b + (size_t)l*DD, 0);

        // mlp1 with fused LN A-load, + gelu -> m split (3-pass)
        mma_gemm<4,2,3><<<dim3(ED/128, (MM+127)/128, 1), 256, SMEM_DYN>>>(
            nullptr, nullptr, 0, 0,
            w1Th + (size_t)l*ED*DD, w1Tl + (size_t)l*ED*DD, DD, 0,
            mlp_b1 + (size_t)l*ED, ln2_g + (size_t)l*DD, ln2_b + (size_t)l*DD,
            nullptr, 0, 0, MM, ED, DD);

        // mlp2 + gelu -> fp32 h (3-pass)
        mma_gemm<5,0,3><<<dim3(DD/128, (MM+127)/128, 1), 256, SMEM_DYN>>>(
            mh, ml, ED, 0,
            w2Th + (size_t)l*DD*ED, w2Tl + (size_t)l*DD*ED, ED, 0,
            mlp_b2 + (size_t)l*DD, nullptr, nullptr, gh, DD, 0, MM, DD, ED);
    }

    long total = (long)MM * DD;
    out_kernel<<<(unsigned)((total + 255) / 256), 256>>>((float*)d_out);
}